// round 11
// baseline (speedup 1.0000x reference)
#include <cuda_runtime.h>
#include <cuda_fp16.h>
#include <math.h>
#include <stdint.h>

#define L 2048
#define HID 3072
#define HEADS 24
#define HD 128
#define MLPD 12288
#define H1 21504
#define CATD 15360
#define H3 9216   // 3*HID

// ---------------- scratch ----------------
__device__ float g_m[3 * HID];
__device__ float g_y1p[4 * 3 * (size_t)L * 32];
__device__ float g_plp[8 * (size_t)L * 64];
__device__ float g_o[4 * (size_t)L * HID];

__device__ __half g_hh[(size_t)L * H3];            // qkv part of h (fp16, lora-up included)
__device__ __half g_xmod2[(size_t)L * 3200];       // tiled, chunks 0..47 = x_mod, 48..49 = y-ext
__device__ __half g_w12[(size_t)H1 * 3200];        // tiled, chunks 0..47 = w1, 48..49 = up-ext
__device__ __half g_w22[(size_t)HID * CATD];
__device__ __half g_cat2[(size_t)L * CATD];
__device__ __half g_q2[(size_t)HEADS * L * HD];
__device__ __half g_k2[(size_t)HEADS * L * HD];
__device__ __half g_v2[(size_t)HEADS * HD * L];

// ================= helpers =================
__device__ __forceinline__ uint32_t smem_u32(const void* p) {
    uint32_t a;
    asm("{ .reg .u64 t; cvta.to.shared.u64 t, %1; cvt.u32.u64 %0, t; }" : "=r"(a) : "l"(p));
    return a;
}
__device__ __forceinline__ void mbar_init(uint32_t a, uint32_t cnt) {
    asm volatile("mbarrier.init.shared.b64 [%0], %1;" :: "r"(a), "r"(cnt) : "memory");
}
__device__ __forceinline__ void mbar_expect(uint32_t a, uint32_t bytes) {
    asm volatile("mbarrier.arrive.expect_tx.shared.b64 _, [%0], %1;" :: "r"(a), "r"(bytes) : "memory");
}
__device__ __forceinline__ void mbar_wait(uint32_t a, uint32_t parity) {
    asm volatile(
        "{\n\t.reg .pred P;\n"
        "WL_%=:\n\t"
        "mbarrier.try_wait.parity.acquire.cta.shared::cta.b64 P, [%0], %1, 0x989680;\n\t"
        "@P bra WD_%=;\n\t"
        "bra WL_%=;\n"
        "WD_%=:\n\t}"
        :: "r"(a), "r"(parity) : "memory");
}
__device__ __forceinline__ void bulk_g2s(uint32_t dst, const void* src, uint32_t bytes, uint32_t mbar) {
    asm volatile(
        "cp.async.bulk.shared::cta.global.mbarrier::complete_tx::bytes [%0], [%1], %2, [%3];"
        :: "r"(dst), "l"(src), "r"(bytes), "r"(mbar) : "memory");
}
__device__ __forceinline__ void ldsm4(uint32_t& r0, uint32_t& r1, uint32_t& r2, uint32_t& r3,
                                      uint32_t addr) {
    asm volatile("ldmatrix.sync.aligned.m8n8.x4.shared.b16 {%0,%1,%2,%3}, [%4];"
                 : "=r"(r0), "=r"(r1), "=r"(r2), "=r"(r3) : "r"(addr));
}
__device__ __forceinline__ void mma16816(float* d, const uint32_t* a, const uint32_t* b) {
    asm volatile(
        "mma.sync.aligned.m16n8k16.row.col.f32.f16.f16.f32 "
        "{%0,%1,%2,%3}, {%4,%5,%6,%7}, {%8,%9}, {%0,%1,%2,%3};"
        : "+f"(d[0]), "+f"(d[1]), "+f"(d[2]), "+f"(d[3])
        : "r"(a[0]), "r"(a[1]), "r"(a[2]), "r"(a[3]), "r"(b[0]), "r"(b[1]));
}
__device__ __forceinline__ uint32_t packh2(float a, float b) {
    __half2 h = __floats2half2_rn(a, b);
    return *(uint32_t*)&h;
}
__device__ __forceinline__ float gelu1(float x) {
    return 0.5f * x * (1.f + tanhf(0.7978845608028654f * (x + 0.044715f * x * x * x)));
}
__device__ __forceinline__ uint32_t swz128(uint32_t base, int r, int q) {
    return base + (uint32_t)r * 128u + ((uint32_t)(q ^ (r & 7)) << 4);
}
__device__ __forceinline__ uint32_t swz256(uint32_t base, int r, int q8) {
    int sr = r * 2 + (q8 >> 3);
    int q = q8 & 7;
    return base + (uint32_t)sr * 128u + ((uint32_t)(q ^ (sr & 7)) << 4);
}
__device__ __forceinline__ size_t tiled_off(int M, int r, int c) {
    return ((size_t)(c >> 6) * M + r) * 64 + (size_t)((((c & 63) >> 3) ^ (r & 7)) << 3) + (c & 7);
}

// ================= bulk-fed fp16 NT GEMM =================
template <int MODE>
__global__ __launch_bounds__(512, 1) void gemm512(
    const __half* __restrict__ At, const __half* __restrict__ Bt,
    float* __restrict__ C, const float* __restrict__ bias,
    __half* __restrict__ catp, int nc, int kbase, int nbase,
    int M, int N, int ldc, long long zsC)
{
    constexpr uint32_t ABYTES = 128u * 128u;
    constexpr uint32_t BBYTES = 256u * 128u;
    constexpr uint32_t STAGE = ABYTES + BBYTES;

    extern __shared__ char smraw[];
    uint32_t s0 = smem_u32(smraw);
    uint32_t mbar = s0 + 3u * STAGE;

    const int t = threadIdx.x, w = t >> 5, lane = t & 31;
    const int wm = w & 3, wn = w >> 2;
    const int m0 = blockIdx.x * 128, n0 = (nbase + blockIdx.y) * 256;
    const int z = blockIdx.z;
    const int c0 = kbase + z * nc;
    C += (size_t)z * zsC;

    if (t == 0) {
        mbar_init(mbar, 1); mbar_init(mbar + 8, 1); mbar_init(mbar + 16, 1);
    }
    __syncthreads();

    auto issue = [&](int c, int stg) {
        if (t == 0) {
            uint32_t mb = mbar + (uint32_t)stg * 8u;
            uint32_t ab = s0 + (uint32_t)stg * STAGE;
            mbar_expect(mb, ABYTES + BBYTES);
            bulk_g2s(ab, At + ((size_t)(c0 + c) * M + m0) * 64, ABYTES, mb);
            bulk_g2s(ab + ABYTES, Bt + ((size_t)(c0 + c) * N + n0) * 64, BBYTES, mb);
        }
    };

    issue(0, 0); issue(1, 1); issue(2, 2);

    float acc[2][8][4] = {};
    uint32_t ph[3] = {0u, 0u, 0u};

    for (int c = 0; c < nc; c++) {
        int stg = c % 3;
        mbar_wait(mbar + (uint32_t)stg * 8u, ph[stg]);
        ph[stg] ^= 1u;

        uint32_t ab = s0 + (uint32_t)stg * STAGE;
        uint32_t bb = ab + ABYTES;

        #pragma unroll
        for (int s = 0; s < 4; s++) {
            uint32_t Af[2][4];
            #pragma unroll
            for (int mt = 0; mt < 2; mt++) {
                int r = wm * 32 + mt * 16 + (lane & 15);
                int q = s * 2 + (lane >> 4);
                ldsm4(Af[mt][0], Af[mt][1], Af[mt][2], Af[mt][3], swz128(ab, r, q));
            }
            uint32_t Bf[8][2];
            #pragma unroll
            for (int np = 0; np < 4; np++) {
                int r = wn * 64 + np * 16 + ((lane >> 4) << 3) + (lane & 7);
                int q = s * 2 + ((lane >> 3) & 1);
                ldsm4(Bf[2 * np][0], Bf[2 * np][1], Bf[2 * np + 1][0], Bf[2 * np + 1][1],
                      swz128(bb, r, q));
            }
            #pragma unroll
            for (int mt = 0; mt < 2; mt++)
                #pragma unroll
                for (int nt = 0; nt < 8; nt++)
                    mma16816(acc[mt][nt], Af[mt], Bf[nt]);
        }
        __syncthreads();
        if (c + 3 < nc) issue(c + 3, stg);
    }

    #pragma unroll
    for (int mt = 0; mt < 2; mt++) {
        int row = m0 + wm * 32 + mt * 16 + (lane >> 2);
        #pragma unroll
        for (int nt = 0; nt < 8; nt++) {
            int col = n0 + wn * 64 + nt * 8 + (lane & 3) * 2;
            if (MODE == 1) {
                float b0 = bias[col], b1v = bias[col + 1];
                float v00 = acc[mt][nt][0] + b0, v01 = acc[mt][nt][1] + b1v;
                float v10 = acc[mt][nt][2] + b0, v11 = acc[mt][nt][3] + b1v;
                if (n0 >= H3) {
                    int cc = col - 6144;
                    *(__half2*)(catp + tiled_off(L, row, cc)) =
                        __floats2half2_rn(gelu1(v00), gelu1(v01));
                    *(__half2*)(catp + tiled_off(L, row + 8, cc)) =
                        __floats2half2_rn(gelu1(v10), gelu1(v11));
                } else {
                    *(__half2*)(g_hh + (size_t)row * H3 + col) = __floats2half2_rn(v00, v01);
                    *(__half2*)(g_hh + (size_t)(row + 8) * H3 + col) = __floats2half2_rn(v10, v11);
                }
            } else {
                *(float2*)(C + (size_t)row * ldc + col) =
                    make_float2(acc[mt][nt][0], acc[mt][nt][1]);
                *(float2*)(C + (size_t)(row + 8) * ldc + col) =
                    make_float2(acc[mt][nt][2], acc[mt][nt][3]);
            }
        }
    }
}

// ================= flash attention =================
__global__ __launch_bounds__(256, 1) void flash_k(
    const __half* __restrict__ Qg, const __half* __restrict__ Kg,
    const __half* __restrict__ Vg, __half* __restrict__ catp)
{
    extern __shared__ char smraw[];
    uint32_t s0 = smem_u32(smraw);
    const uint32_t sQ = s0;
    const uint32_t sK[2] = {s0 + 32768u, s0 + 98304u};
    const uint32_t sV[2] = {s0 + 65536u, s0 + 131072u};
    const uint32_t mbar = s0 + 163840u;

    const int t = threadIdx.x, w = t >> 5, lane = t & 31;
    const int qt = blockIdx.x, head = blockIdx.y;

    const __half* Qp = Qg + ((size_t)head * L + qt * 128) * 128;
    const __half* Kp = Kg + (size_t)head * L * 128;
    const __half* Vp = Vg + (size_t)head * 16 * 16384;

    if (t == 0) { mbar_init(mbar, 1); mbar_init(mbar + 8, 1); }
    __syncthreads();
    if (t == 0) {
        mbar_expect(mbar, 98304u);
        bulk_g2s(sQ, Qp, 32768u, mbar);
        bulk_g2s(sK[0], Kp, 32768u, mbar);
        bulk_g2s(sV[0], Vp, 32768u, mbar);
        mbar_expect(mbar + 8, 65536u);
        bulk_g2s(sK[1], Kp + (size_t)128 * 128, 32768u, mbar + 8);
        bulk_g2s(sV[1], Vp + 16384, 32768u, mbar + 8);
    }

    const float CSC = 0.08838834764831845f * 1.4426950408889634f;
    float m_[2] = {-1e30f, -1e30f}, l_[2] = {0.f, 0.f};
    float oacc[16][4] = {};
    uint32_t ph[2] = {0u, 0u};

    for (int kt = 0; kt < 16; kt++) {
        int buf = kt & 1;
        mbar_wait(mbar + (uint32_t)buf * 8u, ph[buf]);
        ph[buf] ^= 1u;

        float sacc[16][4] = {};
        #pragma unroll
        for (int ks = 0; ks < 8; ks++) {
            uint32_t Af[4];
            {
                int r = w * 16 + (lane & 15);
                int q8 = ks * 2 + (lane >> 4);
                ldsm4(Af[0], Af[1], Af[2], Af[3], swz256(sQ, r, q8));
            }
            uint32_t Bf[16][2];
            #pragma unroll
            for (int np = 0; np < 8; np++) {
                int r = np * 16 + ((lane >> 4) << 3) + (lane & 7);
                int q8 = ks * 2 + ((lane >> 3) & 1);
                ldsm4(Bf[2 * np][0], Bf[2 * np][1], Bf[2 * np + 1][0], Bf[2 * np + 1][1],
                      swz256(sK[buf], r, q8));
            }
            #pragma unroll
            for (int nt = 0; nt < 16; nt++) mma16816(sacc[nt], Af, Bf[nt]);
        }

        #pragma unroll
        for (int h = 0; h < 2; h++) {
            float tm = -1e30f;
            #pragma unroll
            for (int nt = 0; nt < 16; nt++)
                tm = fmaxf(tm, fmaxf(sacc[nt][2 * h], sacc[nt][2 * h + 1]));
            tm *= CSC;
            tm = fmaxf(tm, __shfl_xor_sync(0xffffffffu, tm, 1));
            tm = fmaxf(tm, __shfl_xor_sync(0xffffffffu, tm, 2));
            float mn = fmaxf(m_[h], tm);
            float alpha = exp2f(m_[h] - mn);
            float rs = 0.f;
            #pragma unroll
            for (int nt = 0; nt < 16; nt++) {
                float p0 = exp2f(sacc[nt][2 * h] * CSC - mn);
                float p1 = exp2f(sacc[nt][2 * h + 1] * CSC - mn);
                sacc[nt][2 * h] = p0; sacc[nt][2 * h + 1] = p1;
                rs += p0 + p1;
            }
            rs += __shfl_xor_sync(0xffffffffu, rs, 1);
            rs += __shfl_xor_sync(0xffffffffu, rs, 2);
            l_[h] = l_[h] * alpha + rs;
            m_[h] = mn;
            #pragma unroll
            for (int nt = 0; nt < 16; nt++) { oacc[nt][2 * h] *= alpha; oacc[nt][2 * h + 1] *= alpha; }
        }

        #pragma unroll
        for (int kk = 0; kk < 8; kk++) {
            uint32_t pf[4];
            pf[0] = packh2(sacc[2 * kk][0], sacc[2 * kk][1]);
            pf[1] = packh2(sacc[2 * kk][2], sacc[2 * kk][3]);
            pf[2] = packh2(sacc[2 * kk + 1][0], sacc[2 * kk + 1][1]);
            pf[3] = packh2(sacc[2 * kk + 1][2], sacc[2 * kk + 1][3]);
            uint32_t Bv[16][2];
            #pragma unroll
            for (int np = 0; np < 8; np++) {
                int r = np * 16 + ((lane >> 4) << 3) + (lane & 7);
                int q8 = kk * 2 + ((lane >> 3) & 1);
                ldsm4(Bv[2 * np][0], Bv[2 * np][1], Bv[2 * np + 1][0], Bv[2 * np + 1][1],
                      swz256(sV[buf], r, q8));
            }
            #pragma unroll
            for (int nt = 0; nt < 16; nt++) mma16816(oacc[nt], pf, Bv[nt]);
        }

        __syncthreads();
        if (kt + 2 < 16 && t == 0) {
            mbar_expect(mbar + (uint32_t)buf * 8u, 65536u);
            bulk_g2s(sK[buf], Kp + (size_t)(kt + 2) * 128 * 128, 32768u, mbar + (uint32_t)buf * 8u);
            bulk_g2s(sV[buf], Vp + (size_t)(kt + 2) * 16384, 32768u, mbar + (uint32_t)buf * 8u);
        }
    }

    float inv0 = 1.f / l_[0], inv1 = 1.f / l_[1];
    int row0 = qt * 128 + w * 16 + (lane >> 2);
    #pragma unroll
    for (int nt = 0; nt < 16; nt++) {
        int col = head * 128 + nt * 8 + (lane & 3) * 2;
        *(__half2*)(catp + tiled_off(L, row0, col)) =
            __floats2half2_rn(oacc[nt][0] * inv0, oacc[nt][1] * inv0);
        *(__half2*)(catp + tiled_off(L, row0 + 8, col)) =
            __floats2half2_rn(oacc[nt][2] * inv1, oacc[nt][3] * inv1);
    }
}

// ================= conversions =================
__global__ void conv_tile(const float* __restrict__ src, __half* __restrict__ dst,
                          int N, int K, long long n8) {
    long long i = (long long)blockIdx.x * 256 + threadIdx.x;
    if (i >= n8) return;
    int kq = K >> 3;
    int r = (int)(i / kq), q8i = (int)(i - (long long)r * kq);
    int c0 = q8i * 8;
    const float4* s = (const float4*)(src + (size_t)r * K + c0);
    float4 a = s[0], b = s[1];
    __half2 h0 = __floats2half2_rn(a.x, a.y);
    __half2 h1 = __floats2half2_rn(a.z, a.w);
    __half2 h2 = __floats2half2_rn(b.x, b.y);
    __half2 h3 = __floats2half2_rn(b.z, b.w);
    uint4 o;
    o.x = *(uint32_t*)&h0; o.y = *(uint32_t*)&h1;
    o.z = *(uint32_t*)&h2; o.w = *(uint32_t*)&h3;
    *(uint4*)(dst + tiled_off(N, r, c0)) = o;
}

__global__ void upext_k(const float* __restrict__ upq, const float* __restrict__ upk,
                        const float* __restrict__ upv) {
    int i = blockIdx.x * 256 + threadIdx.x;
    int o = i >> 7, j = i & 127;
    int mat = o / HID, colm = o - mat * HID;
    int jj = j - mat * 32;
    float v = 0.f;
    if (j < 96 && jj >= 0 && jj < 32) {
        const float* up = (mat == 0) ? upq : (mat == 1) ? upk : upv;
        v = up[(size_t)colm * 32 + jj];
    }
    g_w12[tiled_off(H1, o, 3072 + j)] = __float2half(v);
}

__global__ void yext_k() {
    int i = blockIdx.x * 256 + threadIdx.x;
    int l = i >> 5, j = i & 31;
    float s0 = 0.f, s1 = 0.f, s2 = 0.f;
    #pragma unroll
    for (int z = 0; z < 4; z++) {
        size_t base = (size_t)z * 3 * L * 32 + (size_t)l * 32 + j;
        s0 += g_y1p[base];
        s1 += g_y1p[base + (size_t)L * 32];
        s2 += g_y1p[base + 2 * (size_t)L * 32];
    }
    g_xmod2[tiled_off(L, l, 3072 + j)]  = __float2half(s0);
    g_xmod2[tiled_off(L, l, 3104 + j)]  = __float2half(s1);
    g_xmod2[tiled_off(L, l, 3136 + j)]  = __float2half(s2);
    g_xmod2[tiled_off(L, l, 3168 + j)]  = __float2half(0.f);
}

// ================= small kernels =================
__global__ __launch_bounds__(256) void mod_gemv(const float* __restrict__ vec,
                                                const float* __restrict__ W,
                                                const float* __restrict__ b) {
    __shared__ float sv[HID];
    int t = threadIdx.x;
    for (int j = t; j < HID; j += 256) {
        float v = vec[j];
        sv[j] = v / (1.f + expf(-v));
    }
    __syncthreads();
    int o = blockIdx.x * 8 + (t >> 5);
    int lane = t & 31;
    const float* w = W + (size_t)o * HID;
    float acc = 0.f;
    for (int k = lane; k < HID; k += 32) acc += sv[k] * w[k];
    #pragma unroll
    for (int s = 16; s; s >>= 1) acc += __shfl_xor_sync(0xffffffffu, acc, s);
    if (lane == 0) g_m[o] = acc + b[o];
}

__global__ __launch_bounds__(256) void ln_mod_k(const float* __restrict__ x) {
    int l = blockIdx.x, t = threadIdx.x;
    const float* xr = x + (size_t)l * HID;
    float s = 0.f, s2 = 0.f;
    for (int j = t; j < HID; j += 256) { float v = xr[j]; s += v; s2 += v * v; }
    __shared__ float sh[16];
    #pragma unroll
    for (int o = 16; o; o >>= 1) {
        s  += __shfl_xor_sync(0xffffffffu, s, o);
        s2 += __shfl_xor_sync(0xffffffffu, s2, o);
    }
    if ((t & 31) == 0) { sh[t >> 5] = s; sh[8 + (t >> 5)] = s2; }
    __syncthreads();
    float ts = 0.f, ts2 = 0.f;
    #pragma unroll
    for (int i = 0; i < 8; i++) { ts += sh[i]; ts2 += sh[8 + i]; }
    float mu = ts * (1.f / HID);
    float var = ts2 * (1.f / HID) - mu * mu;
    float r = rsqrtf(var + 1e-6f);
    for (int u = t; u < HID / 8; u += 256) {
        int j0 = u * 8;
        __half2 hp[4];
        #pragma unroll
        for (int e = 0; e < 4; e++) {
            int j = j0 + 2 * e;
            float v0 = (xr[j] - mu) * r;
            float v1 = (xr[j + 1] - mu) * r;
            hp[e] = __floats2half2_rn((1.f + g_m[HID + j]) * v0 + g_m[j],
                                      (1.f + g_m[HID + j + 1]) * v1 + g_m[j + 1]);
        }
        uint4 o;
        o.x = *(uint32_t*)&hp[0]; o.y = *(uint32_t*)&hp[1];
        o.z = *(uint32_t*)&hp[2]; o.w = *(uint32_t*)&hp[3];
        *(uint4*)(g_xmod2 + tiled_off(L, l, j0)) = o;
    }
}

__global__ __launch_bounds__(256) void lora_down_s(
    const __half* __restrict__ X, const float* __restrict__ D0,
    const float* __restrict__ D1, const float* __restrict__ D2,
    float* __restrict__ Yp, int nc, int kbase, int K,
    long long zs, long long ms, int ldy)
{
    __shared__ float xs[64][65];
    __shared__ float ds[64][32];
    int t = threadIdx.x;
    int m0 = blockIdx.x * 64;
    int mat = blockIdx.y, z = blockIdx.z;
    const float* D = (mat == 0) ? D0 : ((mat == 1) ? D1 : D2);
    float* Y = Yp + (size_t)z * zs + (size_t)mat * ms;
    int tx = t & 31, ty = t >> 5;
    int drow = t >> 3, df4 = t & 7;
    float acc[8] = {};
    int k0b = (kbase + z * nc) * 64;

    for (int c = 0; c < nc; c++) {
        int k0 = k0b + c * 64;
        #pragma unroll
        for (int j = 0; j < 4; j++) {
            int slot = t + j * 256;
            int row = slot >> 4, c4 = (slot & 15) * 4;
            uint2 u = *(const uint2*)(X + tiled_off(L, m0 + row, k0 + c4));
            __half2 ab = *(__half2*)&u.x, cd = *(__half2*)&u.y;
            float2 f0 = __half22float2(ab), f1 = __half22float2(cd);
            xs[c4][row] = f0.x; xs[c4 + 1][row] = f0.y;
            xs[c4 + 2][row] = f1.x; xs[c4 + 3][row] = f1.y;
        }
        #pragma unroll
        for (int j = 0; j < 2; j++) {
            int kk = (df4 + 8 * j) * 4;
            float4 vd = *(const float4*)(D + (size_t)drow * K + k0 + kk);
            ds[kk][drow] = vd.x; ds[kk + 1][drow] = vd.y;
            ds[kk + 2][drow] = vd.z; ds[kk + 3][drow] = vd.w;
        }
        __syncthreads();
        #pragma unroll
        for (int kk = 0; kk < 64; kk++) {
            float dv = ds[kk][tx];
            #pragma unroll
            for (int i = 0; i < 8; i++) acc[i] += xs[kk][ty * 8 + i] * dv;
        }
        __syncthreads();
    }
    #pragma unroll
    for (int i = 0; i < 8; i++)
        Y[(size_t)(m0 + ty * 8 + i) * ldy + tx] = acc[i];
}

__global__ __launch_bounds__(128) void qkv_finalize(
    const float* __restrict__ q_scale, const float* __restrict__ k_scale,
    const float* __restrict__ pe)
{
    __shared__ float sq[128], sk[128], red[8];

    const int head = blockIdx.x, d = threadIdx.x;
    const int l0 = blockIdx.y * 16;
    const int col = head * HD + d;

    const float qsc = q_scale[d], ksc = k_scale[d];
    const float qsc2 = q_scale[d ^ 1], ksc2 = k_scale[d ^ 1];

    for (int li = 0; li < 16; li++) {
        int l = l0 + li;
        size_t hb = (size_t)l * H3;
        float qv = __half2float(g_hh[hb + col]);
        float kv = __half2float(g_hh[hb + HID + col]);
        float vv = __half2float(g_hh[hb + 2 * HID + col]);

        __syncthreads();
        sq[d] = qv; sk[d] = kv;
        float aq = qv * qv, ak = kv * kv;
        #pragma unroll
        for (int o = 16; o; o >>= 1) {
            aq += __shfl_xor_sync(0xffffffffu, aq, o);
            ak += __shfl_xor_sync(0xffffffffu, ak, o);
        }
        if ((d & 31) == 0) { red[d >> 5] = aq; red[4 + (d >> 5)] = ak; }
        __syncthreads();

        float rq = rsqrtf((red[0] + red[1] + red[2] + red[3]) * (1.f / HD) + 1e-6f);
        float rk = rsqrtf((red[4] + red[5] + red[6] + red[7]) * (1.f / HD) + 1e-6f);

        int e = d & ~1, o_ = d | 1;
        float sce = (d & 1) ? qsc2 : qsc;
        float sco = (d & 1) ? qsc : qsc2;
        float kce = (d & 1) ? ksc2 : ksc;
        float kco = (d & 1) ? ksc : ksc2;
        float q0 = sq[e]  * rq * sce;
        float q1 = sq[o_] * rq * sco;
        float k0 = sk[e]  * rk * kce;
        float k1 = sk[o_] * rk * kco;

        const float* p = pe + ((size_t)l * 64 + (d >> 1)) * 4;
        float qo = (d & 1) ? (p[2] * q0 + p[3] * q1) : (p[0] * q0 + p[1] * q1);
        float ko = (d & 1) ? (p[2] * k0 + p[3] * k1) : (p[0] * k0 + p[1] * k1);

        {
            int q8 = d >> 3, sub = d >> 6;
            int sr = l * 2 + sub;
            size_t off = ((size_t)head * L + l) * 128 + (size_t)sub * 64 +
                         (size_t)(((q8 & 7) ^ (sr & 7)) << 3) + (d & 7);
            g_q2[off] = __float2half(qo);
            g_k2[off] = __float2half(ko);
        }
        {
            int kt = l >> 7, lc = l & 127;
            int q8 = lc >> 3;
            int sr = d * 2 + (q8 >> 3);
            size_t off = ((size_t)(head * 16 + kt)) * 16384 + (size_t)sr * 64 +
                         (size_t)(((q8 & 7) ^ (sr & 7)) << 3) + (lc & 7);
            g_v2[off] = __float2half(vv);
        }
    }
}

__global__ __launch_bounds__(256) void final_k(const float* __restrict__ x,
                                               const float* __restrict__ pu,
                                               const float* __restrict__ b2,
                                               float* __restrict__ out)
{
    int l = blockIdx.y;
    int c = blockIdx.x * 256 + threadIdx.x;
    __shared__ float sp[64];
    if (threadIdx.x < 64) {
        float s = 0.f;
        #pragma unroll
        for (int z = 0; z < 8; z++)
            s += g_plp[(size_t)z * L * 64 + (size_t)l * 64 + threadIdx.x];
        sp[threadIdx.x] = s;
    }
    __syncthreads();

    const float4* ur = (const float4*)(pu + (size_t)c * 64);
    float a = 0.f;
    #pragma unroll
    for (int r = 0; r < 16; r++) {
        float4 u = ur[r];
        a += u.x * sp[4 * r] + u.y * sp[4 * r + 1] + u.z * sp[4 * r + 2] + u.w * sp[4 * r + 3];
    }
    size_t idx = (size_t)l * HID + c;
    const size_t LH = (size_t)L * HID;
    float o = g_o[idx] + g_o[idx + LH] + g_o[idx + 2 * LH] + g_o[idx + 3 * LH] + b2[c] + a;
    out[idx] = x[idx] + g_m[2 * HID + c] * o;
}

// ================= launch =================
extern "C" void kernel_launch(void* const* d_in, const int* in_sizes, int n_in,
                              void* d_out, int out_size)
{
    const float* x   = (const float*)d_in[0];
    const float* vec = (const float*)d_in[1];
    const float* pe  = (const float*)d_in[2];
    const float* mw  = (const float*)d_in[3];
    const float* mb  = (const float*)d_in[4];
    const float* w1  = (const float*)d_in[5];
    const float* b1  = (const float*)d_in[6];
    const float* w2  = (const float*)d_in[7];
    const float* b2  = (const float*)d_in[8];
    const float* qs  = (const float*)d_in[9];
    const float* ks  = (const float*)d_in[10];
    const float* lqd = (const float*)d_in[11];
    const float* lqu = (const float*)d_in[12];
    const float* lkd = (const float*)d_in[13];
    const float* lku = (const float*)d_in[14];
    const float* lvd = (const float*)d_in[15];
    const float* lvu = (const float*)d_in[16];
    const float* pd  = (const float*)d_in[17];
    const float* pu  = (const float*)d_in[18];
    float* out = (float*)d_out;

    float *y1p, *plp, *ob;
    __half *xmod2, *w12, *w22, *cat2, *q2, *k2, *v2;
    cudaGetSymbolAddress((void**)&y1p,   g_y1p);
    cudaGetSymbolAddress((void**)&plp,   g_plp);
    cudaGetSymbolAddress((void**)&ob,    g_o);
    cudaGetSymbolAddress((void**)&xmod2, g_xmod2);
    cudaGetSymbolAddress((void**)&w12,   g_w12);
    cudaGetSymbolAddress((void**)&w22,   g_w22);
    cudaGetSymbolAddress((void**)&cat2,  g_cat2);
    cudaGetSymbolAddress((void**)&q2,    g_q2);
    cudaGetSymbolAddress((void**)&k2,    g_k2);
    cudaGetSymbolAddress((void**)&v2,    g_v2);

    const int SMG = 3 * 48 * 1024 + 64;
    const int SMF = 5 * 32 * 1024 + 64;

    static cudaStream_t s1 = 0, s2 = 0;
    static cudaEvent_t evRoot = 0, evLn = 0, evW1 = 0, evUp = 0, evW2 = 0;
    static cudaEvent_t evQKV = 0, evMLP = 0, evFlash = 0, evG2m = 0, evLpm = 0;
    static bool init_done = false;
    if (!init_done) {
        cudaFuncSetAttribute(gemm512<1>, cudaFuncAttributeMaxDynamicSharedMemorySize, SMG);
        cudaFuncSetAttribute(gemm512<0>, cudaFuncAttributeMaxDynamicSharedMemorySize, SMG);
        cudaFuncSetAttribute(flash_k,    cudaFuncAttributeMaxDynamicSharedMemorySize, SMF);
        cudaStreamCreateWithFlags(&s1, cudaStreamNonBlocking);
        cudaStreamCreateWithFlags(&s2, cudaStreamNonBlocking);
        cudaEventCreateWithFlags(&evRoot, cudaEventDisableTiming);
        cudaEventCreateWithFlags(&evLn,   cudaEventDisableTiming);
        cudaEventCreateWithFlags(&evW1,   cudaEventDisableTiming);
        cudaEventCreateWithFlags(&evUp,   cudaEventDisableTiming);
        cudaEventCreateWithFlags(&evW2,   cudaEventDisableTiming);
        cudaEventCreateWithFlags(&evQKV,  cudaEventDisableTiming);
        cudaEventCreateWithFlags(&evMLP,  cudaEventDisableTiming);
        cudaEventCreateWithFlags(&evFlash,cudaEventDisableTiming);
        cudaEventCreateWithFlags(&evG2m,  cudaEventDisableTiming);
        cudaEventCreateWithFlags(&evLpm,  cudaEventDisableTiming);
        init_done = true;
    }

    cudaEventRecord(evRoot, 0);
    cudaStreamWaitEvent(s1, evRoot, 0);
    cudaStreamWaitEvent(s2, evRoot, 0);

    // ---- phase 0: independent prep ----
    // s1: conv_w1 (needed by both gemm1 parts)
    conv_tile<<<(int)(((size_t)H1 * HID / 8 + 255) / 256), 256, 0, s1>>>(
        w1, w12, H1, HID, (size_t)H1 * HID / 8);
    cudaEventRecord(evW1, s1);
    // s2: up-ext then conv_w2 (both input-only)
    upext_k<<<(H3 * 128) / 256, 256, 0, s2>>>(lqu, lku, lvu);
    cudaEventRecord(evUp, s2);
    conv_tile<<<(int)(((size_t)HID * CATD / 8 + 255) / 256), 256, 0, s2>>>(
        w2, w22, HID, CATD, (size_t)HID * CATD / 8);
    cudaEventRecord(evW2, s2);
    // s0: modulation + layernorm
    mod_gemv<<<(3 * HID) / 8, 256>>>(vec, mw, mb);
    ln_mod_k<<<L, 256>>>(x);
    cudaEventRecord(evLn, 0);

    // ---- phase 1 (critical path on s0): qkv lora -> yext -> gemm1-QKV ----
    lora_down_s<<<dim3(L / 64, 3, 4), 256>>>(
        xmod2, lqd, lkd, lvd, y1p, 12, 0, HID,
        3LL * L * 32, (long long)L * 32, 32);
    yext_k<<<(L * 32) / 256, 256>>>();
    cudaStreamWaitEvent(0, evW1, 0);
    cudaStreamWaitEvent(0, evUp, 0);
    gemm512<1><<<dim3(L / 128, 36, 1), 512, SMG>>>(
        xmod2, w12, nullptr, b1, cat2, 50, 0, 0, L, H1, 0, 0LL);
    cudaEventRecord(evQKV, 0);

    // ---- phase 2a (s1): gemm1-MLP after QKV completes (runs ∥ flash chain) ----
    cudaStreamWaitEvent(s1, evQKV, 0);
    cudaStreamWaitEvent(s1, evLn, 0);
    gemm512<1><<<dim3(L / 128, 48, 1), 512, SMG, s1>>>(
        xmod2, w12, nullptr, b1, cat2, 48, 0, 36, L, H1, 0, 0LL);
    cudaEventRecord(evMLP, s1);
    // s1: gemm2 over MLP K-chunks -> g_o[0..1]
    cudaStreamWaitEvent(s1, evW2, 0);
    gemm512<0><<<dim3(L / 128, HID / 256, 2), 512, SMG, s1>>>(
        cat2, w22, ob, nullptr, nullptr, 96, 48, 0, L, HID, HID, (long long)L * HID);
    cudaEventRecord(evG2m, s1);

    // ---- phase 2b (s0): finalize -> flash -> gemm2-attn -> proj-lora-attn ----
    qkv_finalize<<<dim3(HEADS, L / 16), 128>>>(qs, ks, pe);
    flash_k<<<dim3(L / 128, HEADS), 256, SMF>>>(q2, k2, v2, cat2);
    cudaEventRecord(evFlash, 0);
    cudaStreamWaitEvent(0, evW2, 0);
    gemm512<0><<<dim3(L / 128, HID / 256, 2), 512, SMG>>>(
        cat2, w22, ob + 2 * (size_t)L * HID, nullptr, nullptr, 24, 0, 0, L, HID, HID,
        (long long)L * HID);
    lora_down_s<<<dim3(L / 64, 2, 2), 256>>>(
        cat2, pd, pd + (size_t)32 * CATD, nullptr, plp + 6 * (size_t)L * 64, 24, 0, CATD,
        (long long)L * 64, 32LL, 64);

    // ---- phase 2c (s2): proj lora over MLP chunks (after gemm1-MLP) ----
    cudaStreamWaitEvent(s2, evMLP, 0);
    lora_down_s<<<dim3(L / 64, 2, 6), 256, 0, s2>>>(
        cat2, pd, pd + (size_t)32 * CATD, nullptr, plp, 32, 48, CATD,
        (long long)L * 64, 32LL, 64);
    cudaEventRecord(evLpm, s2);

    // ---- join ----
    cudaStreamWaitEvent(0, evG2m, 0);
    cudaStreamWaitEvent(0, evLpm, 0);
    final_k<<<dim3(HID / 256, L), 256>>>(x, pu, b2, out);
}

// round 12
// speedup vs baseline: 1.0333x; 1.0333x over previous
#include <cuda_runtime.h>
#include <cuda_fp16.h>
#include <math.h>
#include <stdint.h>

#define L 2048
#define HID 3072
#define HEADS 24
#define HD 128
#define MLPD 12288
#define H1 21504
#define CATD 15360
#define H3 9216   // 3*HID

// ---------------- scratch ----------------
__device__ float g_m[3 * HID];
__device__ float g_y1p[4 * 3 * (size_t)L * 32];
__device__ float g_plp[8 * (size_t)L * 64];
__device__ float g_o[4 * (size_t)L * HID];

__device__ __half g_hh[(size_t)L * H3];            // qkv part of h (fp16, lora-up included)
__device__ __half g_xmod2[(size_t)L * 3200];       // tiled, chunks 0..47 = x_mod, 48..49 = y-ext
__device__ __half g_w12[(size_t)H1 * 3200];        // tiled, chunks 0..47 = w1, 48..49 = up-ext
__device__ __half g_w22[(size_t)HID * CATD];
__device__ __half g_cat2[(size_t)L * CATD];
__device__ __half g_q2[(size_t)HEADS * L * HD];
__device__ __half g_k2[(size_t)HEADS * L * HD];
__device__ __half g_v2[(size_t)HEADS * HD * L];

// ================= helpers =================
__device__ __forceinline__ uint32_t smem_u32(const void* p) {
    uint32_t a;
    asm("{ .reg .u64 t; cvta.to.shared.u64 t, %1; cvt.u32.u64 %0, t; }" : "=r"(a) : "l"(p));
    return a;
}
__device__ __forceinline__ void mbar_init(uint32_t a, uint32_t cnt) {
    asm volatile("mbarrier.init.shared.b64 [%0], %1;" :: "r"(a), "r"(cnt) : "memory");
}
__device__ __forceinline__ void mbar_expect(uint32_t a, uint32_t bytes) {
    asm volatile("mbarrier.arrive.expect_tx.shared.b64 _, [%0], %1;" :: "r"(a), "r"(bytes) : "memory");
}
__device__ __forceinline__ void mbar_arrive(uint32_t a) {
    asm volatile("mbarrier.arrive.shared.b64 _, [%0];" :: "r"(a) : "memory");
}
__device__ __forceinline__ void mbar_wait(uint32_t a, uint32_t parity) {
    asm volatile(
        "{\n\t.reg .pred P;\n"
        "WL_%=:\n\t"
        "mbarrier.try_wait.parity.acquire.cta.shared::cta.b64 P, [%0], %1, 0x989680;\n\t"
        "@P bra WD_%=;\n\t"
        "bra WL_%=;\n"
        "WD_%=:\n\t}"
        :: "r"(a), "r"(parity) : "memory");
}
__device__ __forceinline__ void bulk_g2s(uint32_t dst, const void* src, uint32_t bytes, uint32_t mbar) {
    asm volatile(
        "cp.async.bulk.shared::cta.global.mbarrier::complete_tx::bytes [%0], [%1], %2, [%3];"
        :: "r"(dst), "l"(src), "r"(bytes), "r"(mbar) : "memory");
}
__device__ __forceinline__ void ldsm4(uint32_t& r0, uint32_t& r1, uint32_t& r2, uint32_t& r3,
                                      uint32_t addr) {
    asm volatile("ldmatrix.sync.aligned.m8n8.x4.shared.b16 {%0,%1,%2,%3}, [%4];"
                 : "=r"(r0), "=r"(r1), "=r"(r2), "=r"(r3) : "r"(addr));
}
__device__ __forceinline__ void mma16816(float* d, const uint32_t* a, const uint32_t* b) {
    asm volatile(
        "mma.sync.aligned.m16n8k16.row.col.f32.f16.f16.f32 "
        "{%0,%1,%2,%3}, {%4,%5,%6,%7}, {%8,%9}, {%0,%1,%2,%3};"
        : "+f"(d[0]), "+f"(d[1]), "+f"(d[2]), "+f"(d[3])
        : "r"(a[0]), "r"(a[1]), "r"(a[2]), "r"(a[3]), "r"(b[0]), "r"(b[1]));
}
__device__ __forceinline__ uint32_t packh2(float a, float b) {
    __half2 h = __floats2half2_rn(a, b);
    return *(uint32_t*)&h;
}
__device__ __forceinline__ float gelu1(float x) {
    return 0.5f * x * (1.f + tanhf(0.7978845608028654f * (x + 0.044715f * x * x * x)));
}
__device__ __forceinline__ uint32_t swz128(uint32_t base, int r, int q) {
    return base + (uint32_t)r * 128u + ((uint32_t)(q ^ (r & 7)) << 4);
}
__device__ __forceinline__ uint32_t swz256(uint32_t base, int r, int q8) {
    int sr = r * 2 + (q8 >> 3);
    int q = q8 & 7;
    return base + (uint32_t)sr * 128u + ((uint32_t)(q ^ (sr & 7)) << 4);
}
__device__ __forceinline__ size_t tiled_off(int M, int r, int c) {
    return ((size_t)(c >> 6) * M + r) * 64 + (size_t)((((c & 63) >> 3) ^ (r & 7)) << 3) + (c & 7);
}

// ================= bulk-fed fp16 NT GEMM (warp-async pipeline) =================
// full[3] mbarriers at mbar+0/8/16 (tx-based); empty[3] at mbar+24/32/40 (count=16).
// No per-chunk __syncthreads: warps arrive on empty[stg]; only t0 waits before reissue.
template <int MODE>
__global__ __launch_bounds__(512, 1) void gemm512(
    const __half* __restrict__ At, const __half* __restrict__ Bt,
    float* __restrict__ C, const float* __restrict__ bias,
    __half* __restrict__ catp, int nc, int kbase, int nbase,
    int M, int N, int ldc, long long zsC)
{
    constexpr uint32_t ABYTES = 128u * 128u;
    constexpr uint32_t BBYTES = 256u * 128u;
    constexpr uint32_t STAGE = ABYTES + BBYTES;

    extern __shared__ char smraw[];
    uint32_t s0 = smem_u32(smraw);
    uint32_t mbar = s0 + 3u * STAGE;

    const int t = threadIdx.x, w = t >> 5, lane = t & 31;
    const int wm = w & 3, wn = w >> 2;
    const int m0 = blockIdx.x * 128, n0 = (nbase + blockIdx.y) * 256;
    const int z = blockIdx.z;
    const int c0 = kbase + z * nc;
    C += (size_t)z * zsC;

    if (t == 0) {
        mbar_init(mbar, 1); mbar_init(mbar + 8, 1); mbar_init(mbar + 16, 1);
        mbar_init(mbar + 24, 16); mbar_init(mbar + 32, 16); mbar_init(mbar + 40, 16);
    }
    __syncthreads();

    auto issue = [&](int c, int stg) {
        uint32_t mb = mbar + (uint32_t)stg * 8u;
        uint32_t ab = s0 + (uint32_t)stg * STAGE;
        mbar_expect(mb, ABYTES + BBYTES);
        bulk_g2s(ab, At + ((size_t)(c0 + c) * M + m0) * 64, ABYTES, mb);
        bulk_g2s(ab + ABYTES, Bt + ((size_t)(c0 + c) * N + n0) * 64, BBYTES, mb);
    };

    if (t == 0) { issue(0, 0); issue(1, 1); issue(2, 2); }

    float acc[2][8][4] = {};
    uint32_t phf[3] = {0u, 0u, 0u};
    uint32_t phe[3] = {0u, 0u, 0u};

    for (int c = 0; c < nc; c++) {
        int stg = c % 3;
        mbar_wait(mbar + (uint32_t)stg * 8u, phf[stg]);
        phf[stg] ^= 1u;

        uint32_t ab = s0 + (uint32_t)stg * STAGE;
        uint32_t bb = ab + ABYTES;

        #pragma unroll
        for (int s = 0; s < 4; s++) {
            uint32_t Af[2][4];
            #pragma unroll
            for (int mt = 0; mt < 2; mt++) {
                int r = wm * 32 + mt * 16 + (lane & 15);
                int q = s * 2 + (lane >> 4);
                ldsm4(Af[mt][0], Af[mt][1], Af[mt][2], Af[mt][3], swz128(ab, r, q));
            }
            uint32_t Bf[8][2];
            #pragma unroll
            for (int np = 0; np < 4; np++) {
                int r = wn * 64 + np * 16 + ((lane >> 4) << 3) + (lane & 7);
                int q = s * 2 + ((lane >> 3) & 1);
                ldsm4(Bf[2 * np][0], Bf[2 * np][1], Bf[2 * np + 1][0], Bf[2 * np + 1][1],
                      swz128(bb, r, q));
            }
            #pragma unroll
            for (int mt = 0; mt < 2; mt++)
                #pragma unroll
                for (int nt = 0; nt < 8; nt++)
                    mma16816(acc[mt][nt], Af[mt], Bf[nt]);
        }

        // warp done reading stage stg for this chunk
        if (lane == 0) mbar_arrive(mbar + 24u + (uint32_t)stg * 8u);
        // producer (t0) waits for all 16 warps, then reuses the stage
        if (t == 0 && c + 3 < nc) {
            mbar_wait(mbar + 24u + (uint32_t)stg * 8u, phe[stg]);
            phe[stg] ^= 1u;
            issue(c + 3, stg);
        }
    }

    #pragma unroll
    for (int mt = 0; mt < 2; mt++) {
        int row = m0 + wm * 32 + mt * 16 + (lane >> 2);
        #pragma unroll
        for (int nt = 0; nt < 8; nt++) {
            int col = n0 + wn * 64 + nt * 8 + (lane & 3) * 2;
            if (MODE == 1) {
                float b0 = bias[col], b1v = bias[col + 1];
                float v00 = acc[mt][nt][0] + b0, v01 = acc[mt][nt][1] + b1v;
                float v10 = acc[mt][nt][2] + b0, v11 = acc[mt][nt][3] + b1v;
                if (n0 >= H3) {
                    int cc = col - 6144;
                    *(__half2*)(catp + tiled_off(L, row, cc)) =
                        __floats2half2_rn(gelu1(v00), gelu1(v01));
                    *(__half2*)(catp + tiled_off(L, row + 8, cc)) =
                        __floats2half2_rn(gelu1(v10), gelu1(v11));
                } else {
                    *(__half2*)(g_hh + (size_t)row * H3 + col) = __floats2half2_rn(v00, v01);
                    *(__half2*)(g_hh + (size_t)(row + 8) * H3 + col) = __floats2half2_rn(v10, v11);
                }
            } else {
                *(float2*)(C + (size_t)row * ldc + col) =
                    make_float2(acc[mt][nt][0], acc[mt][nt][1]);
                *(float2*)(C + (size_t)(row + 8) * ldc + col) =
                    make_float2(acc[mt][nt][2], acc[mt][nt][3]);
            }
        }
    }
}

// ================= flash attention =================
__global__ __launch_bounds__(256, 1) void flash_k(
    const __half* __restrict__ Qg, const __half* __restrict__ Kg,
    const __half* __restrict__ Vg, __half* __restrict__ catp)
{
    extern __shared__ char smraw[];
    uint32_t s0 = smem_u32(smraw);
    const uint32_t sQ = s0;
    const uint32_t sK[2] = {s0 + 32768u, s0 + 98304u};
    const uint32_t sV[2] = {s0 + 65536u, s0 + 131072u};
    const uint32_t mbar = s0 + 163840u;

    const int t = threadIdx.x, w = t >> 5, lane = t & 31;
    const int qt = blockIdx.x, head = blockIdx.y;

    const __half* Qp = Qg + ((size_t)head * L + qt * 128) * 128;
    const __half* Kp = Kg + (size_t)head * L * 128;
    const __half* Vp = Vg + (size_t)head * 16 * 16384;

    if (t == 0) { mbar_init(mbar, 1); mbar_init(mbar + 8, 1); }
    __syncthreads();
    if (t == 0) {
        mbar_expect(mbar, 98304u);
        bulk_g2s(sQ, Qp, 32768u, mbar);
        bulk_g2s(sK[0], Kp, 32768u, mbar);
        bulk_g2s(sV[0], Vp, 32768u, mbar);
        mbar_expect(mbar + 8, 65536u);
        bulk_g2s(sK[1], Kp + (size_t)128 * 128, 32768u, mbar + 8);
        bulk_g2s(sV[1], Vp + 16384, 32768u, mbar + 8);
    }

    const float CSC = 0.08838834764831845f * 1.4426950408889634f;
    float m_[2] = {-1e30f, -1e30f}, l_[2] = {0.f, 0.f};
    float oacc[16][4] = {};
    uint32_t ph[2] = {0u, 0u};

    for (int kt = 0; kt < 16; kt++) {
        int buf = kt & 1;
        mbar_wait(mbar + (uint32_t)buf * 8u, ph[buf]);
        ph[buf] ^= 1u;

        float sacc[16][4] = {};
        #pragma unroll
        for (int ks = 0; ks < 8; ks++) {
            uint32_t Af[4];
            {
                int r = w * 16 + (lane & 15);
                int q8 = ks * 2 + (lane >> 4);
                ldsm4(Af[0], Af[1], Af[2], Af[3], swz256(sQ, r, q8));
            }
            uint32_t Bf[16][2];
            #pragma unroll
            for (int np = 0; np < 8; np++) {
                int r = np * 16 + ((lane >> 4) << 3) + (lane & 7);
                int q8 = ks * 2 + ((lane >> 3) & 1);
                ldsm4(Bf[2 * np][0], Bf[2 * np][1], Bf[2 * np + 1][0], Bf[2 * np + 1][1],
                      swz256(sK[buf], r, q8));
            }
            #pragma unroll
            for (int nt = 0; nt < 16; nt++) mma16816(sacc[nt], Af, Bf[nt]);
        }

        #pragma unroll
        for (int h = 0; h < 2; h++) {
            float tm = -1e30f;
            #pragma unroll
            for (int nt = 0; nt < 16; nt++)
                tm = fmaxf(tm, fmaxf(sacc[nt][2 * h], sacc[nt][2 * h + 1]));
            tm *= CSC;
            tm = fmaxf(tm, __shfl_xor_sync(0xffffffffu, tm, 1));
            tm = fmaxf(tm, __shfl_xor_sync(0xffffffffu, tm, 2));
            float mn = fmaxf(m_[h], tm);
            float alpha = exp2f(m_[h] - mn);
            float rs = 0.f;
            #pragma unroll
            for (int nt = 0; nt < 16; nt++) {
                float p0 = exp2f(sacc[nt][2 * h] * CSC - mn);
                float p1 = exp2f(sacc[nt][2 * h + 1] * CSC - mn);
                sacc[nt][2 * h] = p0; sacc[nt][2 * h + 1] = p1;
                rs += p0 + p1;
            }
            rs += __shfl_xor_sync(0xffffffffu, rs, 1);
            rs += __shfl_xor_sync(0xffffffffu, rs, 2);
            l_[h] = l_[h] * alpha + rs;
            m_[h] = mn;
            #pragma unroll
            for (int nt = 0; nt < 16; nt++) { oacc[nt][2 * h] *= alpha; oacc[nt][2 * h + 1] *= alpha; }
        }

        #pragma unroll
        for (int kk = 0; kk < 8; kk++) {
            uint32_t pf[4];
            pf[0] = packh2(sacc[2 * kk][0], sacc[2 * kk][1]);
            pf[1] = packh2(sacc[2 * kk][2], sacc[2 * kk][3]);
            pf[2] = packh2(sacc[2 * kk + 1][0], sacc[2 * kk + 1][1]);
            pf[3] = packh2(sacc[2 * kk + 1][2], sacc[2 * kk + 1][3]);
            uint32_t Bv[16][2];
            #pragma unroll
            for (int np = 0; np < 8; np++) {
                int r = np * 16 + ((lane >> 4) << 3) + (lane & 7);
                int q8 = kk * 2 + ((lane >> 3) & 1);
                ldsm4(Bv[2 * np][0], Bv[2 * np][1], Bv[2 * np + 1][0], Bv[2 * np + 1][1],
                      swz256(sV[buf], r, q8));
            }
            #pragma unroll
            for (int nt = 0; nt < 16; nt++) mma16816(oacc[nt], pf, Bv[nt]);
        }

        __syncthreads();
        if (kt + 2 < 16 && t == 0) {
            mbar_expect(mbar + (uint32_t)buf * 8u, 65536u);
            bulk_g2s(sK[buf], Kp + (size_t)(kt + 2) * 128 * 128, 32768u, mbar + (uint32_t)buf * 8u);
            bulk_g2s(sV[buf], Vp + (size_t)(kt + 2) * 16384, 32768u, mbar + (uint32_t)buf * 8u);
        }
    }

    float inv0 = 1.f / l_[0], inv1 = 1.f / l_[1];
    int row0 = qt * 128 + w * 16 + (lane >> 2);
    #pragma unroll
    for (int nt = 0; nt < 16; nt++) {
        int col = head * 128 + nt * 8 + (lane & 3) * 2;
        *(__half2*)(catp + tiled_off(L, row0, col)) =
            __floats2half2_rn(oacc[nt][0] * inv0, oacc[nt][1] * inv0);
        *(__half2*)(catp + tiled_off(L, row0 + 8, col)) =
            __floats2half2_rn(oacc[nt][2] * inv1, oacc[nt][3] * inv1);
    }
}

// ================= conversions =================
__global__ void conv_tile(const float* __restrict__ src, __half* __restrict__ dst,
                          int N, int K, long long n8) {
    long long i = (long long)blockIdx.x * 256 + threadIdx.x;
    if (i >= n8) return;
    int kq = K >> 3;
    int r = (int)(i / kq), q8i = (int)(i - (long long)r * kq);
    int c0 = q8i * 8;
    const float4* s = (const float4*)(src + (size_t)r * K + c0);
    float4 a = s[0], b = s[1];
    __half2 h0 = __floats2half2_rn(a.x, a.y);
    __half2 h1 = __floats2half2_rn(a.z, a.w);
    __half2 h2 = __floats2half2_rn(b.x, b.y);
    __half2 h3 = __floats2half2_rn(b.z, b.w);
    uint4 o;
    o.x = *(uint32_t*)&h0; o.y = *(uint32_t*)&h1;
    o.z = *(uint32_t*)&h2; o.w = *(uint32_t*)&h3;
    *(uint4*)(dst + tiled_off(N, r, c0)) = o;
}

__global__ void upext_k(const float* __restrict__ upq, const float* __restrict__ upk,
                        const float* __restrict__ upv) {
    int i = blockIdx.x * 256 + threadIdx.x;
    int o = i >> 7, j = i & 127;
    int mat = o / HID, colm = o - mat * HID;
    int jj = j - mat * 32;
    float v = 0.f;
    if (j < 96 && jj >= 0 && jj < 32) {
        const float* up = (mat == 0) ? upq : (mat == 1) ? upk : upv;
        v = up[(size_t)colm * 32 + jj];
    }
    g_w12[tiled_off(H1, o, 3072 + j)] = __float2half(v);
}

__global__ void yext_k() {
    int i = blockIdx.x * 256 + threadIdx.x;
    int l = i >> 5, j = i & 31;
    float s0 = 0.f, s1 = 0.f, s2 = 0.f;
    #pragma unroll
    for (int z = 0; z < 4; z++) {
        size_t base = (size_t)z * 3 * L * 32 + (size_t)l * 32 + j;
        s0 += g_y1p[base];
        s1 += g_y1p[base + (size_t)L * 32];
        s2 += g_y1p[base + 2 * (size_t)L * 32];
    }
    g_xmod2[tiled_off(L, l, 3072 + j)]  = __float2half(s0);
    g_xmod2[tiled_off(L, l, 3104 + j)]  = __float2half(s1);
    g_xmod2[tiled_off(L, l, 3136 + j)]  = __float2half(s2);
    g_xmod2[tiled_off(L, l, 3168 + j)]  = __float2half(0.f);
}

// ================= small kernels =================
__global__ __launch_bounds__(256) void mod_gemv(const float* __restrict__ vec,
                                                const float* __restrict__ W,
                                                const float* __restrict__ b) {
    __shared__ float sv[HID];
    int t = threadIdx.x;
    for (int j = t; j < HID; j += 256) {
        float v = vec[j];
        sv[j] = v / (1.f + expf(-v));
    }
    __syncthreads();
    int o = blockIdx.x * 8 + (t >> 5);
    int lane = t & 31;
    const float* w = W + (size_t)o * HID;
    float acc = 0.f;
    for (int k = lane; k < HID; k += 32) acc += sv[k] * w[k];
    #pragma unroll
    for (int s = 16; s; s >>= 1) acc += __shfl_xor_sync(0xffffffffu, acc, s);
    if (lane == 0) g_m[o] = acc + b[o];
}

__global__ __launch_bounds__(256) void ln_mod_k(const float* __restrict__ x) {
    int l = blockIdx.x, t = threadIdx.x;
    const float* xr = x + (size_t)l * HID;
    float s = 0.f, s2 = 0.f;
    for (int j = t; j < HID; j += 256) { float v = xr[j]; s += v; s2 += v * v; }
    __shared__ float sh[16];
    #pragma unroll
    for (int o = 16; o; o >>= 1) {
        s  += __shfl_xor_sync(0xffffffffu, s, o);
        s2 += __shfl_xor_sync(0xffffffffu, s2, o);
    }
    if ((t & 31) == 0) { sh[t >> 5] = s; sh[8 + (t >> 5)] = s2; }
    __syncthreads();
    float ts = 0.f, ts2 = 0.f;
    #pragma unroll
    for (int i = 0; i < 8; i++) { ts += sh[i]; ts2 += sh[8 + i]; }
    float mu = ts * (1.f / HID);
    float var = ts2 * (1.f / HID) - mu * mu;
    float r = rsqrtf(var + 1e-6f);
    for (int u = t; u < HID / 8; u += 256) {
        int j0 = u * 8;
        __half2 hp[4];
        #pragma unroll
        for (int e = 0; e < 4; e++) {
            int j = j0 + 2 * e;
            float v0 = (xr[j] - mu) * r;
            float v1 = (xr[j + 1] - mu) * r;
            hp[e] = __floats2half2_rn((1.f + g_m[HID + j]) * v0 + g_m[j],
                                      (1.f + g_m[HID + j + 1]) * v1 + g_m[j + 1]);
        }
        uint4 o;
        o.x = *(uint32_t*)&hp[0]; o.y = *(uint32_t*)&hp[1];
        o.z = *(uint32_t*)&hp[2]; o.w = *(uint32_t*)&hp[3];
        *(uint4*)(g_xmod2 + tiled_off(L, l, j0)) = o;
    }
}

__global__ __launch_bounds__(256) void lora_down_s(
    const __half* __restrict__ X, const float* __restrict__ D0,
    const float* __restrict__ D1, const float* __restrict__ D2,
    float* __restrict__ Yp, int nc, int kbase, int K,
    long long zs, long long ms, int ldy)
{
    __shared__ float xs[64][65];
    __shared__ float ds[64][32];
    int t = threadIdx.x;
    int m0 = blockIdx.x * 64;
    int mat = blockIdx.y, z = blockIdx.z;
    const float* D = (mat == 0) ? D0 : ((mat == 1) ? D1 : D2);
    float* Y = Yp + (size_t)z * zs + (size_t)mat * ms;
    int tx = t & 31, ty = t >> 5;
    int drow = t >> 3, df4 = t & 7;
    float acc[8] = {};
    int k0b = (kbase + z * nc) * 64;

    for (int c = 0; c < nc; c++) {
        int k0 = k0b + c * 64;
        #pragma unroll
        for (int j = 0; j < 4; j++) {
            int slot = t + j * 256;
            int row = slot >> 4, c4 = (slot & 15) * 4;
            uint2 u = *(const uint2*)(X + tiled_off(L, m0 + row, k0 + c4));
            __half2 ab = *(__half2*)&u.x, cd = *(__half2*)&u.y;
            float2 f0 = __half22float2(ab), f1 = __half22float2(cd);
            xs[c4][row] = f0.x; xs[c4 + 1][row] = f0.y;
            xs[c4 + 2][row] = f1.x; xs[c4 + 3][row] = f1.y;
        }
        #pragma unroll
        for (int j = 0; j < 2; j++) {
            int kk = (df4 + 8 * j) * 4;
            float4 vd = *(const float4*)(D + (size_t)drow * K + k0 + kk);
            ds[kk][drow] = vd.x; ds[kk + 1][drow] = vd.y;
            ds[kk + 2][drow] = vd.z; ds[kk + 3][drow] = vd.w;
        }
        __syncthreads();
        #pragma unroll
        for (int kk = 0; kk < 64; kk++) {
            float dv = ds[kk][tx];
            #pragma unroll
            for (int i = 0; i < 8; i++) acc[i] += xs[kk][ty * 8 + i] * dv;
        }
        __syncthreads();
    }
    #pragma unroll
    for (int i = 0; i < 8; i++)
        Y[(size_t)(m0 + ty * 8 + i) * ldy + tx] = acc[i];
}

__global__ __launch_bounds__(128) void qkv_finalize(
    const float* __restrict__ q_scale, const float* __restrict__ k_scale,
    const float* __restrict__ pe)
{
    __shared__ float sq[128], sk[128], red[8];

    const int head = blockIdx.x, d = threadIdx.x;
    const int l0 = blockIdx.y * 16;
    const int col = head * HD + d;

    const float qsc = q_scale[d], ksc = k_scale[d];
    const float qsc2 = q_scale[d ^ 1], ksc2 = k_scale[d ^ 1];

    for (int li = 0; li < 16; li++) {
        int l = l0 + li;
        size_t hb = (size_t)l * H3;
        float qv = __half2float(g_hh[hb + col]);
        float kv = __half2float(g_hh[hb + HID + col]);
        float vv = __half2float(g_hh[hb + 2 * HID + col]);

        __syncthreads();
        sq[d] = qv; sk[d] = kv;
        float aq = qv * qv, ak = kv * kv;
        #pragma unroll
        for (int o = 16; o; o >>= 1) {
            aq += __shfl_xor_sync(0xffffffffu, aq, o);
            ak += __shfl_xor_sync(0xffffffffu, ak, o);
        }
        if ((d & 31) == 0) { red[d >> 5] = aq; red[4 + (d >> 5)] = ak; }
        __syncthreads();

        float rq = rsqrtf((red[0] + red[1] + red[2] + red[3]) * (1.f / HD) + 1e-6f);
        float rk = rsqrtf((red[4] + red[5] + red[6] + red[7]) * (1.f / HD) + 1e-6f);

        int e = d & ~1, o_ = d | 1;
        float sce = (d & 1) ? qsc2 : qsc;
        float sco = (d & 1) ? qsc : qsc2;
        float kce = (d & 1) ? ksc2 : ksc;
        float kco = (d & 1) ? ksc : ksc2;
        float q0 = sq[e]  * rq * sce;
        float q1 = sq[o_] * rq * sco;
        float k0 = sk[e]  * rk * kce;
        float k1 = sk[o_] * rk * kco;

        const float* p = pe + ((size_t)l * 64 + (d >> 1)) * 4;
        float qo = (d & 1) ? (p[2] * q0 + p[3] * q1) : (p[0] * q0 + p[1] * q1);
        float ko = (d & 1) ? (p[2] * k0 + p[3] * k1) : (p[0] * k0 + p[1] * k1);

        {
            int q8 = d >> 3, sub = d >> 6;
            int sr = l * 2 + sub;
            size_t off = ((size_t)head * L + l) * 128 + (size_t)sub * 64 +
                         (size_t)(((q8 & 7) ^ (sr & 7)) << 3) + (d & 7);
            g_q2[off] = __float2half(qo);
            g_k2[off] = __float2half(ko);
        }
        {
            int kt = l >> 7, lc = l & 127;
            int q8 = lc >> 3;
            int sr = d * 2 + (q8 >> 3);
            size_t off = ((size_t)(head * 16 + kt)) * 16384 + (size_t)sr * 64 +
                         (size_t)(((q8 & 7) ^ (sr & 7)) << 3) + (lc & 7);
            g_v2[off] = __float2half(vv);
        }
    }
}

__global__ __launch_bounds__(256) void final_k(const float* __restrict__ x,
                                               const float* __restrict__ pu,
                                               const float* __restrict__ b2,
                                               float* __restrict__ out)
{
    int l = blockIdx.y;
    int c = blockIdx.x * 256 + threadIdx.x;
    __shared__ float sp[64];
    if (threadIdx.x < 64) {
        float s = 0.f;
        #pragma unroll
        for (int z = 0; z < 8; z++)
            s += g_plp[(size_t)z * L * 64 + (size_t)l * 64 + threadIdx.x];
        sp[threadIdx.x] = s;
    }
    __syncthreads();

    const float4* ur = (const float4*)(pu + (size_t)c * 64);
    float a = 0.f;
    #pragma unroll
    for (int r = 0; r < 16; r++) {
        float4 u = ur[r];
        a += u.x * sp[4 * r] + u.y * sp[4 * r + 1] + u.z * sp[4 * r + 2] + u.w * sp[4 * r + 3];
    }
    size_t idx = (size_t)l * HID + c;
    const size_t LH = (size_t)L * HID;
    float o = g_o[idx] + g_o[idx + LH] + g_o[idx + 2 * LH] + g_o[idx + 3 * LH] + b2[c] + a;
    out[idx] = x[idx] + g_m[2 * HID + c] * o;
}

// ================= launch (R10 schedule) =================
extern "C" void kernel_launch(void* const* d_in, const int* in_sizes, int n_in,
                              void* d_out, int out_size)
{
    const float* x   = (const float*)d_in[0];
    const float* vec = (const float*)d_in[1];
    const float* pe  = (const float*)d_in[2];
    const float* mw  = (const float*)d_in[3];
    const float* mb  = (const float*)d_in[4];
    const float* w1  = (const float*)d_in[5];
    const float* b1  = (const float*)d_in[6];
    const float* w2  = (const float*)d_in[7];
    const float* b2  = (const float*)d_in[8];
    const float* qs  = (const float*)d_in[9];
    const float* ks  = (const float*)d_in[10];
    const float* lqd = (const float*)d_in[11];
    const float* lqu = (const float*)d_in[12];
    const float* lkd = (const float*)d_in[13];
    const float* lku = (const float*)d_in[14];
    const float* lvd = (const float*)d_in[15];
    const float* lvu = (const float*)d_in[16];
    const float* pd  = (const float*)d_in[17];
    const float* pu  = (const float*)d_in[18];
    float* out = (float*)d_out;

    float *y1p, *plp, *ob;
    __half *xmod2, *w12, *w22, *cat2, *q2, *k2, *v2;
    cudaGetSymbolAddress((void**)&y1p,   g_y1p);
    cudaGetSymbolAddress((void**)&plp,   g_plp);
    cudaGetSymbolAddress((void**)&ob,    g_o);
    cudaGetSymbolAddress((void**)&xmod2, g_xmod2);
    cudaGetSymbolAddress((void**)&w12,   g_w12);
    cudaGetSymbolAddress((void**)&w22,   g_w22);
    cudaGetSymbolAddress((void**)&cat2,  g_cat2);
    cudaGetSymbolAddress((void**)&q2,    g_q2);
    cudaGetSymbolAddress((void**)&k2,    g_k2);
    cudaGetSymbolAddress((void**)&v2,    g_v2);

    const int SMG = 3 * 48 * 1024 + 64;
    const int SMF = 5 * 32 * 1024 + 64;

    static cudaStream_t s1 = 0, s2 = 0;
    static cudaEvent_t evRoot = 0, evLn = 0, evW1 = 0, evUp = 0, evW2 = 0;
    static cudaEvent_t evY = 0, evMLP = 0, evG2m = 0, evLpm = 0;
    static bool init_done = false;
    if (!init_done) {
        cudaFuncSetAttribute(gemm512<1>, cudaFuncAttributeMaxDynamicSharedMemorySize, SMG);
        cudaFuncSetAttribute(gemm512<0>, cudaFuncAttributeMaxDynamicSharedMemorySize, SMG);
        cudaFuncSetAttribute(flash_k,    cudaFuncAttributeMaxDynamicSharedMemorySize, SMF);
        cudaStreamCreateWithFlags(&s1, cudaStreamNonBlocking);
        cudaStreamCreateWithFlags(&s2, cudaStreamNonBlocking);
        cudaEventCreateWithFlags(&evRoot, cudaEventDisableTiming);
        cudaEventCreateWithFlags(&evLn,   cudaEventDisableTiming);
        cudaEventCreateWithFlags(&evW1,   cudaEventDisableTiming);
        cudaEventCreateWithFlags(&evUp,   cudaEventDisableTiming);
        cudaEventCreateWithFlags(&evW2,   cudaEventDisableTiming);
        cudaEventCreateWithFlags(&evY,    cudaEventDisableTiming);
        cudaEventCreateWithFlags(&evMLP,  cudaEventDisableTiming);
        cudaEventCreateWithFlags(&evG2m,  cudaEventDisableTiming);
        cudaEventCreateWithFlags(&evLpm,  cudaEventDisableTiming);
        init_done = true;
    }

    cudaEventRecord(evRoot, 0);
    cudaStreamWaitEvent(s1, evRoot, 0);
    cudaStreamWaitEvent(s2, evRoot, 0);

    // 0,1: s0 modulation + layernorm
    mod_gemv<<<(3 * HID) / 8, 256>>>(vec, mw, mb);
    ln_mod_k<<<L, 256>>>(x);
    cudaEventRecord(evLn, 0);

    // 2,3: s1 conv w1 then gemm1-MLP (profiling slot 3)
    conv_tile<<<(int)(((size_t)H1 * HID / 8 + 255) / 256), 256, 0, s1>>>(
        w1, w12, H1, HID, (size_t)H1 * HID / 8);
    cudaEventRecord(evW1, s1);
    cudaStreamWaitEvent(s1, evLn, 0);
    gemm512<1><<<dim3(L / 128, 48, 1), 512, SMG, s1>>>(
        xmod2, w12, nullptr, b1, cat2, 48, 0, 36, L, H1, 0, 0LL);
    cudaEventRecord(evMLP, s1);

    // s2: up-ext, then qkv lora downs, then y-ext
    upext_k<<<(H3 * 128) / 256, 256, 0, s2>>>(lqu, lku, lvu);
    cudaEventRecord(evUp, s2);
    cudaStreamWaitEvent(s2, evLn, 0);
    lora_down_s<<<dim3(L / 64, 3, 4), 256, 0, s2>>>(
        xmod2, lqd, lkd, lvd, y1p, 12, 0, HID,
        3LL * L * 32, (long long)L * 32, 32);
    yext_k<<<(L * 32) / 256, 256, 0, s2>>>();
    cudaEventRecord(evY, s2);

    // s1: conv w2
    conv_tile<<<(int)(((size_t)HID * CATD / 8 + 255) / 256), 256, 0, s1>>>(
        w2, w22, HID, CATD, (size_t)HID * CATD / 8);
    cudaEventRecord(evW2, s1);

    // s0: gemm1-QKV (48 x_mod chunks + 2 lora-ext chunks)
    cudaStreamWaitEvent(0, evW1, 0);
    cudaStreamWaitEvent(0, evUp, 0);
    cudaStreamWaitEvent(0, evY, 0);
    gemm512<1><<<dim3(L / 128, 36, 1), 512, SMG>>>(
        xmod2, w12, nullptr, b1, cat2, 50, 0, 0, L, H1, 0, 0LL);

    // s0: finalize + flash
    qkv_finalize<<<dim3(HEADS, L / 16), 128>>>(qs, ks, pe);
    flash_k<<<dim3(L / 128, HEADS), 256, SMF>>>(q2, k2, v2, cat2);

    // s1: gemm2 over MLP K-chunks -> g_o[0..1]
    gemm512<0><<<dim3(L / 128, HID / 256, 2), 512, SMG, s1>>>(
        cat2, w22, ob, nullptr, nullptr, 96, 48, 0, L, HID, HID, (long long)L * HID);
    cudaEventRecord(evG2m, s1);

    // s2: proj lora over MLP K-chunks -> plp[0..5]
    cudaStreamWaitEvent(s2, evMLP, 0);
    lora_down_s<<<dim3(L / 64, 2, 6), 256, 0, s2>>>(
        cat2, pd, pd + (size_t)32 * CATD, nullptr, plp, 32, 48, CATD,
        (long long)L * 64, 32LL, 64);
    cudaEventRecord(evLpm, s2);

    // s0: gemm2 attn chunks -> g_o[2..3], proj lora attn -> plp[6..7]
    cudaStreamWaitEvent(0, evW2, 0);
    gemm512<0><<<dim3(L / 128, HID / 256, 2), 512, SMG>>>(
        cat2, w22, ob + 2 * (size_t)L * HID, nullptr, nullptr, 24, 0, 0, L, HID, HID,
        (long long)L * HID);
    lora_down_s<<<dim3(L / 64, 2, 2), 256>>>(
        cat2, pd, pd + (size_t)32 * CATD, nullptr, plp + 6 * (size_t)L * 64, 24, 0, CATD,
        (long long)L * 64, 32LL, 64);

    // join
    cudaStreamWaitEvent(0, evG2m, 0);
    cudaStreamWaitEvent(0, evLpm, 0);
    final_k<<<dim3(HID / 256, L), 256>>>(x, pu, b2, out);
}

// round 13
// speedup vs baseline: 1.0714x; 1.0369x over previous
#include <cuda_runtime.h>
#include <cuda_fp16.h>
#include <math.h>
#include <stdint.h>

#define L 2048
#define HID 3072
#define HEADS 24
#define HD 128
#define MLPD 12288
#define H1 21504
#define CATD 15360
#define H3 9216   // 3*HID

// ---------------- scratch ----------------
__device__ float g_m[3 * HID];
__device__ float g_y1p[4 * 3 * (size_t)L * 32];
__device__ float g_plp[8 * (size_t)L * 64];
__device__ float g_o[4 * (size_t)L * HID];

__device__ __half g_hh[(size_t)L * H3];
__device__ __half g_xmod2[(size_t)L * 3200];
__device__ __half g_w12[(size_t)H1 * 3200];
__device__ __half g_w22[(size_t)HID * CATD];
__device__ __half g_cat2[(size_t)L * CATD];
__device__ __half g_q2[(size_t)HEADS * L * HD];
__device__ __half g_k2[(size_t)HEADS * L * HD];
__device__ __half g_v2[(size_t)HEADS * HD * L];

// ================= helpers =================
__device__ __forceinline__ uint32_t smem_u32(const void* p) {
    uint32_t a;
    asm("{ .reg .u64 t; cvta.to.shared.u64 t, %1; cvt.u32.u64 %0, t; }" : "=r"(a) : "l"(p));
    return a;
}
__device__ __forceinline__ void mbar_init(uint32_t a, uint32_t cnt) {
    asm volatile("mbarrier.init.shared.b64 [%0], %1;" :: "r"(a), "r"(cnt) : "memory");
}
__device__ __forceinline__ void mbar_expect(uint32_t a, uint32_t bytes) {
    asm volatile("mbarrier.arrive.expect_tx.shared.b64 _, [%0], %1;" :: "r"(a), "r"(bytes) : "memory");
}
__device__ __forceinline__ void mbar_arrive(uint32_t a) {
    asm volatile("mbarrier.arrive.shared.b64 _, [%0];" :: "r"(a) : "memory");
}
__device__ __forceinline__ void mbar_wait(uint32_t a, uint32_t parity) {
    asm volatile(
        "{\n\t.reg .pred P;\n"
        "WL_%=:\n\t"
        "mbarrier.try_wait.parity.acquire.cta.shared::cta.b64 P, [%0], %1, 0x989680;\n\t"
        "@P bra WD_%=;\n\t"
        "bra WL_%=;\n"
        "WD_%=:\n\t}"
        :: "r"(a), "r"(parity) : "memory");
}
__device__ __forceinline__ void bulk_g2s(uint32_t dst, const void* src, uint32_t bytes, uint32_t mbar) {
    asm volatile(
        "cp.async.bulk.shared::cta.global.mbarrier::complete_tx::bytes [%0], [%1], %2, [%3];"
        :: "r"(dst), "l"(src), "r"(bytes), "r"(mbar) : "memory");
}
__device__ __forceinline__ void ldsm4(uint32_t& r0, uint32_t& r1, uint32_t& r2, uint32_t& r3,
                                      uint32_t addr) {
    asm volatile("ldmatrix.sync.aligned.m8n8.x4.shared.b16 {%0,%1,%2,%3}, [%4];"
                 : "=r"(r0), "=r"(r1), "=r"(r2), "=r"(r3) : "r"(addr));
}
__device__ __forceinline__ void mma16816(float* d, const uint32_t* a, const uint32_t* b) {
    asm volatile(
        "mma.sync.aligned.m16n8k16.row.col.f32.f16.f16.f32 "
        "{%0,%1,%2,%3}, {%4,%5,%6,%7}, {%8,%9}, {%0,%1,%2,%3};"
        : "+f"(d[0]), "+f"(d[1]), "+f"(d[2]), "+f"(d[3])
        : "r"(a[0]), "r"(a[1]), "r"(a[2]), "r"(a[3]), "r"(b[0]), "r"(b[1]));
}
__device__ __forceinline__ uint32_t packh2(float a, float b) {
    __half2 h = __floats2half2_rn(a, b);
    return *(uint32_t*)&h;
}
__device__ __forceinline__ float gelu1(float x) {
    return 0.5f * x * (1.f + tanhf(0.7978845608028654f * (x + 0.044715f * x * x * x)));
}
__device__ __forceinline__ uint32_t swz128(uint32_t base, int r, int q) {
    return base + (uint32_t)r * 128u + ((uint32_t)(q ^ (r & 7)) << 4);
}
__device__ __forceinline__ uint32_t swz256(uint32_t base, int r, int q8) {
    int sr = r * 2 + (q8 >> 3);
    int q = q8 & 7;
    return base + (uint32_t)sr * 128u + ((uint32_t)(q ^ (sr & 7)) << 4);
}
__device__ __forceinline__ size_t tiled_off(int M, int r, int c) {
    return ((size_t)(c >> 6) * M + r) * 64 + (size_t)((((c & 63) >> 3) ^ (r & 7)) << 3) + (c & 7);
}

// ================= bulk-fed fp16 NT GEMM (4-stage, rotating producer) =================
// full[4] at mbF (tx, count=1); empty[4] at mbE (count=16).
// Chunk c: stage c&3; full parity (c>>2)&1. Producer for chunk c+4 is warp (c&15),
// which waits empty[c&3] parity (c>>2)&1 after its own arrive, then issues.
template <int MODE>
__global__ __launch_bounds__(512, 1) void gemm512(
    const __half* __restrict__ At, const __half* __restrict__ Bt,
    float* __restrict__ C, const float* __restrict__ bias,
    __half* __restrict__ catp, int nc, int kbase, int nbase,
    int M, int N, int ldc, long long zsC)
{
    constexpr uint32_t ABYTES = 128u * 128u;
    constexpr uint32_t BBYTES = 256u * 128u;
    constexpr uint32_t STAGE = ABYTES + BBYTES;   // 48KB

    extern __shared__ char smraw[];
    uint32_t s0 = smem_u32(smraw);
    uint32_t mbF = s0 + 4u * STAGE;
    uint32_t mbE = mbF + 32u;

    const int t = threadIdx.x, w = t >> 5, lane = t & 31;
    const int wm = w & 3, wn = w >> 2;
    const int m0 = blockIdx.x * 128, n0 = (nbase + blockIdx.y) * 256;
    const int z = blockIdx.z;
    const int c0 = kbase + z * nc;
    C += (size_t)z * zsC;

    if (t == 0) {
        #pragma unroll
        for (int i = 0; i < 4; i++) {
            mbar_init(mbF + (uint32_t)i * 8u, 1);
            mbar_init(mbE + (uint32_t)i * 8u, 16);
        }
    }
    __syncthreads();

    auto issue = [&](int c, int stg) {
        uint32_t mb = mbF + (uint32_t)stg * 8u;
        uint32_t ab = s0 + (uint32_t)stg * STAGE;
        mbar_expect(mb, ABYTES + BBYTES);
        bulk_g2s(ab, At + ((size_t)(c0 + c) * M + m0) * 64, ABYTES, mb);
        bulk_g2s(ab + ABYTES, Bt + ((size_t)(c0 + c) * N + n0) * 64, BBYTES, mb);
    };

    if (t == 0) { issue(0, 0); issue(1, 1); issue(2, 2); issue(3, 3); }

    float acc[2][8][4] = {};

    for (int c = 0; c < nc; c++) {
        int stg = c & 3;
        uint32_t par = (uint32_t)((c >> 2) & 1);
        mbar_wait(mbF + (uint32_t)stg * 8u, par);

        uint32_t ab = s0 + (uint32_t)stg * STAGE;
        uint32_t bb = ab + ABYTES;

        #pragma unroll
        for (int s = 0; s < 4; s++) {
            uint32_t Af[2][4];
            #pragma unroll
            for (int mt = 0; mt < 2; mt++) {
                int r = wm * 32 + mt * 16 + (lane & 15);
                int q = s * 2 + (lane >> 4);
                ldsm4(Af[mt][0], Af[mt][1], Af[mt][2], Af[mt][3], swz128(ab, r, q));
            }
            uint32_t Bf[8][2];
            #pragma unroll
            for (int np = 0; np < 4; np++) {
                int r = wn * 64 + np * 16 + ((lane >> 4) << 3) + (lane & 7);
                int q = s * 2 + ((lane >> 3) & 1);
                ldsm4(Bf[2 * np][0], Bf[2 * np][1], Bf[2 * np + 1][0], Bf[2 * np + 1][1],
                      swz128(bb, r, q));
            }
            #pragma unroll
            for (int mt = 0; mt < 2; mt++)
                #pragma unroll
                for (int nt = 0; nt < 8; nt++)
                    mma16816(acc[mt][nt], Af[mt], Bf[nt]);
        }

        if (lane == 0) {
            mbar_arrive(mbE + (uint32_t)stg * 8u);
            if (c + 4 < nc && w == (c & 15)) {
                mbar_wait(mbE + (uint32_t)stg * 8u, par);
                issue(c + 4, stg);
            }
        }
    }

    #pragma unroll
    for (int mt = 0; mt < 2; mt++) {
        int row = m0 + wm * 32 + mt * 16 + (lane >> 2);
        #pragma unroll
        for (int nt = 0; nt < 8; nt++) {
            int col = n0 + wn * 64 + nt * 8 + (lane & 3) * 2;
            if (MODE == 1) {
                float b0 = bias[col], b1v = bias[col + 1];
                float v00 = acc[mt][nt][0] + b0, v01 = acc[mt][nt][1] + b1v;
                float v10 = acc[mt][nt][2] + b0, v11 = acc[mt][nt][3] + b1v;
                if (n0 >= H3) {
                    int cc = col - 6144;
                    *(__half2*)(catp + tiled_off(L, row, cc)) =
                        __floats2half2_rn(gelu1(v00), gelu1(v01));
                    *(__half2*)(catp + tiled_off(L, row + 8, cc)) =
                        __floats2half2_rn(gelu1(v10), gelu1(v11));
                } else {
                    *(__half2*)(g_hh + (size_t)row * H3 + col) = __floats2half2_rn(v00, v01);
                    *(__half2*)(g_hh + (size_t)(row + 8) * H3 + col) = __floats2half2_rn(v10, v11);
                }
            } else {
                *(float2*)(C + (size_t)row * ldc + col) =
                    make_float2(acc[mt][nt][0], acc[mt][nt][1]);
                *(float2*)(C + (size_t)(row + 8) * ldc + col) =
                    make_float2(acc[mt][nt][2], acc[mt][nt][3]);
            }
        }
    }
}

// ================= flash attention =================
__global__ __launch_bounds__(256, 1) void flash_k(
    const __half* __restrict__ Qg, const __half* __restrict__ Kg,
    const __half* __restrict__ Vg, __half* __restrict__ catp)
{
    extern __shared__ char smraw[];
    uint32_t s0 = smem_u32(smraw);
    const uint32_t sQ = s0;
    const uint32_t sK[2] = {s0 + 32768u, s0 + 98304u};
    const uint32_t sV[2] = {s0 + 65536u, s0 + 131072u};
    const uint32_t mbar = s0 + 163840u;

    const int t = threadIdx.x, w = t >> 5, lane = t & 31;
    const int qt = blockIdx.x, head = blockIdx.y;

    const __half* Qp = Qg + ((size_t)head * L + qt * 128) * 128;
    const __half* Kp = Kg + (size_t)head * L * 128;
    const __half* Vp = Vg + (size_t)head * 16 * 16384;

    if (t == 0) { mbar_init(mbar, 1); mbar_init(mbar + 8, 1); }
    __syncthreads();
    if (t == 0) {
        mbar_expect(mbar, 98304u);
        bulk_g2s(sQ, Qp, 32768u, mbar);
        bulk_g2s(sK[0], Kp, 32768u, mbar);
        bulk_g2s(sV[0], Vp, 32768u, mbar);
        mbar_expect(mbar + 8, 65536u);
        bulk_g2s(sK[1], Kp + (size_t)128 * 128, 32768u, mbar + 8);
        bulk_g2s(sV[1], Vp + 16384, 32768u, mbar + 8);
    }

    const float CSC = 0.08838834764831845f * 1.4426950408889634f;
    float m_[2] = {-1e30f, -1e30f}, l_[2] = {0.f, 0.f};
    float oacc[16][4] = {};
    uint32_t ph[2] = {0u, 0u};

    for (int kt = 0; kt < 16; kt++) {
        int buf = kt & 1;
        mbar_wait(mbar + (uint32_t)buf * 8u, ph[buf]);
        ph[buf] ^= 1u;

        float sacc[16][4] = {};
        #pragma unroll
        for (int ks = 0; ks < 8; ks++) {
            uint32_t Af[4];
            {
                int r = w * 16 + (lane & 15);
                int q8 = ks * 2 + (lane >> 4);
                ldsm4(Af[0], Af[1], Af[2], Af[3], swz256(sQ, r, q8));
            }
            uint32_t Bf[16][2];
            #pragma unroll
            for (int np = 0; np < 8; np++) {
                int r = np * 16 + ((lane >> 4) << 3) + (lane & 7);
                int q8 = ks * 2 + ((lane >> 3) & 1);
                ldsm4(Bf[2 * np][0], Bf[2 * np][1], Bf[2 * np + 1][0], Bf[2 * np + 1][1],
                      swz256(sK[buf], r, q8));
            }
            #pragma unroll
            for (int nt = 0; nt < 16; nt++) mma16816(sacc[nt], Af, Bf[nt]);
        }

        #pragma unroll
        for (int h = 0; h < 2; h++) {
            float tm = -1e30f;
            #pragma unroll
            for (int nt = 0; nt < 16; nt++)
                tm = fmaxf(tm, fmaxf(sacc[nt][2 * h], sacc[nt][2 * h + 1]));
            tm *= CSC;
            tm = fmaxf(tm, __shfl_xor_sync(0xffffffffu, tm, 1));
            tm = fmaxf(tm, __shfl_xor_sync(0xffffffffu, tm, 2));
            float mn = fmaxf(m_[h], tm);
            float alpha = exp2f(m_[h] - mn);
            float rs = 0.f;
            #pragma unroll
            for (int nt = 0; nt < 16; nt++) {
                float p0 = exp2f(sacc[nt][2 * h] * CSC - mn);
                float p1 = exp2f(sacc[nt][2 * h + 1] * CSC - mn);
                sacc[nt][2 * h] = p0; sacc[nt][2 * h + 1] = p1;
                rs += p0 + p1;
            }
            rs += __shfl_xor_sync(0xffffffffu, rs, 1);
            rs += __shfl_xor_sync(0xffffffffu, rs, 2);
            l_[h] = l_[h] * alpha + rs;
            m_[h] = mn;
            #pragma unroll
            for (int nt = 0; nt < 16; nt++) { oacc[nt][2 * h] *= alpha; oacc[nt][2 * h + 1] *= alpha; }
        }

        #pragma unroll
        for (int kk = 0; kk < 8; kk++) {
            uint32_t pf[4];
            pf[0] = packh2(sacc[2 * kk][0], sacc[2 * kk][1]);
            pf[1] = packh2(sacc[2 * kk][2], sacc[2 * kk][3]);
            pf[2] = packh2(sacc[2 * kk + 1][0], sacc[2 * kk + 1][1]);
            pf[3] = packh2(sacc[2 * kk + 1][2], sacc[2 * kk + 1][3]);
            uint32_t Bv[16][2];
            #pragma unroll
            for (int np = 0; np < 8; np++) {
                int r = np * 16 + ((lane >> 4) << 3) + (lane & 7);
                int q8 = kk * 2 + ((lane >> 3) & 1);
                ldsm4(Bv[2 * np][0], Bv[2 * np][1], Bv[2 * np + 1][0], Bv[2 * np + 1][1],
                      swz256(sV[buf], r, q8));
            }
            #pragma unroll
            for (int nt = 0; nt < 16; nt++) mma16816(oacc[nt], pf, Bv[nt]);
        }

        __syncthreads();
        if (kt + 2 < 16 && t == 0) {
            mbar_expect(mbar + (uint32_t)buf * 8u, 65536u);
            bulk_g2s(sK[buf], Kp + (size_t)(kt + 2) * 128 * 128, 32768u, mbar + (uint32_t)buf * 8u);
            bulk_g2s(sV[buf], Vp + (size_t)(kt + 2) * 16384, 32768u, mbar + (uint32_t)buf * 8u);
        }
    }

    float inv0 = 1.f / l_[0], inv1 = 1.f / l_[1];
    int row0 = qt * 128 + w * 16 + (lane >> 2);
    #pragma unroll
    for (int nt = 0; nt < 16; nt++) {
        int col = head * 128 + nt * 8 + (lane & 3) * 2;
        *(__half2*)(catp + tiled_off(L, row0, col)) =
            __floats2half2_rn(oacc[nt][0] * inv0, oacc[nt][1] * inv0);
        *(__half2*)(catp + tiled_off(L, row0 + 8, col)) =
            __floats2half2_rn(oacc[nt][2] * inv1, oacc[nt][3] * inv1);
    }
}

// ================= conversions =================
__global__ void conv_tile(const float* __restrict__ src, __half* __restrict__ dst,
                          int N, int K, long long n8) {
    long long i = (long long)blockIdx.x * 256 + threadIdx.x;
    if (i >= n8) return;
    int kq = K >> 3;
    int r = (int)(i / kq), q8i = (int)(i - (long long)r * kq);
    int c0 = q8i * 8;
    const float4* s = (const float4*)(src + (size_t)r * K + c0);
    float4 a = s[0], b = s[1];
    __half2 h0 = __floats2half2_rn(a.x, a.y);
    __half2 h1 = __floats2half2_rn(a.z, a.w);
    __half2 h2 = __floats2half2_rn(b.x, b.y);
    __half2 h3 = __floats2half2_rn(b.z, b.w);
    uint4 o;
    o.x = *(uint32_t*)&h0; o.y = *(uint32_t*)&h1;
    o.z = *(uint32_t*)&h2; o.w = *(uint32_t*)&h3;
    *(uint4*)(dst + tiled_off(N, r, c0)) = o;
}

__global__ void upext_k(const float* __restrict__ upq, const float* __restrict__ upk,
                        const float* __restrict__ upv) {
    int i = blockIdx.x * 256 + threadIdx.x;
    int o = i >> 7, j = i & 127;
    int mat = o / HID, colm = o - mat * HID;
    int jj = j - mat * 32;
    float v = 0.f;
    if (j < 96 && jj >= 0 && jj < 32) {
        const float* up = (mat == 0) ? upq : (mat == 1) ? upk : upv;
        v = up[(size_t)colm * 32 + jj];
    }
    g_w12[tiled_off(H1, o, 3072 + j)] = __float2half(v);
}

__global__ void yext_k() {
    int i = blockIdx.x * 256 + threadIdx.x;
    int l = i >> 5, j = i & 31;
    float s0 = 0.f, s1 = 0.f, s2 = 0.f;
    #pragma unroll
    for (int z = 0; z < 4; z++) {
        size_t base = (size_t)z * 3 * L * 32 + (size_t)l * 32 + j;
        s0 += g_y1p[base];
        s1 += g_y1p[base + (size_t)L * 32];
        s2 += g_y1p[base + 2 * (size_t)L * 32];
    }
    g_xmod2[tiled_off(L, l, 3072 + j)]  = __float2half(s0);
    g_xmod2[tiled_off(L, l, 3104 + j)]  = __float2half(s1);
    g_xmod2[tiled_off(L, l, 3136 + j)]  = __float2half(s2);
    g_xmod2[tiled_off(L, l, 3168 + j)]  = __float2half(0.f);
}

// ================= small kernels =================
__global__ __launch_bounds__(256) void mod_gemv(const float* __restrict__ vec,
                                                const float* __restrict__ W,
                                                const float* __restrict__ b) {
    __shared__ float sv[HID];
    int t = threadIdx.x;
    for (int j = t; j < HID; j += 256) {
        float v = vec[j];
        sv[j] = v / (1.f + expf(-v));
    }
    __syncthreads();
    int o = blockIdx.x * 8 + (t >> 5);
    int lane = t & 31;
    const float* w = W + (size_t)o * HID;
    float acc = 0.f;
    for (int k = lane; k < HID; k += 32) acc += sv[k] * w[k];
    #pragma unroll
    for (int s = 16; s; s >>= 1) acc += __shfl_xor_sync(0xffffffffu, acc, s);
    if (lane == 0) g_m[o] = acc + b[o];
}

__global__ __launch_bounds__(256) void ln_mod_k(const float* __restrict__ x) {
    int l = blockIdx.x, t = threadIdx.x;
    const float* xr = x + (size_t)l * HID;
    float s = 0.f, s2 = 0.f;
    for (int j = t; j < HID; j += 256) { float v = xr[j]; s += v; s2 += v * v; }
    __shared__ float sh[16];
    #pragma unroll
    for (int o = 16; o; o >>= 1) {
        s  += __shfl_xor_sync(0xffffffffu, s, o);
        s2 += __shfl_xor_sync(0xffffffffu, s2, o);
    }
    if ((t & 31) == 0) { sh[t >> 5] = s; sh[8 + (t >> 5)] = s2; }
    __syncthreads();
    float ts = 0.f, ts2 = 0.f;
    #pragma unroll
    for (int i = 0; i < 8; i++) { ts += sh[i]; ts2 += sh[8 + i]; }
    float mu = ts * (1.f / HID);
    float var = ts2 * (1.f / HID) - mu * mu;
    float r = rsqrtf(var + 1e-6f);
    for (int u = t; u < HID / 8; u += 256) {
        int j0 = u * 8;
        __half2 hp[4];
        #pragma unroll
        for (int e = 0; e < 4; e++) {
            int j = j0 + 2 * e;
            float v0 = (xr[j] - mu) * r;
            float v1 = (xr[j + 1] - mu) * r;
            hp[e] = __floats2half2_rn((1.f + g_m[HID + j]) * v0 + g_m[j],
                                      (1.f + g_m[HID + j + 1]) * v1 + g_m[j + 1]);
        }
        uint4 o;
        o.x = *(uint32_t*)&hp[0]; o.y = *(uint32_t*)&hp[1];
        o.z = *(uint32_t*)&hp[2]; o.w = *(uint32_t*)&hp[3];
        *(uint4*)(g_xmod2 + tiled_off(L, l, j0)) = o;
    }
}

__global__ __launch_bounds__(256) void lora_down_s(
    const __half* __restrict__ X, const float* __restrict__ D0,
    const float* __restrict__ D1, const float* __restrict__ D2,
    float* __restrict__ Yp, int nc, int kbase, int K,
    long long zs, long long ms, int ldy)
{
    __shared__ float xs[64][65];
    __shared__ float ds[64][32];
    int t = threadIdx.x;
    int m0 = blockIdx.x * 64;
    int mat = blockIdx.y, z = blockIdx.z;
    const float* D = (mat == 0) ? D0 : ((mat == 1) ? D1 : D2);
    float* Y = Yp + (size_t)z * zs + (size_t)mat * ms;
    int tx = t & 31, ty = t >> 5;
    int drow = t >> 3, df4 = t & 7;
    float acc[8] = {};
    int k0b = (kbase + z * nc) * 64;

    for (int c = 0; c < nc; c++) {
        int k0 = k0b + c * 64;
        #pragma unroll
        for (int j = 0; j < 4; j++) {
            int slot = t + j * 256;
            int row = slot >> 4, c4 = (slot & 15) * 4;
            uint2 u = *(const uint2*)(X + tiled_off(L, m0 + row, k0 + c4));
            __half2 ab = *(__half2*)&u.x, cd = *(__half2*)&u.y;
            float2 f0 = __half22float2(ab), f1 = __half22float2(cd);
            xs[c4][row] = f0.x; xs[c4 + 1][row] = f0.y;
            xs[c4 + 2][row] = f1.x; xs[c4 + 3][row] = f1.y;
        }
        #pragma unroll
        for (int j = 0; j < 2; j++) {
            int kk = (df4 + 8 * j) * 4;
            float4 vd = *(const float4*)(D + (size_t)drow * K + k0 + kk);
            ds[kk][drow] = vd.x; ds[kk + 1][drow] = vd.y;
            ds[kk + 2][drow] = vd.z; ds[kk + 3][drow] = vd.w;
        }
        __syncthreads();
        #pragma unroll
        for (int kk = 0; kk < 64; kk++) {
            float dv = ds[kk][tx];
            #pragma unroll
            for (int i = 0; i < 8; i++) acc[i] += xs[kk][ty * 8 + i] * dv;
        }
        __syncthreads();
    }
    #pragma unroll
    for (int i = 0; i < 8; i++)
        Y[(size_t)(m0 + ty * 8 + i) * ldy + tx] = acc[i];
}

__global__ __launch_bounds__(128) void qkv_finalize(
    const float* __restrict__ q_scale, const float* __restrict__ k_scale,
    const float* __restrict__ pe)
{
    __shared__ float sq[128], sk[128], red[8];

    const int head = blockIdx.x, d = threadIdx.x;
    const int l0 = blockIdx.y * 16;
    const int col = head * HD + d;

    const float qsc = q_scale[d], ksc = k_scale[d];
    const float qsc2 = q_scale[d ^ 1], ksc2 = k_scale[d ^ 1];

    for (int li = 0; li < 16; li++) {
        int l = l0 + li;
        size_t hb = (size_t)l * H3;
        float qv = __half2float(g_hh[hb + col]);
        float kv = __half2float(g_hh[hb + HID + col]);
        float vv = __half2float(g_hh[hb + 2 * HID + col]);

        __syncthreads();
        sq[d] = qv; sk[d] = kv;
        float aq = qv * qv, ak = kv * kv;
        #pragma unroll
        for (int o = 16; o; o >>= 1) {
            aq += __shfl_xor_sync(0xffffffffu, aq, o);
            ak += __shfl_xor_sync(0xffffffffu, ak, o);
        }
        if ((d & 31) == 0) { red[d >> 5] = aq; red[4 + (d >> 5)] = ak; }
        __syncthreads();

        float rq = rsqrtf((red[0] + red[1] + red[2] + red[3]) * (1.f / HD) + 1e-6f);
        float rk = rsqrtf((red[4] + red[5] + red[6] + red[7]) * (1.f / HD) + 1e-6f);

        int e = d & ~1, o_ = d | 1;
        float sce = (d & 1) ? qsc2 : qsc;
        float sco = (d & 1) ? qsc : qsc2;
        float kce = (d & 1) ? ksc2 : ksc;
        float kco = (d & 1) ? ksc : ksc2;
        float q0 = sq[e]  * rq * sce;
        float q1 = sq[o_] * rq * sco;
        float k0 = sk[e]  * rk * kce;
        float k1 = sk[o_] * rk * kco;

        const float* p = pe + ((size_t)l * 64 + (d >> 1)) * 4;
        float qo = (d & 1) ? (p[2] * q0 + p[3] * q1) : (p[0] * q0 + p[1] * q1);
        float ko = (d & 1) ? (p[2] * k0 + p[3] * k1) : (p[0] * k0 + p[1] * k1);

        {
            int q8 = d >> 3, sub = d >> 6;
            int sr = l * 2 + sub;
            size_t off = ((size_t)head * L + l) * 128 + (size_t)sub * 64 +
                         (size_t)(((q8 & 7) ^ (sr & 7)) << 3) + (d & 7);
            g_q2[off] = __float2half(qo);
            g_k2[off] = __float2half(ko);
        }
        {
            int kt = l >> 7, lc = l & 127;
            int q8 = lc >> 3;
            int sr = d * 2 + (q8 >> 3);
            size_t off = ((size_t)(head * 16 + kt)) * 16384 + (size_t)sr * 64 +
                         (size_t)(((q8 & 7) ^ (sr & 7)) << 3) + (lc & 7);
            g_v2[off] = __float2half(vv);
        }
    }
}

__global__ __launch_bounds__(256) void final_k(const float* __restrict__ x,
                                               const float* __restrict__ pu,
                                               const float* __restrict__ b2,
                                               float* __restrict__ out)
{
    int l = blockIdx.y;
    int c = blockIdx.x * 256 + threadIdx.x;
    __shared__ float sp[64];
    if (threadIdx.x < 64) {
        float s = 0.f;
        #pragma unroll
        for (int z = 0; z < 8; z++)
            s += g_plp[(size_t)z * L * 64 + (size_t)l * 64 + threadIdx.x];
        sp[threadIdx.x] = s;
    }
    __syncthreads();

    const float4* ur = (const float4*)(pu + (size_t)c * 64);
    float a = 0.f;
    #pragma unroll
    for (int r = 0; r < 16; r++) {
        float4 u = ur[r];
        a += u.x * sp[4 * r] + u.y * sp[4 * r + 1] + u.z * sp[4 * r + 2] + u.w * sp[4 * r + 3];
    }
    size_t idx = (size_t)l * HID + c;
    const size_t LH = (size_t)L * HID;
    float o = g_o[idx] + g_o[idx + LH] + g_o[idx + 2 * LH] + g_o[idx + 3 * LH] + b2[c] + a;
    out[idx] = x[idx] + g_m[2 * HID + c] * o;
}

// ================= launch (R10 schedule) =================
extern "C" void kernel_launch(void* const* d_in, const int* in_sizes, int n_in,
                              void* d_out, int out_size)
{
    const float* x   = (const float*)d_in[0];
    const float* vec = (const float*)d_in[1];
    const float* pe  = (const float*)d_in[2];
    const float* mw  = (const float*)d_in[3];
    const float* mb  = (const float*)d_in[4];
    const float* w1  = (const float*)d_in[5];
    const float* b1  = (const float*)d_in[6];
    const float* w2  = (const float*)d_in[7];
    const float* b2  = (const float*)d_in[8];
    const float* qs  = (const float*)d_in[9];
    const float* ks  = (const float*)d_in[10];
    const float* lqd = (const float*)d_in[11];
    const float* lqu = (const float*)d_in[12];
    const float* lkd = (const float*)d_in[13];
    const float* lku = (const float*)d_in[14];
    const float* lvd = (const float*)d_in[15];
    const float* lvu = (const float*)d_in[16];
    const float* pd  = (const float*)d_in[17];
    const float* pu  = (const float*)d_in[18];
    float* out = (float*)d_out;

    float *y1p, *plp, *ob;
    __half *xmod2, *w12, *w22, *cat2, *q2, *k2, *v2;
    cudaGetSymbolAddress((void**)&y1p,   g_y1p);
    cudaGetSymbolAddress((void**)&plp,   g_plp);
    cudaGetSymbolAddress((void**)&ob,    g_o);
    cudaGetSymbolAddress((void**)&xmod2, g_xmod2);
    cudaGetSymbolAddress((void**)&w12,   g_w12);
    cudaGetSymbolAddress((void**)&w22,   g_w22);
    cudaGetSymbolAddress((void**)&cat2,  g_cat2);
    cudaGetSymbolAddress((void**)&q2,    g_q2);
    cudaGetSymbolAddress((void**)&k2,    g_k2);
    cudaGetSymbolAddress((void**)&v2,    g_v2);

    const int SMG = 4 * 48 * 1024 + 64;   // 196672
    const int SMF = 5 * 32 * 1024 + 64;

    static cudaStream_t s1 = 0, s2 = 0;
    static cudaEvent_t evRoot = 0, evLn = 0, evW1 = 0, evUp = 0, evW2 = 0;
    static cudaEvent_t evY = 0, evMLP = 0, evG2m = 0, evLpm = 0;
    static bool init_done = false;
    if (!init_done) {
        cudaFuncSetAttribute(gemm512<1>, cudaFuncAttributeMaxDynamicSharedMemorySize, SMG);
        cudaFuncSetAttribute(gemm512<0>, cudaFuncAttributeMaxDynamicSharedMemorySize, SMG);
        cudaFuncSetAttribute(flash_k,    cudaFuncAttributeMaxDynamicSharedMemorySize, SMF);
        cudaStreamCreateWithFlags(&s1, cudaStreamNonBlocking);
        cudaStreamCreateWithFlags(&s2, cudaStreamNonBlocking);
        cudaEventCreateWithFlags(&evRoot, cudaEventDisableTiming);
        cudaEventCreateWithFlags(&evLn,   cudaEventDisableTiming);
        cudaEventCreateWithFlags(&evW1,   cudaEventDisableTiming);
        cudaEventCreateWithFlags(&evUp,   cudaEventDisableTiming);
        cudaEventCreateWithFlags(&evW2,   cudaEventDisableTiming);
        cudaEventCreateWithFlags(&evY,    cudaEventDisableTiming);
        cudaEventCreateWithFlags(&evMLP,  cudaEventDisableTiming);
        cudaEventCreateWithFlags(&evG2m,  cudaEventDisableTiming);
        cudaEventCreateWithFlags(&evLpm,  cudaEventDisableTiming);
        init_done = true;
    }

    cudaEventRecord(evRoot, 0);
    cudaStreamWaitEvent(s1, evRoot, 0);
    cudaStreamWaitEvent(s2, evRoot, 0);

    // 0,1: s0 modulation + layernorm
    mod_gemv<<<(3 * HID) / 8, 256>>>(vec, mw, mb);
    ln_mod_k<<<L, 256>>>(x);
    cudaEventRecord(evLn, 0);

    // 2,3: s1 conv w1 then gemm1-MLP (profiling slot 3)
    conv_tile<<<(int)(((size_t)H1 * HID / 8 + 255) / 256), 256, 0, s1>>>(
        w1, w12, H1, HID, (size_t)H1 * HID / 8);
    cudaEventRecord(evW1, s1);
    cudaStreamWaitEvent(s1, evLn, 0);
    gemm512<1><<<dim3(L / 128, 48, 1), 512, SMG, s1>>>(
        xmod2, w12, nullptr, b1, cat2, 48, 0, 36, L, H1, 0, 0LL);
    cudaEventRecord(evMLP, s1);

    // s2: up-ext, then qkv lora downs, then y-ext
    upext_k<<<(H3 * 128) / 256, 256, 0, s2>>>(lqu, lku, lvu);
    cudaEventRecord(evUp, s2);
    cudaStreamWaitEvent(s2, evLn, 0);
    lora_down_s<<<dim3(L / 64, 3, 4), 256, 0, s2>>>(
        xmod2, lqd, lkd, lvd, y1p, 12, 0, HID,
        3LL * L * 32, (long long)L * 32, 32);
    yext_k<<<(L * 32) / 256, 256, 0, s2>>>();
    cudaEventRecord(evY, s2);

    // s1: conv w2
    conv_tile<<<(int)(((size_t)HID * CATD / 8 + 255) / 256), 256, 0, s1>>>(
        w2, w22, HID, CATD, (size_t)HID * CATD / 8);
    cudaEventRecord(evW2, s1);

    // s0: gemm1-QKV (48 x_mod chunks + 2 lora-ext chunks)
    cudaStreamWaitEvent(0, evW1, 0);
    cudaStreamWaitEvent(0, evUp, 0);
    cudaStreamWaitEvent(0, evY, 0);
    gemm512<1><<<dim3(L / 128, 36, 1), 512, SMG>>>(
        xmod2, w12, nullptr, b1, cat2, 50, 0, 0, L, H1, 0, 0LL);

    // s0: finalize + flash
    qkv_finalize<<<dim3(HEADS, L / 16), 128>>>(qs, ks, pe);
    flash_k<<<dim3(L / 128, HEADS), 256, SMF>>>(q2, k2, v2, cat2);

    // s1: gemm2 over MLP K-chunks -> g_o[0..1]
    gemm512<0><<<dim3(L / 128, HID / 256, 2), 512, SMG, s1>>>(
        cat2, w22, ob, nullptr, nullptr, 96, 48, 0, L, HID, HID, (long long)L * HID);
    cudaEventRecord(evG2m, s1);

    // s2: proj lora over MLP K-chunks -> plp[0..5]
    cudaStreamWaitEvent(s2, evMLP, 0);
    lora_down_s<<<dim3(L / 64, 2, 6), 256, 0, s2>>>(
        cat2, pd, pd + (size_t)32 * CATD, nullptr, plp, 32, 48, CATD,
        (long long)L * 64, 32LL, 64);
    cudaEventRecord(evLpm, s2);

    // s0: gemm2 attn chunks -> g_o[2..3], proj lora attn -> plp[6..7]
    cudaStreamWaitEvent(0, evW2, 0);
    gemm512<0><<<dim3(L / 128, HID / 256, 2), 512, SMG>>>(
        cat2, w22, ob + 2 * (size_t)L * HID, nullptr, nullptr, 24, 0, 0, L, HID, HID,
        (long long)L * HID);
    lora_down_s<<<dim3(L / 64, 2, 2), 256>>>(
        cat2, pd, pd + (size_t)32 * CATD, nullptr, plp + 6 * (size_t)L * 64, 24, 0, CATD,
        (long long)L * 64, 32LL, 64);

    // join
    cudaStreamWaitEvent(0, evG2m, 0);
    cudaStreamWaitEvent(0, evLpm, 0);
    final_k<<<dim3(HID / 256, L), 256>>>(x, pu, b2, out);
}

// round 14
// speedup vs baseline: 1.0787x; 1.0069x over previous
#include <cuda_runtime.h>
#include <cuda_fp16.h>
#include <math.h>
#include <stdint.h>

#define L 2048
#define HID 3072
#define HEADS 24
#define HD 128
#define MLPD 12288
#define H1 21504
#define CATD 15360
#define H3 9216   // 3*HID

// ---------------- scratch ----------------
__device__ float g_m[3 * HID];
__device__ float g_y1p[4 * 3 * (size_t)L * 32];
__device__ float g_plp[8 * (size_t)L * 64];
__device__ float g_o[4 * (size_t)L * HID];

__device__ __half g_hh[(size_t)L * H3];
__device__ __half g_xmod2[(size_t)L * 3200];
__device__ __half g_w12[(size_t)H1 * 3200];
__device__ __half g_w22[(size_t)HID * CATD];
__device__ __half g_cat2[(size_t)L * CATD];
__device__ __half g_q2[(size_t)HEADS * L * HD];
__device__ __half g_k2[(size_t)HEADS * L * HD];
__device__ __half g_v2[(size_t)HEADS * HD * L];

// ================= helpers =================
__device__ __forceinline__ uint32_t smem_u32(const void* p) {
    uint32_t a;
    asm("{ .reg .u64 t; cvta.to.shared.u64 t, %1; cvt.u32.u64 %0, t; }" : "=r"(a) : "l"(p));
    return a;
}
__device__ __forceinline__ void mbar_init(uint32_t a, uint32_t cnt) {
    asm volatile("mbarrier.init.shared.b64 [%0], %1;" :: "r"(a), "r"(cnt) : "memory");
}
__device__ __forceinline__ void mbar_expect(uint32_t a, uint32_t bytes) {
    asm volatile("mbarrier.arrive.expect_tx.shared.b64 _, [%0], %1;" :: "r"(a), "r"(bytes) : "memory");
}
__device__ __forceinline__ void mbar_arrive(uint32_t a) {
    asm volatile("mbarrier.arrive.shared.b64 _, [%0];" :: "r"(a) : "memory");
}
__device__ __forceinline__ void mbar_wait(uint32_t a, uint32_t parity) {
    asm volatile(
        "{\n\t.reg .pred P;\n"
        "WL_%=:\n\t"
        "mbarrier.try_wait.parity.acquire.cta.shared::cta.b64 P, [%0], %1, 0x989680;\n\t"
        "@P bra WD_%=;\n\t"
        "bra WL_%=;\n"
        "WD_%=:\n\t}"
        :: "r"(a), "r"(parity) : "memory");
}
__device__ __forceinline__ void bulk_g2s(uint32_t dst, const void* src, uint32_t bytes, uint32_t mbar) {
    asm volatile(
        "cp.async.bulk.shared::cta.global.mbarrier::complete_tx::bytes [%0], [%1], %2, [%3];"
        :: "r"(dst), "l"(src), "r"(bytes), "r"(mbar) : "memory");
}
__device__ __forceinline__ void ldsm4(uint32_t& r0, uint32_t& r1, uint32_t& r2, uint32_t& r3,
                                      uint32_t addr) {
    asm volatile("ldmatrix.sync.aligned.m8n8.x4.shared.b16 {%0,%1,%2,%3}, [%4];"
                 : "=r"(r0), "=r"(r1), "=r"(r2), "=r"(r3) : "r"(addr));
}
__device__ __forceinline__ void mma16816(float* d, const uint32_t* a, const uint32_t* b) {
    asm volatile(
        "mma.sync.aligned.m16n8k16.row.col.f32.f16.f16.f32 "
        "{%0,%1,%2,%3}, {%4,%5,%6,%7}, {%8,%9}, {%0,%1,%2,%3};"
        : "+f"(d[0]), "+f"(d[1]), "+f"(d[2]), "+f"(d[3])
        : "r"(a[0]), "r"(a[1]), "r"(a[2]), "r"(a[3]), "r"(b[0]), "r"(b[1]));
}
__device__ __forceinline__ uint32_t packh2(float a, float b) {
    __half2 h = __floats2half2_rn(a, b);
    return *(uint32_t*)&h;
}
__device__ __forceinline__ float gelu1(float x) {
    return 0.5f * x * (1.f + tanhf(0.7978845608028654f * (x + 0.044715f * x * x * x)));
}
__device__ __forceinline__ uint32_t swz128(uint32_t base, int r, int q) {
    return base + (uint32_t)r * 128u + ((uint32_t)(q ^ (r & 7)) << 4);
}
__device__ __forceinline__ uint32_t swz256(uint32_t base, int r, int q8) {
    int sr = r * 2 + (q8 >> 3);
    int q = q8 & 7;
    return base + (uint32_t)sr * 128u + ((uint32_t)(q ^ (sr & 7)) << 4);
}
__device__ __forceinline__ size_t tiled_off(int M, int r, int c) {
    return ((size_t)(c >> 6) * M + r) * 64 + (size_t)((((c & 63) >> 3) ^ (r & 7)) << 3) + (c & 7);
}

// ================= bulk-fed fp16 NT GEMM (4-stage, rotating producer, unrolled stages) ======
template <int MODE>
__global__ __launch_bounds__(512, 1) void gemm512(
    const __half* __restrict__ At, const __half* __restrict__ Bt,
    float* __restrict__ C, const float* __restrict__ bias,
    __half* __restrict__ catp, int nc, int kbase, int nbase,
    int M, int N, int ldc, long long zsC)
{
    constexpr uint32_t ABYTES = 128u * 128u;
    constexpr uint32_t BBYTES = 256u * 128u;
    constexpr uint32_t STAGE = ABYTES + BBYTES;   // 48KB

    extern __shared__ char smraw[];
    uint32_t s0 = smem_u32(smraw);
    uint32_t mbF = s0 + 4u * STAGE;
    uint32_t mbE = mbF + 32u;

    const int t = threadIdx.x, w = t >> 5, lane = t & 31;
    const int wm = w & 3, wn = w >> 2;
    const int m0 = blockIdx.x * 128, n0 = (nbase + blockIdx.y) * 256;
    const int z = blockIdx.z;
    const int c0 = kbase + z * nc;
    C += (size_t)z * zsC;

    if (t == 0) {
        #pragma unroll
        for (int i = 0; i < 4; i++) {
            mbar_init(mbF + (uint32_t)i * 8u, 1);
            mbar_init(mbE + (uint32_t)i * 8u, 16);
        }
    }
    __syncthreads();

    auto issue = [&](int c, int stg) {
        uint32_t mb = mbF + (uint32_t)stg * 8u;
        uint32_t ab = s0 + (uint32_t)stg * STAGE;
        mbar_expect(mb, ABYTES + BBYTES);
        bulk_g2s(ab, At + ((size_t)(c0 + c) * M + m0) * 64, ABYTES, mb);
        bulk_g2s(ab + ABYTES, Bt + ((size_t)(c0 + c) * N + n0) * 64, BBYTES, mb);
    };

    if (t == 0) { issue(0, 0); issue(1, 1); issue(2, 2); issue(3, 3); }

    // loop-invariant swizzled offsets (relative to stage base)
    uint32_t offA[4][2], offB[4][4];
    #pragma unroll
    for (int s = 0; s < 4; s++) {
        #pragma unroll
        for (int mt = 0; mt < 2; mt++) {
            int r = wm * 32 + mt * 16 + (lane & 15);
            int q = s * 2 + (lane >> 4);
            offA[s][mt] = swz128(0, r, q);
        }
        #pragma unroll
        for (int np = 0; np < 4; np++) {
            int r = wn * 64 + np * 16 + ((lane >> 4) << 3) + (lane & 7);
            int q = s * 2 + ((lane >> 3) & 1);
            offB[s][np] = ABYTES + swz128(0, r, q);
        }
    }

    float acc[2][8][4] = {};

    for (int cb = 0; cb < nc; cb += 4) {
        uint32_t par = (uint32_t)((cb >> 2) & 1);
        #pragma unroll
        for (int i = 0; i < 4; i++) {
            int c = cb + i;
            if (c >= nc) break;
            mbar_wait(mbF + (uint32_t)i * 8u, par);

            uint32_t sb = s0 + (uint32_t)i * STAGE;

            #pragma unroll
            for (int s = 0; s < 4; s++) {
                uint32_t Af[2][4];
                #pragma unroll
                for (int mt = 0; mt < 2; mt++)
                    ldsm4(Af[mt][0], Af[mt][1], Af[mt][2], Af[mt][3], sb + offA[s][mt]);
                uint32_t Bf[8][2];
                #pragma unroll
                for (int np = 0; np < 4; np++)
                    ldsm4(Bf[2 * np][0], Bf[2 * np][1], Bf[2 * np + 1][0], Bf[2 * np + 1][1],
                          sb + offB[s][np]);
                #pragma unroll
                for (int mt = 0; mt < 2; mt++)
                    #pragma unroll
                    for (int nt = 0; nt < 8; nt++)
                        mma16816(acc[mt][nt], Af[mt], Bf[nt]);
            }

            if (lane == 0) {
                mbar_arrive(mbE + (uint32_t)i * 8u);
                if (c + 4 < nc && w == (c & 15)) {
                    mbar_wait(mbE + (uint32_t)i * 8u, par);
                    issue(c + 4, i);
                }
            }
        }
    }

    #pragma unroll
    for (int mt = 0; mt < 2; mt++) {
        int row = m0 + wm * 32 + mt * 16 + (lane >> 2);
        #pragma unroll
        for (int nt = 0; nt < 8; nt++) {
            int col = n0 + wn * 64 + nt * 8 + (lane & 3) * 2;
            if (MODE == 1) {
                float b0 = bias[col], b1v = bias[col + 1];
                float v00 = acc[mt][nt][0] + b0, v01 = acc[mt][nt][1] + b1v;
                float v10 = acc[mt][nt][2] + b0, v11 = acc[mt][nt][3] + b1v;
                if (n0 >= H3) {
                    int cc = col - 6144;
                    *(__half2*)(catp + tiled_off(L, row, cc)) =
                        __floats2half2_rn(gelu1(v00), gelu1(v01));
                    *(__half2*)(catp + tiled_off(L, row + 8, cc)) =
                        __floats2half2_rn(gelu1(v10), gelu1(v11));
                } else {
                    *(__half2*)(g_hh + (size_t)row * H3 + col) = __floats2half2_rn(v00, v01);
                    *(__half2*)(g_hh + (size_t)(row + 8) * H3 + col) = __floats2half2_rn(v10, v11);
                }
            } else {
                *(float2*)(C + (size_t)row * ldc + col) =
                    make_float2(acc[mt][nt][0], acc[mt][nt][1]);
                *(float2*)(C + (size_t)(row + 8) * ldc + col) =
                    make_float2(acc[mt][nt][2], acc[mt][nt][3]);
            }
        }
    }
}

// ================= flash attention =================
__global__ __launch_bounds__(256, 1) void flash_k(
    const __half* __restrict__ Qg, const __half* __restrict__ Kg,
    const __half* __restrict__ Vg, __half* __restrict__ catp)
{
    extern __shared__ char smraw[];
    uint32_t s0 = smem_u32(smraw);
    const uint32_t sQ = s0;
    const uint32_t sK[2] = {s0 + 32768u, s0 + 98304u};
    const uint32_t sV[2] = {s0 + 65536u, s0 + 131072u};
    const uint32_t mbar = s0 + 163840u;

    const int t = threadIdx.x, w = t >> 5, lane = t & 31;
    const int qt = blockIdx.x, head = blockIdx.y;

    const __half* Qp = Qg + ((size_t)head * L + qt * 128) * 128;
    const __half* Kp = Kg + (size_t)head * L * 128;
    const __half* Vp = Vg + (size_t)head * 16 * 16384;

    if (t == 0) { mbar_init(mbar, 1); mbar_init(mbar + 8, 1); }
    __syncthreads();
    if (t == 0) {
        mbar_expect(mbar, 98304u);
        bulk_g2s(sQ, Qp, 32768u, mbar);
        bulk_g2s(sK[0], Kp, 32768u, mbar);
        bulk_g2s(sV[0], Vp, 32768u, mbar);
        mbar_expect(mbar + 8, 65536u);
        bulk_g2s(sK[1], Kp + (size_t)128 * 128, 32768u, mbar + 8);
        bulk_g2s(sV[1], Vp + 16384, 32768u, mbar + 8);
    }

    const float CSC = 0.08838834764831845f * 1.4426950408889634f;
    float m_[2] = {-1e30f, -1e30f}, l_[2] = {0.f, 0.f};
    float oacc[16][4] = {};
    uint32_t ph[2] = {0u, 0u};

    for (int kt = 0; kt < 16; kt++) {
        int buf = kt & 1;
        mbar_wait(mbar + (uint32_t)buf * 8u, ph[buf]);
        ph[buf] ^= 1u;

        float sacc[16][4] = {};
        #pragma unroll
        for (int ks = 0; ks < 8; ks++) {
            uint32_t Af[4];
            {
                int r = w * 16 + (lane & 15);
                int q8 = ks * 2 + (lane >> 4);
                ldsm4(Af[0], Af[1], Af[2], Af[3], swz256(sQ, r, q8));
            }
            uint32_t Bf[16][2];
            #pragma unroll
            for (int np = 0; np < 8; np++) {
                int r = np * 16 + ((lane >> 4) << 3) + (lane & 7);
                int q8 = ks * 2 + ((lane >> 3) & 1);
                ldsm4(Bf[2 * np][0], Bf[2 * np][1], Bf[2 * np + 1][0], Bf[2 * np + 1][1],
                      swz256(sK[buf], r, q8));
            }
            #pragma unroll
            for (int nt = 0; nt < 16; nt++) mma16816(sacc[nt], Af, Bf[nt]);
        }

        #pragma unroll
        for (int h = 0; h < 2; h++) {
            float tm = -1e30f;
            #pragma unroll
            for (int nt = 0; nt < 16; nt++)
                tm = fmaxf(tm, fmaxf(sacc[nt][2 * h], sacc[nt][2 * h + 1]));
            tm *= CSC;
            tm = fmaxf(tm, __shfl_xor_sync(0xffffffffu, tm, 1));
            tm = fmaxf(tm, __shfl_xor_sync(0xffffffffu, tm, 2));
            float mn = fmaxf(m_[h], tm);
            float alpha = exp2f(m_[h] - mn);
            float rs = 0.f;
            #pragma unroll
            for (int nt = 0; nt < 16; nt++) {
                float p0 = exp2f(sacc[nt][2 * h] * CSC - mn);
                float p1 = exp2f(sacc[nt][2 * h + 1] * CSC - mn);
                sacc[nt][2 * h] = p0; sacc[nt][2 * h + 1] = p1;
                rs += p0 + p1;
            }
            rs += __shfl_xor_sync(0xffffffffu, rs, 1);
            rs += __shfl_xor_sync(0xffffffffu, rs, 2);
            l_[h] = l_[h] * alpha + rs;
            m_[h] = mn;
            #pragma unroll
            for (int nt = 0; nt < 16; nt++) { oacc[nt][2 * h] *= alpha; oacc[nt][2 * h + 1] *= alpha; }
        }

        #pragma unroll
        for (int kk = 0; kk < 8; kk++) {
            uint32_t pf[4];
            pf[0] = packh2(sacc[2 * kk][0], sacc[2 * kk][1]);
            pf[1] = packh2(sacc[2 * kk][2], sacc[2 * kk][3]);
            pf[2] = packh2(sacc[2 * kk + 1][0], sacc[2 * kk + 1][1]);
            pf[3] = packh2(sacc[2 * kk + 1][2], sacc[2 * kk + 1][3]);
            uint32_t Bv[16][2];
            #pragma unroll
            for (int np = 0; np < 8; np++) {
                int r = np * 16 + ((lane >> 4) << 3) + (lane & 7);
                int q8 = kk * 2 + ((lane >> 3) & 1);
                ldsm4(Bv[2 * np][0], Bv[2 * np][1], Bv[2 * np + 1][0], Bv[2 * np + 1][1],
                      swz256(sV[buf], r, q8));
            }
            #pragma unroll
            for (int nt = 0; nt < 16; nt++) mma16816(oacc[nt], pf, Bv[nt]);
        }

        __syncthreads();
        if (kt + 2 < 16 && t == 0) {
            mbar_expect(mbar + (uint32_t)buf * 8u, 65536u);
            bulk_g2s(sK[buf], Kp + (size_t)(kt + 2) * 128 * 128, 32768u, mbar + (uint32_t)buf * 8u);
            bulk_g2s(sV[buf], Vp + (size_t)(kt + 2) * 16384, 32768u, mbar + (uint32_t)buf * 8u);
        }
    }

    float inv0 = 1.f / l_[0], inv1 = 1.f / l_[1];
    int row0 = qt * 128 + w * 16 + (lane >> 2);
    #pragma unroll
    for (int nt = 0; nt < 16; nt++) {
        int col = head * 128 + nt * 8 + (lane & 3) * 2;
        *(__half2*)(catp + tiled_off(L, row0, col)) =
            __floats2half2_rn(oacc[nt][0] * inv0, oacc[nt][1] * inv0);
        *(__half2*)(catp + tiled_off(L, row0 + 8, col)) =
            __floats2half2_rn(oacc[nt][2] * inv1, oacc[nt][3] * inv1);
    }
}

// ================= conversions =================
__global__ void conv_tile(const float* __restrict__ src, __half* __restrict__ dst,
                          int N, int K, long long n8) {
    long long i = (long long)blockIdx.x * 256 + threadIdx.x;
    if (i >= n8) return;
    int kq = K >> 3;
    int r = (int)(i / kq), q8i = (int)(i - (long long)r * kq);
    int c0 = q8i * 8;
    const float4* s = (const float4*)(src + (size_t)r * K + c0);
    float4 a = s[0], b = s[1];
    __half2 h0 = __floats2half2_rn(a.x, a.y);
    __half2 h1 = __floats2half2_rn(a.z, a.w);
    __half2 h2 = __floats2half2_rn(b.x, b.y);
    __half2 h3 = __floats2half2_rn(b.z, b.w);
    uint4 o;
    o.x = *(uint32_t*)&h0; o.y = *(uint32_t*)&h1;
    o.z = *(uint32_t*)&h2; o.w = *(uint32_t*)&h3;
    *(uint4*)(dst + tiled_off(N, r, c0)) = o;
}

__global__ void upext_k(const float* __restrict__ upq, const float* __restrict__ upk,
                        const float* __restrict__ upv) {
    int i = blockIdx.x * 256 + threadIdx.x;
    int o = i >> 7, j = i & 127;
    int mat = o / HID, colm = o - mat * HID;
    int jj = j - mat * 32;
    float v = 0.f;
    if (j < 96 && jj >= 0 && jj < 32) {
        const float* up = (mat == 0) ? upq : (mat == 1) ? upk : upv;
        v = up[(size_t)colm * 32 + jj];
    }
    g_w12[tiled_off(H1, o, 3072 + j)] = __float2half(v);
}

__global__ void yext_k() {
    int i = blockIdx.x * 256 + threadIdx.x;
    int l = i >> 5, j = i & 31;
    float s0 = 0.f, s1 = 0.f, s2 = 0.f;
    #pragma unroll
    for (int z = 0; z < 4; z++) {
        size_t base = (size_t)z * 3 * L * 32 + (size_t)l * 32 + j;
        s0 += g_y1p[base];
        s1 += g_y1p[base + (size_t)L * 32];
        s2 += g_y1p[base + 2 * (size_t)L * 32];
    }
    g_xmod2[tiled_off(L, l, 3072 + j)]  = __float2half(s0);
    g_xmod2[tiled_off(L, l, 3104 + j)]  = __float2half(s1);
    g_xmod2[tiled_off(L, l, 3136 + j)]  = __float2half(s2);
    g_xmod2[tiled_off(L, l, 3168 + j)]  = __float2half(0.f);
}

// ================= small kernels =================
__global__ __launch_bounds__(256) void mod_gemv(const float* __restrict__ vec,
                                                const float* __restrict__ W,
                                                const float* __restrict__ b) {
    __shared__ float sv[HID];
    int t = threadIdx.x;
    for (int j = t; j < HID; j += 256) {
        float v = vec[j];
        sv[j] = v / (1.f + expf(-v));
    }
    __syncthreads();
    int o = blockIdx.x * 8 + (t >> 5);
    int lane = t & 31;
    const float* w = W + (size_t)o * HID;
    float acc = 0.f;
    for (int k = lane; k < HID; k += 32) acc += sv[k] * w[k];
    #pragma unroll
    for (int s = 16; s; s >>= 1) acc += __shfl_xor_sync(0xffffffffu, acc, s);
    if (lane == 0) g_m[o] = acc + b[o];
}

__global__ __launch_bounds__(256) void ln_mod_k(const float* __restrict__ x) {
    int l = blockIdx.x, t = threadIdx.x;
    const float* xr = x + (size_t)l * HID;
    float s = 0.f, s2 = 0.f;
    for (int j = t; j < HID; j += 256) { float v = xr[j]; s += v; s2 += v * v; }
    __shared__ float sh[16];
    #pragma unroll
    for (int o = 16; o; o >>= 1) {
        s  += __shfl_xor_sync(0xffffffffu, s, o);
        s2 += __shfl_xor_sync(0xffffffffu, s2, o);
    }
    if ((t & 31) == 0) { sh[t >> 5] = s; sh[8 + (t >> 5)] = s2; }
    __syncthreads();
    float ts = 0.f, ts2 = 0.f;
    #pragma unroll
    for (int i = 0; i < 8; i++) { ts += sh[i]; ts2 += sh[8 + i]; }
    float mu = ts * (1.f / HID);
    float var = ts2 * (1.f / HID) - mu * mu;
    float r = rsqrtf(var + 1e-6f);
    for (int u = t; u < HID / 8; u += 256) {
        int j0 = u * 8;
        __half2 hp[4];
        #pragma unroll
        for (int e = 0; e < 4; e++) {
            int j = j0 + 2 * e;
            float v0 = (xr[j] - mu) * r;
            float v1 = (xr[j + 1] - mu) * r;
            hp[e] = __floats2half2_rn((1.f + g_m[HID + j]) * v0 + g_m[j],
                                      (1.f + g_m[HID + j + 1]) * v1 + g_m[j + 1]);
        }
        uint4 o;
        o.x = *(uint32_t*)&hp[0]; o.y = *(uint32_t*)&hp[1];
        o.z = *(uint32_t*)&hp[2]; o.w = *(uint32_t*)&hp[3];
        *(uint4*)(g_xmod2 + tiled_off(L, l, j0)) = o;
    }
}

__global__ __launch_bounds__(256) void lora_down_s(
    const __half* __restrict__ X, const float* __restrict__ D0,
    const float* __restrict__ D1, const float* __restrict__ D2,
    float* __restrict__ Yp, int nc, int kbase, int K,
    long long zs, long long ms, int ldy)
{
    __shared__ float xs[64][65];
    __shared__ float ds[64][32];
    int t = threadIdx.x;
    int m0 = blockIdx.x * 64;
    int mat = blockIdx.y, z = blockIdx.z;
    const float* D = (mat == 0) ? D0 : ((mat == 1) ? D1 : D2);
    float* Y = Yp + (size_t)z * zs + (size_t)mat * ms;
    int tx = t & 31, ty = t >> 5;
    int drow = t >> 3, df4 = t & 7;
    float acc[8] = {};
    int k0b = (kbase + z * nc) * 64;

    for (int c = 0; c < nc; c++) {
        int k0 = k0b + c * 64;
        #pragma unroll
        for (int j = 0; j < 4; j++) {
            int slot = t + j * 256;
            int row = slot >> 4, c4 = (slot & 15) * 4;
            uint2 u = *(const uint2*)(X + tiled_off(L, m0 + row, k0 + c4));
            __half2 ab = *(__half2*)&u.x, cd = *(__half2*)&u.y;
            float2 f0 = __half22float2(ab), f1 = __half22float2(cd);
            xs[c4][row] = f0.x; xs[c4 + 1][row] = f0.y;
            xs[c4 + 2][row] = f1.x; xs[c4 + 3][row] = f1.y;
        }
        #pragma unroll
        for (int j = 0; j < 2; j++) {
            int kk = (df4 + 8 * j) * 4;
            float4 vd = *(const float4*)(D + (size_t)drow * K + k0 + kk);
            ds[kk][drow] = vd.x; ds[kk + 1][drow] = vd.y;
            ds[kk + 2][drow] = vd.z; ds[kk + 3][drow] = vd.w;
        }
        __syncthreads();
        #pragma unroll
        for (int kk = 0; kk < 64; kk++) {
            float dv = ds[kk][tx];
            #pragma unroll
            for (int i = 0; i < 8; i++) acc[i] += xs[kk][ty * 8 + i] * dv;
        }
        __syncthreads();
    }
    #pragma unroll
    for (int i = 0; i < 8; i++)
        Y[(size_t)(m0 + ty * 8 + i) * ldy + tx] = acc[i];
}

__global__ __launch_bounds__(128) void qkv_finalize(
    const float* __restrict__ q_scale, const float* __restrict__ k_scale,
    const float* __restrict__ pe)
{
    __shared__ float sq[128], sk[128], red[8];

    const int head = blockIdx.x, d = threadIdx.x;
    const int l0 = blockIdx.y * 16;
    const int col = head * HD + d;

    const float qsc = q_scale[d], ksc = k_scale[d];
    const float qsc2 = q_scale[d ^ 1], ksc2 = k_scale[d ^ 1];

    for (int li = 0; li < 16; li++) {
        int l = l0 + li;
        size_t hb = (size_t)l * H3;
        float qv = __half2float(g_hh[hb + col]);
        float kv = __half2float(g_hh[hb + HID + col]);
        float vv = __half2float(g_hh[hb + 2 * HID + col]);

        __syncthreads();
        sq[d] = qv; sk[d] = kv;
        float aq = qv * qv, ak = kv * kv;
        #pragma unroll
        for (int o = 16; o; o >>= 1) {
            aq += __shfl_xor_sync(0xffffffffu, aq, o);
            ak += __shfl_xor_sync(0xffffffffu, ak, o);
        }
        if ((d & 31) == 0) { red[d >> 5] = aq; red[4 + (d >> 5)] = ak; }
        __syncthreads();

        float rq = rsqrtf((red[0] + red[1] + red[2] + red[3]) * (1.f / HD) + 1e-6f);
        float rk = rsqrtf((red[4] + red[5] + red[6] + red[7]) * (1.f / HD) + 1e-6f);

        int e = d & ~1, o_ = d | 1;
        float sce = (d & 1) ? qsc2 : qsc;
        float sco = (d & 1) ? qsc : qsc2;
        float kce = (d & 1) ? ksc2 : ksc;
        float kco = (d & 1) ? ksc : ksc2;
        float q0 = sq[e]  * rq * sce;
        float q1 = sq[o_] * rq * sco;
        float k0 = sk[e]  * rk * kce;
        float k1 = sk[o_] * rk * kco;

        const float* p = pe + ((size_t)l * 64 + (d >> 1)) * 4;
        float qo = (d & 1) ? (p[2] * q0 + p[3] * q1) : (p[0] * q0 + p[1] * q1);
        float ko = (d & 1) ? (p[2] * k0 + p[3] * k1) : (p[0] * k0 + p[1] * k1);

        {
            int q8 = d >> 3, sub = d >> 6;
            int sr = l * 2 + sub;
            size_t off = ((size_t)head * L + l) * 128 + (size_t)sub * 64 +
                         (size_t)(((q8 & 7) ^ (sr & 7)) << 3) + (d & 7);
            g_q2[off] = __float2half(qo);
            g_k2[off] = __float2half(ko);
        }
        {
            int kt = l >> 7, lc = l & 127;
            int q8 = lc >> 3;
            int sr = d * 2 + (q8 >> 3);
            size_t off = ((size_t)(head * 16 + kt)) * 16384 + (size_t)sr * 64 +
                         (size_t)(((q8 & 7) ^ (sr & 7)) << 3) + (lc & 7);
            g_v2[off] = __float2half(vv);
        }
    }
}

__global__ __launch_bounds__(256) void final_k(const float* __restrict__ x,
                                               const float* __restrict__ pu,
                                               const float* __restrict__ b2,
                                               float* __restrict__ out)
{
    int l = blockIdx.y;
    int c = blockIdx.x * 256 + threadIdx.x;
    __shared__ float sp[64];
    if (threadIdx.x < 64) {
        float s = 0.f;
        #pragma unroll
        for (int z = 0; z < 8; z++)
            s += g_plp[(size_t)z * L * 64 + (size_t)l * 64 + threadIdx.x];
        sp[threadIdx.x] = s;
    }
    __syncthreads();

    const float4* ur = (const float4*)(pu + (size_t)c * 64);
    float a = 0.f;
    #pragma unroll
    for (int r = 0; r < 16; r++) {
        float4 u = ur[r];
        a += u.x * sp[4 * r] + u.y * sp[4 * r + 1] + u.z * sp[4 * r + 2] + u.w * sp[4 * r + 3];
    }
    size_t idx = (size_t)l * HID + c;
    const size_t LH = (size_t)L * HID;
    float o = g_o[idx] + g_o[idx + LH] + g_o[idx + 2 * LH] + g_o[idx + 3 * LH] + b2[c] + a;
    out[idx] = x[idx] + g_m[2 * HID + c] * o;
}

// ================= launch (R10 schedule) =================
extern "C" void kernel_launch(void* const* d_in, const int* in_sizes, int n_in,
                              void* d_out, int out_size)
{
    const float* x   = (const float*)d_in[0];
    const float* vec = (const float*)d_in[1];
    const float* pe  = (const float*)d_in[2];
    const float* mw  = (const float*)d_in[3];
    const float* mb  = (const float*)d_in[4];
    const float* w1  = (const float*)d_in[5];
    const float* b1  = (const float*)d_in[6];
    const float* w2  = (const float*)d_in[7];
    const float* b2  = (const float*)d_in[8];
    const float* qs  = (const float*)d_in[9];
    const float* ks  = (const float*)d_in[10];
    const float* lqd = (const float*)d_in[11];
    const float* lqu = (const float*)d_in[12];
    const float* lkd = (const float*)d_in[13];
    const float* lku = (const float*)d_in[14];
    const float* lvd = (const float*)d_in[15];
    const float* lvu = (const float*)d_in[16];
    const float* pd  = (const float*)d_in[17];
    const float* pu  = (const float*)d_in[18];
    float* out = (float*)d_out;

    float *y1p, *plp, *ob;
    __half *xmod2, *w12, *w22, *cat2, *q2, *k2, *v2;
    cudaGetSymbolAddress((void**)&y1p,   g_y1p);
    cudaGetSymbolAddress((void**)&plp,   g_plp);
    cudaGetSymbolAddress((void**)&ob,    g_o);
    cudaGetSymbolAddress((void**)&xmod2, g_xmod2);
    cudaGetSymbolAddress((void**)&w12,   g_w12);
    cudaGetSymbolAddress((void**)&w22,   g_w22);
    cudaGetSymbolAddress((void**)&cat2,  g_cat2);
    cudaGetSymbolAddress((void**)&q2,    g_q2);
    cudaGetSymbolAddress((void**)&k2,    g_k2);
    cudaGetSymbolAddress((void**)&v2,    g_v2);

    const int SMG = 4 * 48 * 1024 + 64;
    const int SMF = 5 * 32 * 1024 + 64;

    static cudaStream_t s1 = 0, s2 = 0;
    static cudaEvent_t evRoot = 0, evLn = 0, evW1 = 0, evUp = 0, evW2 = 0;
    static cudaEvent_t evY = 0, evMLP = 0, evG2m = 0, evLpm = 0;
    static bool init_done = false;
    if (!init_done) {
        cudaFuncSetAttribute(gemm512<1>, cudaFuncAttributeMaxDynamicSharedMemorySize, SMG);
        cudaFuncSetAttribute(gemm512<0>, cudaFuncAttributeMaxDynamicSharedMemorySize, SMG);
        cudaFuncSetAttribute(flash_k,    cudaFuncAttributeMaxDynamicSharedMemorySize, SMF);
        cudaStreamCreateWithFlags(&s1, cudaStreamNonBlocking);
        cudaStreamCreateWithFlags(&s2, cudaStreamNonBlocking);
        cudaEventCreateWithFlags(&evRoot, cudaEventDisableTiming);
        cudaEventCreateWithFlags(&evLn,   cudaEventDisableTiming);
        cudaEventCreateWithFlags(&evW1,   cudaEventDisableTiming);
        cudaEventCreateWithFlags(&evUp,   cudaEventDisableTiming);
        cudaEventCreateWithFlags(&evW2,   cudaEventDisableTiming);
        cudaEventCreateWithFlags(&evY,    cudaEventDisableTiming);
        cudaEventCreateWithFlags(&evMLP,  cudaEventDisableTiming);
        cudaEventCreateWithFlags(&evG2m,  cudaEventDisableTiming);
        cudaEventCreateWithFlags(&evLpm,  cudaEventDisableTiming);
        init_done = true;
    }

    cudaEventRecord(evRoot, 0);
    cudaStreamWaitEvent(s1, evRoot, 0);
    cudaStreamWaitEvent(s2, evRoot, 0);

    // 0,1: s0 modulation + layernorm
    mod_gemv<<<(3 * HID) / 8, 256>>>(vec, mw, mb);
    ln_mod_k<<<L, 256>>>(x);
    cudaEventRecord(evLn, 0);

    // 2,3: s1 conv w1 then gemm1-MLP (profiling slot 3)
    conv_tile<<<(int)(((size_t)H1 * HID / 8 + 255) / 256), 256, 0, s1>>>(
        w1, w12, H1, HID, (size_t)H1 * HID / 8);
    cudaEventRecord(evW1, s1);
    cudaStreamWaitEvent(s1, evLn, 0);
    gemm512<1><<<dim3(L / 128, 48, 1), 512, SMG, s1>>>(
        xmod2, w12, nullptr, b1, cat2, 48, 0, 36, L, H1, 0, 0LL);
    cudaEventRecord(evMLP, s1);

    // s2: up-ext, then qkv lora downs, then y-ext
    upext_k<<<(H3 * 128) / 256, 256, 0, s2>>>(lqu, lku, lvu);
    cudaEventRecord(evUp, s2);
    cudaStreamWaitEvent(s2, evLn, 0);
    lora_down_s<<<dim3(L / 64, 3, 4), 256, 0, s2>>>(
        xmod2, lqd, lkd, lvd, y1p, 12, 0, HID,
        3LL * L * 32, (long long)L * 32, 32);
    yext_k<<<(L * 32) / 256, 256, 0, s2>>>();
    cudaEventRecord(evY, s2);

    // s1: conv w2
    conv_tile<<<(int)(((size_t)HID * CATD / 8 + 255) / 256), 256, 0, s1>>>(
        w2, w22, HID, CATD, (size_t)HID * CATD / 8);
    cudaEventRecord(evW2, s1);

    // s0: gemm1-QKV (48 x_mod chunks + 2 lora-ext chunks)
    cudaStreamWaitEvent(0, evW1, 0);
    cudaStreamWaitEvent(0, evUp, 0);
    cudaStreamWaitEvent(0, evY, 0);
    gemm512<1><<<dim3(L / 128, 36, 1), 512, SMG>>>(
        xmod2, w12, nullptr, b1, cat2, 50, 0, 0, L, H1, 0, 0LL);

    // s0: finalize + flash
    qkv_finalize<<<dim3(HEADS, L / 16), 128>>>(qs, ks, pe);
    flash_k<<<dim3(L / 128, HEADS), 256, SMF>>>(q2, k2, v2, cat2);

    // s1: gemm2 over MLP K-chunks -> g_o[0..1]
    gemm512<0><<<dim3(L / 128, HID / 256, 2), 512, SMG, s1>>>(
        cat2, w22, ob, nullptr, nullptr, 96, 48, 0, L, HID, HID, (long long)L * HID);
    cudaEventRecord(evG2m, s1);

    // s2: proj lora over MLP K-chunks -> plp[0..5]
    cudaStreamWaitEvent(s2, evMLP, 0);
    lora_down_s<<<dim3(L / 64, 2, 6), 256, 0, s2>>>(
        cat2, pd, pd + (size_t)32 * CATD, nullptr, plp, 32, 48, CATD,
        (long long)L * 64, 32LL, 64);
    cudaEventRecord(evLpm, s2);

    // s0: gemm2 attn chunks -> g_o[2..3], proj lora attn -> plp[6..7]
    cudaStreamWaitEvent(0, evW2, 0);
    gemm512<0><<<dim3(L / 128, HID / 256, 2), 512, SMG>>>(
        cat2, w22, ob + 2 * (size_t)L * HID, nullptr, nullptr, 24, 0, 0, L, HID, HID,
        (long long)L * HID);
    lora_down_s<<<dim3(L / 64, 2, 2), 256>>>(
        cat2, pd, pd + (size_t)32 * CATD, nullptr, plp + 6 * (size_t)L * 64, 24, 0, CATD,
        (long long)L * 64, 32LL, 64);

    // join
    cudaStreamWaitEvent(0, evG2m, 0);
    cudaStreamWaitEvent(0, evLpm, 0);
    final_k<<<dim3(HID / 256, L), 256>>>(x, pu, b2, out);
}

// round 15
// speedup vs baseline: 1.0862x; 1.0069x over previous
#include <cuda_runtime.h>
#include <cuda_fp16.h>
#include <math.h>
#include <stdint.h>

#define L 2048
#define HID 3072
#define HEADS 24
#define HD 128
#define MLPD 12288
#define H1 21504
#define CATD 15360
#define H3 9216   // 3*HID

// ---------------- scratch ----------------
__device__ float g_m[3 * HID];
__device__ float g_y1p[4 * 3 * (size_t)L * 32];
__device__ float g_plp[8 * (size_t)L * 64];
__device__ float g_o[4 * (size_t)L * HID];

__device__ __half g_hh[(size_t)L * H3];
__device__ __half g_xmod2[(size_t)L * 3200];
__device__ __half g_w12[(size_t)H1 * 3200];
__device__ __half g_w22[(size_t)HID * CATD];
__device__ __half g_cat2[(size_t)L * CATD];
__device__ __half g_q2[(size_t)HEADS * L * HD];
__device__ __half g_k2[(size_t)HEADS * L * HD];
__device__ __half g_v2[(size_t)HEADS * HD * L];

// ================= helpers =================
__device__ __forceinline__ uint32_t smem_u32(const void* p) {
    uint32_t a;
    asm("{ .reg .u64 t; cvta.to.shared.u64 t, %1; cvt.u32.u64 %0, t; }" : "=r"(a) : "l"(p));
    return a;
}
__device__ __forceinline__ void mbar_init(uint32_t a, uint32_t cnt) {
    asm volatile("mbarrier.init.shared.b64 [%0], %1;" :: "r"(a), "r"(cnt) : "memory");
}
__device__ __forceinline__ void mbar_expect(uint32_t a, uint32_t bytes) {
    asm volatile("mbarrier.arrive.expect_tx.shared.b64 _, [%0], %1;" :: "r"(a), "r"(bytes) : "memory");
}
__device__ __forceinline__ void mbar_arrive(uint32_t a) {
    asm volatile("mbarrier.arrive.shared.b64 _, [%0];" :: "r"(a) : "memory");
}
__device__ __forceinline__ void mbar_wait(uint32_t a, uint32_t parity) {
    asm volatile(
        "{\n\t.reg .pred P;\n"
        "WL_%=:\n\t"
        "mbarrier.try_wait.parity.acquire.cta.shared::cta.b64 P, [%0], %1, 0x989680;\n\t"
        "@P bra WD_%=;\n\t"
        "bra WL_%=;\n"
        "WD_%=:\n\t}"
        :: "r"(a), "r"(parity) : "memory");
}
__device__ __forceinline__ void bulk_g2s(uint32_t dst, const void* src, uint32_t bytes, uint32_t mbar) {
    asm volatile(
        "cp.async.bulk.shared::cta.global.mbarrier::complete_tx::bytes [%0], [%1], %2, [%3];"
        :: "r"(dst), "l"(src), "r"(bytes), "r"(mbar) : "memory");
}
__device__ __forceinline__ void ldsm4(uint32_t& r0, uint32_t& r1, uint32_t& r2, uint32_t& r3,
                                      uint32_t addr) {
    asm volatile("ldmatrix.sync.aligned.m8n8.x4.shared.b16 {%0,%1,%2,%3}, [%4];"
                 : "=r"(r0), "=r"(r1), "=r"(r2), "=r"(r3) : "r"(addr));
}
__device__ __forceinline__ void mma16816(float* d, const uint32_t* a, const uint32_t* b) {
    asm volatile(
        "mma.sync.aligned.m16n8k16.row.col.f32.f16.f16.f32 "
        "{%0,%1,%2,%3}, {%4,%5,%6,%7}, {%8,%9}, {%0,%1,%2,%3};"
        : "+f"(d[0]), "+f"(d[1]), "+f"(d[2]), "+f"(d[3])
        : "r"(a[0]), "r"(a[1]), "r"(a[2]), "r"(a[3]), "r"(b[0]), "r"(b[1]));
}
__device__ __forceinline__ uint32_t packh2(float a, float b) {
    __half2 h = __floats2half2_rn(a, b);
    return *(uint32_t*)&h;
}
__device__ __forceinline__ float gelu1(float x) {
    float u = 0.7978845608028654f * (x + 0.044715f * x * x * x);
    float e = __expf(2.f * u);
    return x * e / (e + 1.f);    // 0.5x(1+tanh(u)) = x*e^{2u}/(e^{2u}+1)
}
__device__ __forceinline__ uint32_t swz128(uint32_t base, int r, int q) {
    return base + (uint32_t)r * 128u + ((uint32_t)(q ^ (r & 7)) << 4);
}
__device__ __forceinline__ uint32_t swz256(uint32_t base, int r, int q8) {
    int sr = r * 2 + (q8 >> 3);
    int q = q8 & 7;
    return base + (uint32_t)sr * 128u + ((uint32_t)(q ^ (sr & 7)) << 4);
}
__device__ __forceinline__ size_t tiled_off(int M, int r, int c) {
    return ((size_t)(c >> 6) * M + r) * 64 + (size_t)((((c & 63) >> 3) ^ (r & 7)) << 3) + (c & 7);
}

// ================= bulk-fed fp16 NT GEMM (4-stage, rotating producer, unrolled stages) ======
template <int MODE>
__global__ __launch_bounds__(512, 1) void gemm512(
    const __half* __restrict__ At, const __half* __restrict__ Bt,
    float* __restrict__ C, const float* __restrict__ bias,
    __half* __restrict__ catp, int nc, int kbase, int nbase,
    int M, int N, int ldc, long long zsC)
{
    constexpr uint32_t ABYTES = 128u * 128u;
    constexpr uint32_t BBYTES = 256u * 128u;
    constexpr uint32_t STAGE = ABYTES + BBYTES;   // 48KB

    extern __shared__ char smraw[];
    uint32_t s0 = smem_u32(smraw);
    uint32_t mbF = s0 + 4u * STAGE;
    uint32_t mbE = mbF + 32u;

    const int t = threadIdx.x, w = t >> 5, lane = t & 31;
    const int wm = w & 3, wn = w >> 2;
    const int m0 = blockIdx.x * 128, n0 = (nbase + blockIdx.y) * 256;
    const int z = blockIdx.z;
    const int c0 = kbase + z * nc;
    C += (size_t)z * zsC;

    if (t == 0) {
        #pragma unroll
        for (int i = 0; i < 4; i++) {
            mbar_init(mbF + (uint32_t)i * 8u, 1);
            mbar_init(mbE + (uint32_t)i * 8u, 16);
        }
    }
    __syncthreads();

    auto issue = [&](int c, int stg) {
        uint32_t mb = mbF + (uint32_t)stg * 8u;
        uint32_t ab = s0 + (uint32_t)stg * STAGE;
        mbar_expect(mb, ABYTES + BBYTES);
        bulk_g2s(ab, At + ((size_t)(c0 + c) * M + m0) * 64, ABYTES, mb);
        bulk_g2s(ab + ABYTES, Bt + ((size_t)(c0 + c) * N + n0) * 64, BBYTES, mb);
    };

    if (t == 0) { issue(0, 0); issue(1, 1); issue(2, 2); issue(3, 3); }

    uint32_t offA[4][2], offB[4][4];
    #pragma unroll
    for (int s = 0; s < 4; s++) {
        #pragma unroll
        for (int mt = 0; mt < 2; mt++) {
            int r = wm * 32 + mt * 16 + (lane & 15);
            int q = s * 2 + (lane >> 4);
            offA[s][mt] = swz128(0, r, q);
        }
        #pragma unroll
        for (int np = 0; np < 4; np++) {
            int r = wn * 64 + np * 16 + ((lane >> 4) << 3) + (lane & 7);
            int q = s * 2 + ((lane >> 3) & 1);
            offB[s][np] = ABYTES + swz128(0, r, q);
        }
    }

    float acc[2][8][4] = {};

    for (int cb = 0; cb < nc; cb += 4) {
        uint32_t par = (uint32_t)((cb >> 2) & 1);
        #pragma unroll
        for (int i = 0; i < 4; i++) {
            int c = cb + i;
            if (c >= nc) break;
            mbar_wait(mbF + (uint32_t)i * 8u, par);

            uint32_t sb = s0 + (uint32_t)i * STAGE;

            #pragma unroll
            for (int s = 0; s < 4; s++) {
                uint32_t Af[2][4];
                #pragma unroll
                for (int mt = 0; mt < 2; mt++)
                    ldsm4(Af[mt][0], Af[mt][1], Af[mt][2], Af[mt][3], sb + offA[s][mt]);
                uint32_t Bf[8][2];
                #pragma unroll
                for (int np = 0; np < 4; np++)
                    ldsm4(Bf[2 * np][0], Bf[2 * np][1], Bf[2 * np + 1][0], Bf[2 * np + 1][1],
                          sb + offB[s][np]);
                #pragma unroll
                for (int mt = 0; mt < 2; mt++)
                    #pragma unroll
                    for (int nt = 0; nt < 8; nt++)
                        mma16816(acc[mt][nt], Af[mt], Bf[nt]);
            }

            if (lane == 0) {
                mbar_arrive(mbE + (uint32_t)i * 8u);
                if (c + 4 < nc && w == (c & 15)) {
                    mbar_wait(mbE + (uint32_t)i * 8u, par);
                    issue(c + 4, i);
                }
            }
        }
    }

    #pragma unroll
    for (int mt = 0; mt < 2; mt++) {
        int row = m0 + wm * 32 + mt * 16 + (lane >> 2);
        #pragma unroll
        for (int nt = 0; nt < 8; nt++) {
            int col = n0 + wn * 64 + nt * 8 + (lane & 3) * 2;
            if (MODE == 1) {
                float b0 = bias[col], b1v = bias[col + 1];
                float v00 = acc[mt][nt][0] + b0, v01 = acc[mt][nt][1] + b1v;
                float v10 = acc[mt][nt][2] + b0, v11 = acc[mt][nt][3] + b1v;
                if (n0 >= H3) {
                    int cc = col - 6144;
                    *(__half2*)(catp + tiled_off(L, row, cc)) =
                        __floats2half2_rn(gelu1(v00), gelu1(v01));
                    *(__half2*)(catp + tiled_off(L, row + 8, cc)) =
                        __floats2half2_rn(gelu1(v10), gelu1(v11));
                } else {
                    *(__half2*)(g_hh + (size_t)row * H3 + col) = __floats2half2_rn(v00, v01);
                    *(__half2*)(g_hh + (size_t)(row + 8) * H3 + col) = __floats2half2_rn(v10, v11);
                }
            } else {
                *(float2*)(C + (size_t)row * ldc + col) =
                    make_float2(acc[mt][nt][0], acc[mt][nt][1]);
                *(float2*)(C + (size_t)(row + 8) * ldc + col) =
                    make_float2(acc[mt][nt][2], acc[mt][nt][3]);
            }
        }
    }
}

// ================= flash attention (warp-async prefetch) =================
// full[2] at mbar+0/8 (tx); empty[2] at mbar+16/24 (count=8).
// Producer for kt+2 is warp (kt&7); parity per buf = (kt>>1)&1.
__global__ __launch_bounds__(256, 1) void flash_k(
    const __half* __restrict__ Qg, const __half* __restrict__ Kg,
    const __half* __restrict__ Vg, __half* __restrict__ catp)
{
    extern __shared__ char smraw[];
    uint32_t s0 = smem_u32(smraw);
    const uint32_t sQ = s0;
    const uint32_t sK[2] = {s0 + 32768u, s0 + 98304u};
    const uint32_t sV[2] = {s0 + 65536u, s0 + 131072u};
    const uint32_t mbar = s0 + 163840u;

    const int t = threadIdx.x, w = t >> 5, lane = t & 31;
    const int qt = blockIdx.x, head = blockIdx.y;

    const __half* Qp = Qg + ((size_t)head * L + qt * 128) * 128;
    const __half* Kp = Kg + (size_t)head * L * 128;
    const __half* Vp = Vg + (size_t)head * 16 * 16384;

    if (t == 0) {
        mbar_init(mbar, 1); mbar_init(mbar + 8, 1);
        mbar_init(mbar + 16, 8); mbar_init(mbar + 24, 8);
    }
    __syncthreads();
    if (t == 0) {
        mbar_expect(mbar, 98304u);
        bulk_g2s(sQ, Qp, 32768u, mbar);
        bulk_g2s(sK[0], Kp, 32768u, mbar);
        bulk_g2s(sV[0], Vp, 32768u, mbar);
        mbar_expect(mbar + 8, 65536u);
        bulk_g2s(sK[1], Kp + (size_t)128 * 128, 32768u, mbar + 8);
        bulk_g2s(sV[1], Vp + 16384, 32768u, mbar + 8);
    }

    const float CSC = 0.08838834764831845f * 1.4426950408889634f;
    float m_[2] = {-1e30f, -1e30f}, l_[2] = {0.f, 0.f};
    float oacc[16][4] = {};

    for (int kt = 0; kt < 16; kt++) {
        int buf = kt & 1;
        uint32_t par = (uint32_t)((kt >> 1) & 1);
        mbar_wait(mbar + (uint32_t)buf * 8u, par);

        float sacc[16][4] = {};
        #pragma unroll
        for (int ks = 0; ks < 8; ks++) {
            uint32_t Af[4];
            {
                int r = w * 16 + (lane & 15);
                int q8 = ks * 2 + (lane >> 4);
                ldsm4(Af[0], Af[1], Af[2], Af[3], swz256(sQ, r, q8));
            }
            uint32_t Bf[16][2];
            #pragma unroll
            for (int np = 0; np < 8; np++) {
                int r = np * 16 + ((lane >> 4) << 3) + (lane & 7);
                int q8 = ks * 2 + ((lane >> 3) & 1);
                ldsm4(Bf[2 * np][0], Bf[2 * np][1], Bf[2 * np + 1][0], Bf[2 * np + 1][1],
                      swz256(sK[buf], r, q8));
            }
            #pragma unroll
            for (int nt = 0; nt < 16; nt++) mma16816(sacc[nt], Af, Bf[nt]);
        }

        #pragma unroll
        for (int h = 0; h < 2; h++) {
            float tm = -1e30f;
            #pragma unroll
            for (int nt = 0; nt < 16; nt++)
                tm = fmaxf(tm, fmaxf(sacc[nt][2 * h], sacc[nt][2 * h + 1]));
            tm *= CSC;
            tm = fmaxf(tm, __shfl_xor_sync(0xffffffffu, tm, 1));
            tm = fmaxf(tm, __shfl_xor_sync(0xffffffffu, tm, 2));
            float mn = fmaxf(m_[h], tm);
            float alpha = exp2f(m_[h] - mn);
            float rs = 0.f;
            #pragma unroll
            for (int nt = 0; nt < 16; nt++) {
                float p0 = exp2f(sacc[nt][2 * h] * CSC - mn);
                float p1 = exp2f(sacc[nt][2 * h + 1] * CSC - mn);
                sacc[nt][2 * h] = p0; sacc[nt][2 * h + 1] = p1;
                rs += p0 + p1;
            }
            rs += __shfl_xor_sync(0xffffffffu, rs, 1);
            rs += __shfl_xor_sync(0xffffffffu, rs, 2);
            l_[h] = l_[h] * alpha + rs;
            m_[h] = mn;
            #pragma unroll
            for (int nt = 0; nt < 16; nt++) { oacc[nt][2 * h] *= alpha; oacc[nt][2 * h + 1] *= alpha; }
        }

        #pragma unroll
        for (int kk = 0; kk < 8; kk++) {
            uint32_t pf[4];
            pf[0] = packh2(sacc[2 * kk][0], sacc[2 * kk][1]);
            pf[1] = packh2(sacc[2 * kk][2], sacc[2 * kk][3]);
            pf[2] = packh2(sacc[2 * kk + 1][0], sacc[2 * kk + 1][1]);
            pf[3] = packh2(sacc[2 * kk + 1][2], sacc[2 * kk + 1][3]);
            uint32_t Bv[16][2];
            #pragma unroll
            for (int np = 0; np < 8; np++) {
                int r = np * 16 + ((lane >> 4) << 3) + (lane & 7);
                int q8 = kk * 2 + ((lane >> 3) & 1);
                ldsm4(Bv[2 * np][0], Bv[2 * np][1], Bv[2 * np + 1][0], Bv[2 * np + 1][1],
                      swz256(sV[buf], r, q8));
            }
            #pragma unroll
            for (int nt = 0; nt < 16; nt++) mma16816(oacc[nt], pf, Bv[nt]);
        }

        // warp done reading sK/sV[buf]; rotating producer refills for kt+2
        if (lane == 0) {
            mbar_arrive(mbar + 16u + (uint32_t)buf * 8u);
            if (kt + 2 < 16 && w == (kt & 7)) {
                mbar_wait(mbar + 16u + (uint32_t)buf * 8u, par);
                mbar_expect(mbar + (uint32_t)buf * 8u, 65536u);
                bulk_g2s(sK[buf], Kp + (size_t)(kt + 2) * 128 * 128, 32768u,
                         mbar + (uint32_t)buf * 8u);
                bulk_g2s(sV[buf], Vp + (size_t)(kt + 2) * 16384, 32768u,
                         mbar + (uint32_t)buf * 8u);
            }
        }
    }

    float inv0 = 1.f / l_[0], inv1 = 1.f / l_[1];
    int row0 = qt * 128 + w * 16 + (lane >> 2);
    #pragma unroll
    for (int nt = 0; nt < 16; nt++) {
        int col = head * 128 + nt * 8 + (lane & 3) * 2;
        *(__half2*)(catp + tiled_off(L, row0, col)) =
            __floats2half2_rn(oacc[nt][0] * inv0, oacc[nt][1] * inv0);
        *(__half2*)(catp + tiled_off(L, row0 + 8, col)) =
            __floats2half2_rn(oacc[nt][2] * inv1, oacc[nt][3] * inv1);
    }
}

// ================= conversions =================
__global__ void conv_tile(const float* __restrict__ src, __half* __restrict__ dst,
                          int N, int K, long long n8) {
    long long i = (long long)blockIdx.x * 256 + threadIdx.x;
    if (i >= n8) return;
    int kq = K >> 3;
    int r = (int)(i / kq), q8i = (int)(i - (long long)r * kq);
    int c0 = q8i * 8;
    const float4* s = (const float4*)(src + (size_t)r * K + c0);
    float4 a = s[0], b = s[1];
    __half2 h0 = __floats2half2_rn(a.x, a.y);
    __half2 h1 = __floats2half2_rn(a.z, a.w);
    __half2 h2 = __floats2half2_rn(b.x, b.y);
    __half2 h3 = __floats2half2_rn(b.z, b.w);
    uint4 o;
    o.x = *(uint32_t*)&h0; o.y = *(uint32_t*)&h1;
    o.z = *(uint32_t*)&h2; o.w = *(uint32_t*)&h3;
    *(uint4*)(dst + tiled_off(N, r, c0)) = o;
}

__global__ void upext_k(const float* __restrict__ upq, const float* __restrict__ upk,
                        const float* __restrict__ upv) {
    int i = blockIdx.x * 256 + threadIdx.x;
    int o = i >> 7, j = i & 127;
    int mat = o / HID, colm = o - mat * HID;
    int jj = j - mat * 32;
    float v = 0.f;
    if (j < 96 && jj >= 0 && jj < 32) {
        const float* up = (mat == 0) ? upq : (mat == 1) ? upk : upv;
        v = up[(size_t)colm * 32 + jj];
    }
    g_w12[tiled_off(H1, o, 3072 + j)] = __float2half(v);
}

__global__ void yext_k() {
    int i = blockIdx.x * 256 + threadIdx.x;
    int l = i >> 5, j = i & 31;
    float s0 = 0.f, s1 = 0.f, s2 = 0.f;
    #pragma unroll
    for (int z = 0; z < 4; z++) {
        size_t base = (size_t)z * 3 * L * 32 + (size_t)l * 32 + j;
        s0 += g_y1p[base];
        s1 += g_y1p[base + (size_t)L * 32];
        s2 += g_y1p[base + 2 * (size_t)L * 32];
    }
    g_xmod2[tiled_off(L, l, 3072 + j)]  = __float2half(s0);
    g_xmod2[tiled_off(L, l, 3104 + j)]  = __float2half(s1);
    g_xmod2[tiled_off(L, l, 3136 + j)]  = __float2half(s2);
    g_xmod2[tiled_off(L, l, 3168 + j)]  = __float2half(0.f);
}

// ================= small kernels =================
__global__ __launch_bounds__(256) void mod_gemv(const float* __restrict__ vec,
                                                const float* __restrict__ W,
                                                const float* __restrict__ b) {
    __shared__ float sv[HID];
    int t = threadIdx.x;
    for (int j = t; j < HID; j += 256) {
        float v = vec[j];
        sv[j] = v / (1.f + expf(-v));
    }
    __syncthreads();
    int o = blockIdx.x * 8 + (t >> 5);
    int lane = t & 31;
    const float* w = W + (size_t)o * HID;
    float acc = 0.f;
    for (int k = lane; k < HID; k += 32) acc += sv[k] * w[k];
    #pragma unroll
    for (int s = 16; s; s >>= 1) acc += __shfl_xor_sync(0xffffffffu, acc, s);
    if (lane == 0) g_m[o] = acc + b[o];
}

__global__ __launch_bounds__(256) void ln_mod_k(const float* __restrict__ x) {
    int l = blockIdx.x, t = threadIdx.x;
    const float* xr = x + (size_t)l * HID;
    float s = 0.f, s2 = 0.f;
    for (int j = t; j < HID; j += 256) { float v = xr[j]; s += v; s2 += v * v; }
    __shared__ float sh[16];
    #pragma unroll
    for (int o = 16; o; o >>= 1) {
        s  += __shfl_xor_sync(0xffffffffu, s, o);
        s2 += __shfl_xor_sync(0xffffffffu, s2, o);
    }
    if ((t & 31) == 0) { sh[t >> 5] = s; sh[8 + (t >> 5)] = s2; }
    __syncthreads();
    float ts = 0.f, ts2 = 0.f;
    #pragma unroll
    for (int i = 0; i < 8; i++) { ts += sh[i]; ts2 += sh[8 + i]; }
    float mu = ts * (1.f / HID);
    float var = ts2 * (1.f / HID) - mu * mu;
    float r = rsqrtf(var + 1e-6f);
    for (int u = t; u < HID / 8; u += 256) {
        int j0 = u * 8;
        __half2 hp[4];
        #pragma unroll
        for (int e = 0; e < 4; e++) {
            int j = j0 + 2 * e;
            float v0 = (xr[j] - mu) * r;
            float v1 = (xr[j + 1] - mu) * r;
            hp[e] = __floats2half2_rn((1.f + g_m[HID + j]) * v0 + g_m[j],
                                      (1.f + g_m[HID + j + 1]) * v1 + g_m[j + 1]);
        }
        uint4 o;
        o.x = *(uint32_t*)&hp[0]; o.y = *(uint32_t*)&hp[1];
        o.z = *(uint32_t*)&hp[2]; o.w = *(uint32_t*)&hp[3];
        *(uint4*)(g_xmod2 + tiled_off(L, l, j0)) = o;
    }
}

__global__ __launch_bounds__(256) void lora_down_s(
    const __half* __restrict__ X, const float* __restrict__ D0,
    const float* __restrict__ D1, const float* __restrict__ D2,
    float* __restrict__ Yp, int nc, int kbase, int K,
    long long zs, long long ms, int ldy)
{
    __shared__ float xs[64][65];
    __shared__ float ds[64][32];
    int t = threadIdx.x;
    int m0 = blockIdx.x * 64;
    int mat = blockIdx.y, z = blockIdx.z;
    const float* D = (mat == 0) ? D0 : ((mat == 1) ? D1 : D2);
    float* Y = Yp + (size_t)z * zs + (size_t)mat * ms;
    int tx = t & 31, ty = t >> 5;
    int drow = t >> 3, df4 = t & 7;
    float acc[8] = {};
    int k0b = (kbase + z * nc) * 64;

    for (int c = 0; c < nc; c++) {
        int k0 = k0b + c * 64;
        #pragma unroll
        for (int j = 0; j < 4; j++) {
            int slot = t + j * 256;
            int row = slot >> 4, c4 = (slot & 15) * 4;
            uint2 u = *(const uint2*)(X + tiled_off(L, m0 + row, k0 + c4));
            __half2 ab = *(__half2*)&u.x, cd = *(__half2*)&u.y;
            float2 f0 = __half22float2(ab), f1 = __half22float2(cd);
            xs[c4][row] = f0.x; xs[c4 + 1][row] = f0.y;
            xs[c4 + 2][row] = f1.x; xs[c4 + 3][row] = f1.y;
        }
        #pragma unroll
        for (int j = 0; j < 2; j++) {
            int kk = (df4 + 8 * j) * 4;
            float4 vd = *(const float4*)(D + (size_t)drow * K + k0 + kk);
            ds[kk][drow] = vd.x; ds[kk + 1][drow] = vd.y;
            ds[kk + 2][drow] = vd.z; ds[kk + 3][drow] = vd.w;
        }
        __syncthreads();
        #pragma unroll
        for (int kk = 0; kk < 64; kk++) {
            float dv = ds[kk][tx];
            #pragma unroll
            for (int i = 0; i < 8; i++) acc[i] += xs[kk][ty * 8 + i] * dv;
        }
        __syncthreads();
    }
    #pragma unroll
    for (int i = 0; i < 8; i++)
        Y[(size_t)(m0 + ty * 8 + i) * ldy + tx] = acc[i];
}

__global__ __launch_bounds__(128) void qkv_finalize(
    const float* __restrict__ q_scale, const float* __restrict__ k_scale,
    const float* __restrict__ pe)
{
    __shared__ float sq[128], sk[128], red[8];

    const int head = blockIdx.x, d = threadIdx.x;
    const int l0 = blockIdx.y * 16;
    const int col = head * HD + d;

    const float qsc = q_scale[d], ksc = k_scale[d];
    const float qsc2 = q_scale[d ^ 1], ksc2 = k_scale[d ^ 1];

    for (int li = 0; li < 16; li++) {
        int l = l0 + li;
        size_t hb = (size_t)l * H3;
        float qv = __half2float(g_hh[hb + col]);
        float kv = __half2float(g_hh[hb + HID + col]);
        float vv = __half2float(g_hh[hb + 2 * HID + col]);

        __syncthreads();
        sq[d] = qv; sk[d] = kv;
        float aq = qv * qv, ak = kv * kv;
        #pragma unroll
        for (int o = 16; o; o >>= 1) {
            aq += __shfl_xor_sync(0xffffffffu, aq, o);
            ak += __shfl_xor_sync(0xffffffffu, ak, o);
        }
        if ((d & 31) == 0) { red[d >> 5] = aq; red[4 + (d >> 5)] = ak; }
        __syncthreads();

        float rq = rsqrtf((red[0] + red[1] + red[2] + red[3]) * (1.f / HD) + 1e-6f);
        float rk = rsqrtf((red[4] + red[5] + red[6] + red[7]) * (1.f / HD) + 1e-6f);

        int e = d & ~1, o_ = d | 1;
        float sce = (d & 1) ? qsc2 : qsc;
        float sco = (d & 1) ? qsc : qsc2;
        float kce = (d & 1) ? ksc2 : ksc;
        float kco = (d & 1) ? ksc : ksc2;
        float q0 = sq[e]  * rq * sce;
        float q1 = sq[o_] * rq * sco;
        float k0 = sk[e]  * rk * kce;
        float k1 = sk[o_] * rk * kco;

        const float* p = pe + ((size_t)l * 64 + (d >> 1)) * 4;
        float qo = (d & 1) ? (p[2] * q0 + p[3] * q1) : (p[0] * q0 + p[1] * q1);
        float ko = (d & 1) ? (p[2] * k0 + p[3] * k1) : (p[0] * k0 + p[1] * k1);

        {
            int q8 = d >> 3, sub = d >> 6;
            int sr = l * 2 + sub;
            size_t off = ((size_t)head * L + l) * 128 + (size_t)sub * 64 +
                         (size_t)(((q8 & 7) ^ (sr & 7)) << 3) + (d & 7);
            g_q2[off] = __float2half(qo);
            g_k2[off] = __float2half(ko);
        }
        {
            int kt = l >> 7, lc = l & 127;
            int q8 = lc >> 3;
            int sr = d * 2 + (q8 >> 3);
            size_t off = ((size_t)(head * 16 + kt)) * 16384 + (size_t)sr * 64 +
                         (size_t)(((q8 & 7) ^ (sr & 7)) << 3) + (lc & 7);
            g_v2[off] = __float2half(vv);
        }
    }
}

__global__ __launch_bounds__(256) void final_k(const float* __restrict__ x,
                                               const float* __restrict__ pu,
                                               const float* __restrict__ b2,
                                               float* __restrict__ out)
{
    int l = blockIdx.y;
    int c = blockIdx.x * 256 + threadIdx.x;
    __shared__ float sp[64];
    if (threadIdx.x < 64) {
        float s = 0.f;
        #pragma unroll
        for (int z = 0; z < 8; z++)
            s += g_plp[(size_t)z * L * 64 + (size_t)l * 64 + threadIdx.x];
        sp[threadIdx.x] = s;
    }
    __syncthreads();

    const float4* ur = (const float4*)(pu + (size_t)c * 64);
    float a = 0.f;
    #pragma unroll
    for (int r = 0; r < 16; r++) {
        float4 u = ur[r];
        a += u.x * sp[4 * r] + u.y * sp[4 * r + 1] + u.z * sp[4 * r + 2] + u.w * sp[4 * r + 3];
    }
    size_t idx = (size_t)l * HID + c;
    const size_t LH = (size_t)L * HID;
    float o = g_o[idx] + g_o[idx + LH] + g_o[idx + 2 * LH] + g_o[idx + 3 * LH] + b2[c] + a;
    out[idx] = x[idx] + g_m[2 * HID + c] * o;
}

// ================= launch (R10 schedule) =================
extern "C" void kernel_launch(void* const* d_in, const int* in_sizes, int n_in,
                              void* d_out, int out_size)
{
    const float* x   = (const float*)d_in[0];
    const float* vec = (const float*)d_in[1];
    const float* pe  = (const float*)d_in[2];
    const float* mw  = (const float*)d_in[3];
    const float* mb  = (const float*)d_in[4];
    const float* w1  = (const float*)d_in[5];
    const float* b1  = (const float*)d_in[6];
    const float* w2  = (const float*)d_in[7];
    const float* b2  = (const float*)d_in[8];
    const float* qs  = (const float*)d_in[9];
    const float* ks  = (const float*)d_in[10];
    const float* lqd = (const float*)d_in[11];
    const float* lqu = (const float*)d_in[12];
    const float* lkd = (const float*)d_in[13];
    const float* lku = (const float*)d_in[14];
    const float* lvd = (const float*)d_in[15];
    const float* lvu = (const float*)d_in[16];
    const float* pd  = (const float*)d_in[17];
    const float* pu  = (const float*)d_in[18];
    float* out = (float*)d_out;

    float *y1p, *plp, *ob;
    __half *xmod2, *w12, *w22, *cat2, *q2, *k2, *v2;
    cudaGetSymbolAddress((void**)&y1p,   g_y1p);
    cudaGetSymbolAddress((void**)&plp,   g_plp);
    cudaGetSymbolAddress((void**)&ob,    g_o);
    cudaGetSymbolAddress((void**)&xmod2, g_xmod2);
    cudaGetSymbolAddress((void**)&w12,   g_w12);
    cudaGetSymbolAddress((void**)&w22,   g_w22);
    cudaGetSymbolAddress((void**)&cat2,  g_cat2);
    cudaGetSymbolAddress((void**)&q2,    g_q2);
    cudaGetSymbolAddress((void**)&k2,    g_k2);
    cudaGetSymbolAddress((void**)&v2,    g_v2);

    const int SMG = 4 * 48 * 1024 + 64;
    const int SMF = 5 * 32 * 1024 + 64;

    static cudaStream_t s1 = 0, s2 = 0;
    static cudaEvent_t evRoot = 0, evLn = 0, evW1 = 0, evUp = 0, evW2 = 0;
    static cudaEvent_t evY = 0, evMLP = 0, evG2m = 0, evLpm = 0;
    static bool init_done = false;
    if (!init_done) {
        cudaFuncSetAttribute(gemm512<1>, cudaFuncAttributeMaxDynamicSharedMemorySize, SMG);
        cudaFuncSetAttribute(gemm512<0>, cudaFuncAttributeMaxDynamicSharedMemorySize, SMG);
        cudaFuncSetAttribute(flash_k,    cudaFuncAttributeMaxDynamicSharedMemorySize, SMF);
        cudaStreamCreateWithFlags(&s1, cudaStreamNonBlocking);
        cudaStreamCreateWithFlags(&s2, cudaStreamNonBlocking);
        cudaEventCreateWithFlags(&evRoot, cudaEventDisableTiming);
        cudaEventCreateWithFlags(&evLn,   cudaEventDisableTiming);
        cudaEventCreateWithFlags(&evW1,   cudaEventDisableTiming);
        cudaEventCreateWithFlags(&evUp,   cudaEventDisableTiming);
        cudaEventCreateWithFlags(&evW2,   cudaEventDisableTiming);
        cudaEventCreateWithFlags(&evY,    cudaEventDisableTiming);
        cudaEventCreateWithFlags(&evMLP,  cudaEventDisableTiming);
        cudaEventCreateWithFlags(&evG2m,  cudaEventDisableTiming);
        cudaEventCreateWithFlags(&evLpm,  cudaEventDisableTiming);
        init_done = true;
    }

    cudaEventRecord(evRoot, 0);
    cudaStreamWaitEvent(s1, evRoot, 0);
    cudaStreamWaitEvent(s2, evRoot, 0);

    // s0: modulation + layernorm
    mod_gemv<<<(3 * HID) / 8, 256>>>(vec, mw, mb);
    ln_mod_k<<<L, 256>>>(x);
    cudaEventRecord(evLn, 0);

    // s1: conv w1 then gemm1-MLP (profiling slot 3)
    conv_tile<<<(int)(((size_t)H1 * HID / 8 + 255) / 256), 256, 0, s1>>>(
        w1, w12, H1, HID, (size_t)H1 * HID / 8);
    cudaEventRecord(evW1, s1);
    cudaStreamWaitEvent(s1, evLn, 0);
    gemm512<1><<<dim3(L / 128, 48, 1), 512, SMG, s1>>>(
        xmod2, w12, nullptr, b1, cat2, 48, 0, 36, L, H1, 0, 0LL);
    cudaEventRecord(evMLP, s1);

    // s2: up-ext, then qkv lora downs, then y-ext
    upext_k<<<(H3 * 128) / 256, 256, 0, s2>>>(lqu, lku, lvu);
    cudaEventRecord(evUp, s2);
    cudaStreamWaitEvent(s2, evLn, 0);
    lora_down_s<<<dim3(L / 64, 3, 4), 256, 0, s2>>>(
        xmod2, lqd, lkd, lvd, y1p, 12, 0, HID,
        3LL * L * 32, (long long)L * 32, 32);
    yext_k<<<(L * 32) / 256, 256, 0, s2>>>();
    cudaEventRecord(evY, s2);

    // s1: conv w2
    conv_tile<<<(int)(((size_t)HID * CATD / 8 + 255) / 256), 256, 0, s1>>>(
        w2, w22, HID, CATD, (size_t)HID * CATD / 8);
    cudaEventRecord(evW2, s1);

    // s0: gemm1-QKV
    cudaStreamWaitEvent(0, evW1, 0);
    cudaStreamWaitEvent(0, evUp, 0);
    cudaStreamWaitEvent(0, evY, 0);
    gemm512<1><<<dim3(L / 128, 36, 1), 512, SMG>>>(
        xmod2, w12, nullptr, b1, cat2, 50, 0, 0, L, H1, 0, 0LL);

    // s0: finalize + flash
    qkv_finalize<<<dim3(HEADS, L / 16), 128>>>(qs, ks, pe);
    flash_k<<<dim3(L / 128, HEADS), 256, SMF>>>(q2, k2, v2, cat2);

    // s1: gemm2 over MLP K-chunks -> g_o[0..1]
    gemm512<0><<<dim3(L / 128, HID / 256, 2), 512, SMG, s1>>>(
        cat2, w22, ob, nullptr, nullptr, 96, 48, 0, L, HID, HID, (long long)L * HID);
    cudaEventRecord(evG2m, s1);

    // s2: proj lora over MLP K-chunks -> plp[0..5]
    cudaStreamWaitEvent(s2, evMLP, 0);
    lora_down_s<<<dim3(L / 64, 2, 6), 256, 0, s2>>>(
        cat2, pd, pd + (size_t)32 * CATD, nullptr, plp, 32, 48, CATD,
        (long long)L * 64, 32LL, 64);
    cudaEventRecord(evLpm, s2);

    // s0: gemm2 attn chunks -> g_o[2..3], proj lora attn -> plp[6..7]
    cudaStreamWaitEvent(0, evW2, 0);
    gemm512<0><<<dim3(L / 128, HID / 256, 2), 512, SMG>>>(
        cat2, w22, ob + 2 * (size_t)L * HID, nullptr, nullptr, 24, 0, 0, L, HID, HID,
        (long long)L * HID);
    lora_down_s<<<dim3(L / 64, 2, 2), 256>>>(
        cat2, pd, pd + (size_t)32 * CATD, nullptr, plp + 6 * (size_t)L * 64, 24, 0, CATD,
        (long long)L * 64, 32LL, 64);

    // join
    cudaStreamWaitEvent(0, evG2m, 0);
    cudaStreamWaitEvent(0, evLpm, 0);
    final_k<<<dim3(HID / 256, L), 256>>>(x, pu, b2, out);
}

// round 16
// speedup vs baseline: 1.0943x; 1.0075x over previous
#include <cuda_runtime.h>
#include <cuda_fp16.h>
#include <math.h>
#include <stdint.h>

#define L 2048
#define HID 3072
#define HEADS 24
#define HD 128
#define MLPD 12288
#define H1 21504
#define CATD 15360
#define H3 9216   // 3*HID

// ---------------- scratch ----------------
__device__ float g_m[3 * HID];
__device__ float g_y1p[4 * 3 * (size_t)L * 32];
__device__ float g_plp[8 * (size_t)L * 64];
__device__ float g_o[6 * (size_t)L * HID];        // 3 MLP + 3 attn partials

__device__ __half g_hh[(size_t)L * H3];
__device__ __half g_xmod2[(size_t)L * 3200];
__device__ __half g_w12[(size_t)H1 * 3200];
__device__ __half g_w22[(size_t)HID * CATD];
__device__ __half g_cat2[(size_t)L * CATD];
__device__ __half g_q2[(size_t)HEADS * L * HD];
__device__ __half g_k2[(size_t)HEADS * L * HD];
__device__ __half g_v2[(size_t)HEADS * HD * L];

// ================= helpers =================
__device__ __forceinline__ uint32_t smem_u32(const void* p) {
    uint32_t a;
    asm("{ .reg .u64 t; cvta.to.shared.u64 t, %1; cvt.u32.u64 %0, t; }" : "=r"(a) : "l"(p));
    return a;
}
__device__ __forceinline__ void mbar_init(uint32_t a, uint32_t cnt) {
    asm volatile("mbarrier.init.shared.b64 [%0], %1;" :: "r"(a), "r"(cnt) : "memory");
}
__device__ __forceinline__ void mbar_expect(uint32_t a, uint32_t bytes) {
    asm volatile("mbarrier.arrive.expect_tx.shared.b64 _, [%0], %1;" :: "r"(a), "r"(bytes) : "memory");
}
__device__ __forceinline__ void mbar_arrive(uint32_t a) {
    asm volatile("mbarrier.arrive.shared.b64 _, [%0];" :: "r"(a) : "memory");
}
__device__ __forceinline__ void mbar_wait(uint32_t a, uint32_t parity) {
    asm volatile(
        "{\n\t.reg .pred P;\n"
        "WL_%=:\n\t"
        "mbarrier.try_wait.parity.acquire.cta.shared::cta.b64 P, [%0], %1, 0x989680;\n\t"
        "@P bra WD_%=;\n\t"
        "bra WL_%=;\n"
        "WD_%=:\n\t}"
        :: "r"(a), "r"(parity) : "memory");
}
__device__ __forceinline__ void bulk_g2s(uint32_t dst, const void* src, uint32_t bytes, uint32_t mbar) {
    asm volatile(
        "cp.async.bulk.shared::cta.global.mbarrier::complete_tx::bytes [%0], [%1], %2, [%3];"
        :: "r"(dst), "l"(src), "r"(bytes), "r"(mbar) : "memory");
}
__device__ __forceinline__ void ldsm4(uint32_t& r0, uint32_t& r1, uint32_t& r2, uint32_t& r3,
                                      uint32_t addr) {
    asm volatile("ldmatrix.sync.aligned.m8n8.x4.shared.b16 {%0,%1,%2,%3}, [%4];"
                 : "=r"(r0), "=r"(r1), "=r"(r2), "=r"(r3) : "r"(addr));
}
__device__ __forceinline__ void mma16816(float* d, const uint32_t* a, const uint32_t* b) {
    asm volatile(
        "mma.sync.aligned.m16n8k16.row.col.f32.f16.f16.f32 "
        "{%0,%1,%2,%3}, {%4,%5,%6,%7}, {%8,%9}, {%0,%1,%2,%3};"
        : "+f"(d[0]), "+f"(d[1]), "+f"(d[2]), "+f"(d[3])
        : "r"(a[0]), "r"(a[1]), "r"(a[2]), "r"(a[3]), "r"(b[0]), "r"(b[1]));
}
__device__ __forceinline__ uint32_t packh2(float a, float b) {
    __half2 h = __floats2half2_rn(a, b);
    return *(uint32_t*)&h;
}
__device__ __forceinline__ float gelu1(float x) {
    float u = 0.7978845608028654f * (x + 0.044715f * x * x * x);
    float e = __expf(2.f * u);
    return x * e / (e + 1.f);
}
__device__ __forceinline__ uint32_t swz128(uint32_t base, int r, int q) {
    return base + (uint32_t)r * 128u + ((uint32_t)(q ^ (r & 7)) << 4);
}
__device__ __forceinline__ uint32_t swz256(uint32_t base, int r, int q8) {
    int sr = r * 2 + (q8 >> 3);
    int q = q8 & 7;
    return base + (uint32_t)sr * 128u + ((uint32_t)(q ^ (sr & 7)) << 4);
}
__device__ __forceinline__ size_t tiled_off(int M, int r, int c) {
    return ((size_t)(c >> 6) * M + r) * 64 + (size_t)((((c & 63) >> 3) ^ (r & 7)) << 3) + (c & 7);
}

// ================= bulk-fed fp16 NT GEMM (4-stage, rotating producer, unrolled stages) ======
template <int MODE>
__global__ __launch_bounds__(512, 1) void gemm512(
    const __half* __restrict__ At, const __half* __restrict__ Bt,
    float* __restrict__ C, const float* __restrict__ bias,
    __half* __restrict__ catp, int nc, int kbase, int nbase,
    int M, int N, int ldc, long long zsC)
{
    constexpr uint32_t ABYTES = 128u * 128u;
    constexpr uint32_t BBYTES = 256u * 128u;
    constexpr uint32_t STAGE = ABYTES + BBYTES;   // 48KB

    extern __shared__ char smraw[];
    uint32_t s0 = smem_u32(smraw);
    uint32_t mbF = s0 + 4u * STAGE;
    uint32_t mbE = mbF + 32u;

    const int t = threadIdx.x, w = t >> 5, lane = t & 31;
    const int wm = w & 3, wn = w >> 2;
    const int m0 = blockIdx.x * 128, n0 = (nbase + blockIdx.y) * 256;
    const int z = blockIdx.z;
    const int c0 = kbase + z * nc;
    C += (size_t)z * zsC;

    if (t == 0) {
        #pragma unroll
        for (int i = 0; i < 4; i++) {
            mbar_init(mbF + (uint32_t)i * 8u, 1);
            mbar_init(mbE + (uint32_t)i * 8u, 16);
        }
    }
    __syncthreads();

    auto issue = [&](int c, int stg) {
        uint32_t mb = mbF + (uint32_t)stg * 8u;
        uint32_t ab = s0 + (uint32_t)stg * STAGE;
        mbar_expect(mb, ABYTES + BBYTES);
        bulk_g2s(ab, At + ((size_t)(c0 + c) * M + m0) * 64, ABYTES, mb);
        bulk_g2s(ab + ABYTES, Bt + ((size_t)(c0 + c) * N + n0) * 64, BBYTES, mb);
    };

    if (t == 0) { issue(0, 0); issue(1, 1); issue(2, 2); issue(3, 3); }

    uint32_t offA[4][2], offB[4][4];
    #pragma unroll
    for (int s = 0; s < 4; s++) {
        #pragma unroll
        for (int mt = 0; mt < 2; mt++) {
            int r = wm * 32 + mt * 16 + (lane & 15);
            int q = s * 2 + (lane >> 4);
            offA[s][mt] = swz128(0, r, q);
        }
        #pragma unroll
        for (int np = 0; np < 4; np++) {
            int r = wn * 64 + np * 16 + ((lane >> 4) << 3) + (lane & 7);
            int q = s * 2 + ((lane >> 3) & 1);
            offB[s][np] = ABYTES + swz128(0, r, q);
        }
    }

    float acc[2][8][4] = {};

    for (int cb = 0; cb < nc; cb += 4) {
        uint32_t par = (uint32_t)((cb >> 2) & 1);
        #pragma unroll
        for (int i = 0; i < 4; i++) {
            int c = cb + i;
            if (c >= nc) break;
            mbar_wait(mbF + (uint32_t)i * 8u, par);

            uint32_t sb = s0 + (uint32_t)i * STAGE;

            #pragma unroll
            for (int s = 0; s < 4; s++) {
                uint32_t Af[2][4];
                #pragma unroll
                for (int mt = 0; mt < 2; mt++)
                    ldsm4(Af[mt][0], Af[mt][1], Af[mt][2], Af[mt][3], sb + offA[s][mt]);
                uint32_t Bf[8][2];
                #pragma unroll
                for (int np = 0; np < 4; np++)
                    ldsm4(Bf[2 * np][0], Bf[2 * np][1], Bf[2 * np + 1][0], Bf[2 * np + 1][1],
                          sb + offB[s][np]);
                #pragma unroll
                for (int mt = 0; mt < 2; mt++)
                    #pragma unroll
                    for (int nt = 0; nt < 8; nt++)
                        mma16816(acc[mt][nt], Af[mt], Bf[nt]);
            }

            if (lane == 0) {
                mbar_arrive(mbE + (uint32_t)i * 8u);
                if (c + 4 < nc && w == (c & 15)) {
                    mbar_wait(mbE + (uint32_t)i * 8u, par);
                    issue(c + 4, i);
                }
            }
        }
    }

    #pragma unroll
    for (int mt = 0; mt < 2; mt++) {
        int row = m0 + wm * 32 + mt * 16 + (lane >> 2);
        #pragma unroll
        for (int nt = 0; nt < 8; nt++) {
            int col = n0 + wn * 64 + nt * 8 + (lane & 3) * 2;
            if (MODE == 1) {
                float b0 = bias[col], b1v = bias[col + 1];
                float v00 = acc[mt][nt][0] + b0, v01 = acc[mt][nt][1] + b1v;
                float v10 = acc[mt][nt][2] + b0, v11 = acc[mt][nt][3] + b1v;
                if (n0 >= H3) {
                    int cc = col - 6144;
                    *(__half2*)(catp + tiled_off(L, row, cc)) =
                        __floats2half2_rn(gelu1(v00), gelu1(v01));
                    *(__half2*)(catp + tiled_off(L, row + 8, cc)) =
                        __floats2half2_rn(gelu1(v10), gelu1(v11));
                } else {
                    *(__half2*)(g_hh + (size_t)row * H3 + col) = __floats2half2_rn(v00, v01);
                    *(__half2*)(g_hh + (size_t)(row + 8) * H3 + col) = __floats2half2_rn(v10, v11);
                }
            } else {
                *(float2*)(C + (size_t)row * ldc + col) =
                    make_float2(acc[mt][nt][0], acc[mt][nt][1]);
                *(float2*)(C + (size_t)(row + 8) * ldc + col) =
                    make_float2(acc[mt][nt][2], acc[mt][nt][3]);
            }
        }
    }
}

// ================= flash attention (warp-async prefetch) =================
__global__ __launch_bounds__(256, 1) void flash_k(
    const __half* __restrict__ Qg, const __half* __restrict__ Kg,
    const __half* __restrict__ Vg, __half* __restrict__ catp)
{
    extern __shared__ char smraw[];
    uint32_t s0 = smem_u32(smraw);
    const uint32_t sQ = s0;
    const uint32_t sK[2] = {s0 + 32768u, s0 + 98304u};
    const uint32_t sV[2] = {s0 + 65536u, s0 + 131072u};
    const uint32_t mbar = s0 + 163840u;

    const int t = threadIdx.x, w = t >> 5, lane = t & 31;
    const int qt = blockIdx.x, head = blockIdx.y;

    const __half* Qp = Qg + ((size_t)head * L + qt * 128) * 128;
    const __half* Kp = Kg + (size_t)head * L * 128;
    const __half* Vp = Vg + (size_t)head * 16 * 16384;

    if (t == 0) {
        mbar_init(mbar, 1); mbar_init(mbar + 8, 1);
        mbar_init(mbar + 16, 8); mbar_init(mbar + 24, 8);
    }
    __syncthreads();
    if (t == 0) {
        mbar_expect(mbar, 98304u);
        bulk_g2s(sQ, Qp, 32768u, mbar);
        bulk_g2s(sK[0], Kp, 32768u, mbar);
        bulk_g2s(sV[0], Vp, 32768u, mbar);
        mbar_expect(mbar + 8, 65536u);
        bulk_g2s(sK[1], Kp + (size_t)128 * 128, 32768u, mbar + 8);
        bulk_g2s(sV[1], Vp + 16384, 32768u, mbar + 8);
    }

    const float CSC = 0.08838834764831845f * 1.4426950408889634f;
    float m_[2] = {-1e30f, -1e30f}, l_[2] = {0.f, 0.f};
    float oacc[16][4] = {};

    for (int kt = 0; kt < 16; kt++) {
        int buf = kt & 1;
        uint32_t par = (uint32_t)((kt >> 1) & 1);
        mbar_wait(mbar + (uint32_t)buf * 8u, par);

        float sacc[16][4] = {};
        #pragma unroll
        for (int ks = 0; ks < 8; ks++) {
            uint32_t Af[4];
            {
                int r = w * 16 + (lane & 15);
                int q8 = ks * 2 + (lane >> 4);
                ldsm4(Af[0], Af[1], Af[2], Af[3], swz256(sQ, r, q8));
            }
            uint32_t Bf[16][2];
            #pragma unroll
            for (int np = 0; np < 8; np++) {
                int r = np * 16 + ((lane >> 4) << 3) + (lane & 7);
                int q8 = ks * 2 + ((lane >> 3) & 1);
                ldsm4(Bf[2 * np][0], Bf[2 * np][1], Bf[2 * np + 1][0], Bf[2 * np + 1][1],
                      swz256(sK[buf], r, q8));
            }
            #pragma unroll
            for (int nt = 0; nt < 16; nt++) mma16816(sacc[nt], Af, Bf[nt]);
        }

        #pragma unroll
        for (int h = 0; h < 2; h++) {
            float tm = -1e30f;
            #pragma unroll
            for (int nt = 0; nt < 16; nt++)
                tm = fmaxf(tm, fmaxf(sacc[nt][2 * h], sacc[nt][2 * h + 1]));
            tm *= CSC;
            tm = fmaxf(tm, __shfl_xor_sync(0xffffffffu, tm, 1));
            tm = fmaxf(tm, __shfl_xor_sync(0xffffffffu, tm, 2));
            float mn = fmaxf(m_[h], tm);
            float alpha = exp2f(m_[h] - mn);
            float rs = 0.f;
            #pragma unroll
            for (int nt = 0; nt < 16; nt++) {
                float p0 = exp2f(sacc[nt][2 * h] * CSC - mn);
                float p1 = exp2f(sacc[nt][2 * h + 1] * CSC - mn);
                sacc[nt][2 * h] = p0; sacc[nt][2 * h + 1] = p1;
                rs += p0 + p1;
            }
            rs += __shfl_xor_sync(0xffffffffu, rs, 1);
            rs += __shfl_xor_sync(0xffffffffu, rs, 2);
            l_[h] = l_[h] * alpha + rs;
            m_[h] = mn;
            #pragma unroll
            for (int nt = 0; nt < 16; nt++) { oacc[nt][2 * h] *= alpha; oacc[nt][2 * h + 1] *= alpha; }
        }

        #pragma unroll
        for (int kk = 0; kk < 8; kk++) {
            uint32_t pf[4];
            pf[0] = packh2(sacc[2 * kk][0], sacc[2 * kk][1]);
            pf[1] = packh2(sacc[2 * kk][2], sacc[2 * kk][3]);
            pf[2] = packh2(sacc[2 * kk + 1][0], sacc[2 * kk + 1][1]);
            pf[3] = packh2(sacc[2 * kk + 1][2], sacc[2 * kk + 1][3]);
            uint32_t Bv[16][2];
            #pragma unroll
            for (int np = 0; np < 8; np++) {
                int r = np * 16 + ((lane >> 4) << 3) + (lane & 7);
                int q8 = kk * 2 + ((lane >> 3) & 1);
                ldsm4(Bv[2 * np][0], Bv[2 * np][1], Bv[2 * np + 1][0], Bv[2 * np + 1][1],
                      swz256(sV[buf], r, q8));
            }
            #pragma unroll
            for (int nt = 0; nt < 16; nt++) mma16816(oacc[nt], pf, Bv[nt]);
        }

        if (lane == 0) {
            mbar_arrive(mbar + 16u + (uint32_t)buf * 8u);
            if (kt + 2 < 16 && w == (kt & 7)) {
                mbar_wait(mbar + 16u + (uint32_t)buf * 8u, par);
                mbar_expect(mbar + (uint32_t)buf * 8u, 65536u);
                bulk_g2s(sK[buf], Kp + (size_t)(kt + 2) * 128 * 128, 32768u,
                         mbar + (uint32_t)buf * 8u);
                bulk_g2s(sV[buf], Vp + (size_t)(kt + 2) * 16384, 32768u,
                         mbar + (uint32_t)buf * 8u);
            }
        }
    }

    float inv0 = 1.f / l_[0], inv1 = 1.f / l_[1];
    int row0 = qt * 128 + w * 16 + (lane >> 2);
    #pragma unroll
    for (int nt = 0; nt < 16; nt++) {
        int col = head * 128 + nt * 8 + (lane & 3) * 2;
        *(__half2*)(catp + tiled_off(L, row0, col)) =
            __floats2half2_rn(oacc[nt][0] * inv0, oacc[nt][1] * inv0);
        *(__half2*)(catp + tiled_off(L, row0 + 8, col)) =
            __floats2half2_rn(oacc[nt][2] * inv1, oacc[nt][3] * inv1);
    }
}

// ================= conversions =================
__global__ void conv_tile(const float* __restrict__ src, __half* __restrict__ dst,
                          int N, int K, long long n8) {
    long long i = (long long)blockIdx.x * 256 + threadIdx.x;
    if (i >= n8) return;
    int kq = K >> 3;
    int r = (int)(i / kq), q8i = (int)(i - (long long)r * kq);
    int c0 = q8i * 8;
    const float4* s = (const float4*)(src + (size_t)r * K + c0);
    float4 a = s[0], b = s[1];
    __half2 h0 = __floats2half2_rn(a.x, a.y);
    __half2 h1 = __floats2half2_rn(a.z, a.w);
    __half2 h2 = __floats2half2_rn(b.x, b.y);
    __half2 h3 = __floats2half2_rn(b.z, b.w);
    uint4 o;
    o.x = *(uint32_t*)&h0; o.y = *(uint32_t*)&h1;
    o.z = *(uint32_t*)&h2; o.w = *(uint32_t*)&h3;
    *(uint4*)(dst + tiled_off(N, r, c0)) = o;
}

__global__ void upext_k(const float* __restrict__ upq, const float* __restrict__ upk,
                        const float* __restrict__ upv) {
    int i = blockIdx.x * 256 + threadIdx.x;
    int o = i >> 7, j = i & 127;
    int mat = o / HID, colm = o - mat * HID;
    int jj = j - mat * 32;
    float v = 0.f;
    if (j < 96 && jj >= 0 && jj < 32) {
        const float* up = (mat == 0) ? upq : (mat == 1) ? upk : upv;
        v = up[(size_t)colm * 32 + jj];
    }
    g_w12[tiled_off(H1, o, 3072 + j)] = __float2half(v);
}

__global__ void yext_k() {
    int i = blockIdx.x * 256 + threadIdx.x;
    int l = i >> 5, j = i & 31;
    float s0 = 0.f, s1 = 0.f, s2 = 0.f;
    #pragma unroll
    for (int z = 0; z < 4; z++) {
        size_t base = (size_t)z * 3 * L * 32 + (size_t)l * 32 + j;
        s0 += g_y1p[base];
        s1 += g_y1p[base + (size_t)L * 32];
        s2 += g_y1p[base + 2 * (size_t)L * 32];
    }
    g_xmod2[tiled_off(L, l, 3072 + j)]  = __float2half(s0);
    g_xmod2[tiled_off(L, l, 3104 + j)]  = __float2half(s1);
    g_xmod2[tiled_off(L, l, 3136 + j)]  = __float2half(s2);
    g_xmod2[tiled_off(L, l, 3168 + j)]  = __float2half(0.f);
}

// ================= small kernels =================
__global__ __launch_bounds__(256) void mod_gemv(const float* __restrict__ vec,
                                                const float* __restrict__ W,
                                                const float* __restrict__ b) {
    __shared__ float sv[HID];
    int t = threadIdx.x;
    for (int j = t; j < HID; j += 256) {
        float v = vec[j];
        sv[j] = v / (1.f + expf(-v));
    }
    __syncthreads();
    int o = blockIdx.x * 8 + (t >> 5);
    int lane = t & 31;
    const float* w = W + (size_t)o * HID;
    float acc = 0.f;
    for (int k = lane; k < HID; k += 32) acc += sv[k] * w[k];
    #pragma unroll
    for (int s = 16; s; s >>= 1) acc += __shfl_xor_sync(0xffffffffu, acc, s);
    if (lane == 0) g_m[o] = acc + b[o];
}

__global__ __launch_bounds__(256) void ln_mod_k(const float* __restrict__ x) {
    int l = blockIdx.x, t = threadIdx.x;
    const float* xr = x + (size_t)l * HID;
    float s = 0.f, s2 = 0.f;
    for (int j = t; j < HID; j += 256) { float v = xr[j]; s += v; s2 += v * v; }
    __shared__ float sh[16];
    #pragma unroll
    for (int o = 16; o; o >>= 1) {
        s  += __shfl_xor_sync(0xffffffffu, s, o);
        s2 += __shfl_xor_sync(0xffffffffu, s2, o);
    }
    if ((t & 31) == 0) { sh[t >> 5] = s; sh[8 + (t >> 5)] = s2; }
    __syncthreads();
    float ts = 0.f, ts2 = 0.f;
    #pragma unroll
    for (int i = 0; i < 8; i++) { ts += sh[i]; ts2 += sh[8 + i]; }
    float mu = ts * (1.f / HID);
    float var = ts2 * (1.f / HID) - mu * mu;
    float r = rsqrtf(var + 1e-6f);
    for (int u = t; u < HID / 8; u += 256) {
        int j0 = u * 8;
        __half2 hp[4];
        #pragma unroll
        for (int e = 0; e < 4; e++) {
            int j = j0 + 2 * e;
            float v0 = (xr[j] - mu) * r;
            float v1 = (xr[j + 1] - mu) * r;
            hp[e] = __floats2half2_rn((1.f + g_m[HID + j]) * v0 + g_m[j],
                                      (1.f + g_m[HID + j + 1]) * v1 + g_m[j + 1]);
        }
        uint4 o;
        o.x = *(uint32_t*)&hp[0]; o.y = *(uint32_t*)&hp[1];
        o.z = *(uint32_t*)&hp[2]; o.w = *(uint32_t*)&hp[3];
        *(uint4*)(g_xmod2 + tiled_off(L, l, j0)) = o;
    }
}

__global__ __launch_bounds__(256) void lora_down_s(
    const __half* __restrict__ X, const float* __restrict__ D0,
    const float* __restrict__ D1, const float* __restrict__ D2,
    float* __restrict__ Yp, int nc, int kbase, int K,
    long long zs, long long ms, int ldy)
{
    __shared__ float xs[64][65];
    __shared__ float ds[64][32];
    int t = threadIdx.x;
    int m0 = blockIdx.x * 64;
    int mat = blockIdx.y, z = blockIdx.z;
    const float* D = (mat == 0) ? D0 : ((mat == 1) ? D1 : D2);
    float* Y = Yp + (size_t)z * zs + (size_t)mat * ms;
    int tx = t & 31, ty = t >> 5;
    int drow = t >> 3, df4 = t & 7;
    float acc[8] = {};
    int k0b = (kbase + z * nc) * 64;

    for (int c = 0; c < nc; c++) {
        int k0 = k0b + c * 64;
        #pragma unroll
        for (int j = 0; j < 4; j++) {
            int slot = t + j * 256;
            int row = slot >> 4, c4 = (slot & 15) * 4;
            uint2 u = *(const uint2*)(X + tiled_off(L, m0 + row, k0 + c4));
            __half2 ab = *(__half2*)&u.x, cd = *(__half2*)&u.y;
            float2 f0 = __half22float2(ab), f1 = __half22float2(cd);
            xs[c4][row] = f0.x; xs[c4 + 1][row] = f0.y;
            xs[c4 + 2][row] = f1.x; xs[c4 + 3][row] = f1.y;
        }
        #pragma unroll
        for (int j = 0; j < 2; j++) {
            int kk = (df4 + 8 * j) * 4;
            float4 vd = *(const float4*)(D + (size_t)drow * K + k0 + kk);
            ds[kk][drow] = vd.x; ds[kk + 1][drow] = vd.y;
            ds[kk + 2][drow] = vd.z; ds[kk + 3][drow] = vd.w;
        }
        __syncthreads();
        #pragma unroll
        for (int kk = 0; kk < 64; kk++) {
            float dv = ds[kk][tx];
            #pragma unroll
            for (int i = 0; i < 8; i++) acc[i] += xs[kk][ty * 8 + i] * dv;
        }
        __syncthreads();
    }
    #pragma unroll
    for (int i = 0; i < 8; i++)
        Y[(size_t)(m0 + ty * 8 + i) * ldy + tx] = acc[i];
}

__global__ __launch_bounds__(128) void qkv_finalize(
    const float* __restrict__ q_scale, const float* __restrict__ k_scale,
    const float* __restrict__ pe)
{
    __shared__ float sq[128], sk[128], red[8];

    const int head = blockIdx.x, d = threadIdx.x;
    const int l0 = blockIdx.y * 16;
    const int col = head * HD + d;

    const float qsc = q_scale[d], ksc = k_scale[d];
    const float qsc2 = q_scale[d ^ 1], ksc2 = k_scale[d ^ 1];

    for (int li = 0; li < 16; li++) {
        int l = l0 + li;
        size_t hb = (size_t)l * H3;
        float qv = __half2float(g_hh[hb + col]);
        float kv = __half2float(g_hh[hb + HID + col]);
        float vv = __half2float(g_hh[hb + 2 * HID + col]);

        __syncthreads();
        sq[d] = qv; sk[d] = kv;
        float aq = qv * qv, ak = kv * kv;
        #pragma unroll
        for (int o = 16; o; o >>= 1) {
            aq += __shfl_xor_sync(0xffffffffu, aq, o);
            ak += __shfl_xor_sync(0xffffffffu, ak, o);
        }
        if ((d & 31) == 0) { red[d >> 5] = aq; red[4 + (d >> 5)] = ak; }
        __syncthreads();

        float rq = rsqrtf((red[0] + red[1] + red[2] + red[3]) * (1.f / HD) + 1e-6f);
        float rk = rsqrtf((red[4] + red[5] + red[6] + red[7]) * (1.f / HD) + 1e-6f);

        int e = d & ~1, o_ = d | 1;
        float sce = (d & 1) ? qsc2 : qsc;
        float sco = (d & 1) ? qsc : qsc2;
        float kce = (d & 1) ? ksc2 : ksc;
        float kco = (d & 1) ? ksc : ksc2;
        float q0 = sq[e]  * rq * sce;
        float q1 = sq[o_] * rq * sco;
        float k0 = sk[e]  * rk * kce;
        float k1 = sk[o_] * rk * kco;

        const float* p = pe + ((size_t)l * 64 + (d >> 1)) * 4;
        float qo = (d & 1) ? (p[2] * q0 + p[3] * q1) : (p[0] * q0 + p[1] * q1);
        float ko = (d & 1) ? (p[2] * k0 + p[3] * k1) : (p[0] * k0 + p[1] * k1);

        {
            int q8 = d >> 3, sub = d >> 6;
            int sr = l * 2 + sub;
            size_t off = ((size_t)head * L + l) * 128 + (size_t)sub * 64 +
                         (size_t)(((q8 & 7) ^ (sr & 7)) << 3) + (d & 7);
            g_q2[off] = __float2half(qo);
            g_k2[off] = __float2half(ko);
        }
        {
            int kt = l >> 7, lc = l & 127;
            int q8 = lc >> 3;
            int sr = d * 2 + (q8 >> 3);
            size_t off = ((size_t)(head * 16 + kt)) * 16384 + (size_t)sr * 64 +
                         (size_t)(((q8 & 7) ^ (sr & 7)) << 3) + (lc & 7);
            g_v2[off] = __float2half(vv);
        }
    }
}

__global__ __launch_bounds__(256) void final_k(const float* __restrict__ x,
                                               const float* __restrict__ pu,
                                               const float* __restrict__ b2,
                                               float* __restrict__ out)
{
    int l = blockIdx.y;
    int c = blockIdx.x * 256 + threadIdx.x;
    __shared__ float sp[64];
    if (threadIdx.x < 64) {
        float s = 0.f;
        #pragma unroll
        for (int z = 0; z < 8; z++)
            s += g_plp[(size_t)z * L * 64 + (size_t)l * 64 + threadIdx.x];
        sp[threadIdx.x] = s;
    }
    __syncthreads();

    const float4* ur = (const float4*)(pu + (size_t)c * 64);
    float a = 0.f;
    #pragma unroll
    for (int r = 0; r < 16; r++) {
        float4 u = ur[r];
        a += u.x * sp[4 * r] + u.y * sp[4 * r + 1] + u.z * sp[4 * r + 2] + u.w * sp[4 * r + 3];
    }
    size_t idx = (size_t)l * HID + c;
    const size_t LH = (size_t)L * HID;
    float o = g_o[idx] + g_o[idx + LH] + g_o[idx + 2 * LH] +
              g_o[idx + 3 * LH] + g_o[idx + 4 * LH] + g_o[idx + 5 * LH] + b2[c] + a;
    out[idx] = x[idx] + g_m[2 * HID + c] * o;
}

// ================= launch =================
extern "C" void kernel_launch(void* const* d_in, const int* in_sizes, int n_in,
                              void* d_out, int out_size)
{
    const float* x   = (const float*)d_in[0];
    const float* vec = (const float*)d_in[1];
    const float* pe  = (const float*)d_in[2];
    const float* mw  = (const float*)d_in[3];
    const float* mb  = (const float*)d_in[4];
    const float* w1  = (const float*)d_in[5];
    const float* b1  = (const float*)d_in[6];
    const float* w2  = (const float*)d_in[7];
    const float* b2  = (const float*)d_in[8];
    const float* qs  = (const float*)d_in[9];
    const float* ks  = (const float*)d_in[10];
    const float* lqd = (const float*)d_in[11];
    const float* lqu = (const float*)d_in[12];
    const float* lkd = (const float*)d_in[13];
    const float* lku = (const float*)d_in[14];
    const float* lvd = (const float*)d_in[15];
    const float* lvu = (const float*)d_in[16];
    const float* pd  = (const float*)d_in[17];
    const float* pu  = (const float*)d_in[18];
    float* out = (float*)d_out;

    float *y1p, *plp, *ob;
    __half *xmod2, *w12, *w22, *cat2, *q2, *k2, *v2;
    cudaGetSymbolAddress((void**)&y1p,   g_y1p);
    cudaGetSymbolAddress((void**)&plp,   g_plp);
    cudaGetSymbolAddress((void**)&ob,    g_o);
    cudaGetSymbolAddress((void**)&xmod2, g_xmod2);
    cudaGetSymbolAddress((void**)&w12,   g_w12);
    cudaGetSymbolAddress((void**)&w22,   g_w22);
    cudaGetSymbolAddress((void**)&cat2,  g_cat2);
    cudaGetSymbolAddress((void**)&q2,    g_q2);
    cudaGetSymbolAddress((void**)&k2,    g_k2);
    cudaGetSymbolAddress((void**)&v2,    g_v2);

    const int SMG = 4 * 48 * 1024 + 64;
    const int SMF = 5 * 32 * 1024 + 64;

    static cudaStream_t s1 = 0, s2 = 0;
    static cudaEvent_t evRoot = 0, evLn = 0, evW1 = 0, evUp = 0, evW2 = 0;
    static cudaEvent_t evY = 0, evMLP = 0, evG2m = 0, evLpm = 0;
    static bool init_done = false;
    if (!init_done) {
        cudaFuncSetAttribute(gemm512<1>, cudaFuncAttributeMaxDynamicSharedMemorySize, SMG);
        cudaFuncSetAttribute(gemm512<0>, cudaFuncAttributeMaxDynamicSharedMemorySize, SMG);
        cudaFuncSetAttribute(flash_k,    cudaFuncAttributeMaxDynamicSharedMemorySize, SMF);
        cudaStreamCreateWithFlags(&s1, cudaStreamNonBlocking);
        cudaStreamCreateWithFlags(&s2, cudaStreamNonBlocking);
        cudaEventCreateWithFlags(&evRoot, cudaEventDisableTiming);
        cudaEventCreateWithFlags(&evLn,   cudaEventDisableTiming);
        cudaEventCreateWithFlags(&evW1,   cudaEventDisableTiming);
        cudaEventCreateWithFlags(&evUp,   cudaEventDisableTiming);
        cudaEventCreateWithFlags(&evW2,   cudaEventDisableTiming);
        cudaEventCreateWithFlags(&evY,    cudaEventDisableTiming);
        cudaEventCreateWithFlags(&evMLP,  cudaEventDisableTiming);
        cudaEventCreateWithFlags(&evG2m,  cudaEventDisableTiming);
        cudaEventCreateWithFlags(&evLpm,  cudaEventDisableTiming);
        init_done = true;
    }

    cudaEventRecord(evRoot, 0);
    cudaStreamWaitEvent(s1, evRoot, 0);
    cudaStreamWaitEvent(s2, evRoot, 0);

    // s0: modulation + layernorm
    mod_gemv<<<(3 * HID) / 8, 256>>>(vec, mw, mb);
    ln_mod_k<<<L, 256>>>(x);
    cudaEventRecord(evLn, 0);

    // s1: conv w1 then gemm1-MLP (profiling slot 3)
    conv_tile<<<(int)(((size_t)H1 * HID / 8 + 255) / 256), 256, 0, s1>>>(
        w1, w12, H1, HID, (size_t)H1 * HID / 8);
    cudaEventRecord(evW1, s1);
    cudaStreamWaitEvent(s1, evLn, 0);
    gemm512<1><<<dim3(L / 128, 48, 1), 512, SMG, s1>>>(
        xmod2, w12, nullptr, b1, cat2, 48, 0, 36, L, H1, 0, 0LL);
    cudaEventRecord(evMLP, s1);

    // s2: up-ext, then qkv lora downs, then y-ext
    upext_k<<<(H3 * 128) / 256, 256, 0, s2>>>(lqu, lku, lvu);
    cudaEventRecord(evUp, s2);
    cudaStreamWaitEvent(s2, evLn, 0);
    lora_down_s<<<dim3(L / 64, 3, 4), 256, 0, s2>>>(
        xmod2, lqd, lkd, lvd, y1p, 12, 0, HID,
        3LL * L * 32, (long long)L * 32, 32);
    yext_k<<<(L * 32) / 256, 256, 0, s2>>>();
    cudaEventRecord(evY, s2);

    // s1: conv w2
    conv_tile<<<(int)(((size_t)HID * CATD / 8 + 255) / 256), 256, 0, s1>>>(
        w2, w22, HID, CATD, (size_t)HID * CATD / 8);
    cudaEventRecord(evW2, s1);

    // s0: gemm1-QKV
    cudaStreamWaitEvent(0, evW1, 0);
    cudaStreamWaitEvent(0, evUp, 0);
    cudaStreamWaitEvent(0, evY, 0);
    gemm512<1><<<dim3(L / 128, 36, 1), 512, SMG>>>(
        xmod2, w12, nullptr, b1, cat2, 50, 0, 0, L, H1, 0, 0LL);

    // s0: finalize + flash
    qkv_finalize<<<dim3(HEADS, L / 16), 128>>>(qs, ks, pe);
    flash_k<<<dim3(L / 128, HEADS), 256, SMF>>>(q2, k2, v2, cat2);

    // s1: gemm2 over MLP K-chunks, split-K=3 -> g_o[0..2]
    gemm512<0><<<dim3(L / 128, HID / 256, 3), 512, SMG, s1>>>(
        cat2, w22, ob, nullptr, nullptr, 64, 48, 0, L, HID, HID, (long long)L * HID);
    cudaEventRecord(evG2m, s1);

    // s2: proj lora over MLP K-chunks -> plp[0..5]
    cudaStreamWaitEvent(s2, evMLP, 0);
    lora_down_s<<<dim3(L / 64, 2, 6), 256, 0, s2>>>(
        cat2, pd, pd + (size_t)32 * CATD, nullptr, plp, 32, 48, CATD,
        (long long)L * 64, 32LL, 64);
    cudaEventRecord(evLpm, s2);

    // s0: gemm2 attn chunks split-K=3 -> g_o[3..5], proj lora attn -> plp[6..7]
    cudaStreamWaitEvent(0, evW2, 0);
    gemm512<0><<<dim3(L / 128, HID / 256, 3), 512, SMG>>>(
        cat2, w22, ob + 3 * (size_t)L * HID, nullptr, nullptr, 16, 0, 0, L, HID, HID,
        (long long)L * HID);
    lora_down_s<<<dim3(L / 64, 2, 2), 256>>>(
        cat2, pd, pd + (size_t)32 * CATD, nullptr, plp + 6 * (size_t)L * 64, 24, 0, CATD,
        (long long)L * 64, 32LL, 64);

    // join
    cudaStreamWaitEvent(0, evG2m, 0);
    cudaStreamWaitEvent(0, evLpm, 0);
    final_k<<<dim3(HID / 256, L), 256>>>(x, pu, b2, out);
}

// round 17
// speedup vs baseline: 1.0966x; 1.0021x over previous
#include <cuda_runtime.h>
#include <cuda_fp16.h>
#include <math.h>
#include <stdint.h>

#define L 2048
#define HID 3072
#define HEADS 24
#define HD 128
#define MLPD 12288
#define H1 21504
#define CATD 15360
#define H3 9216   // 3*HID

// ---------------- scratch ----------------
__device__ float g_m[3 * HID];
__device__ float g_y1p[4 * 3 * (size_t)L * 32];
__device__ float g_plp[8 * (size_t)L * 64];
__device__ float g_o[6 * (size_t)L * HID];        // 3 MLP + 3 attn partials

__device__ __half g_hh[(size_t)L * H3];
__device__ __half g_xmod2[(size_t)L * 3200];
__device__ __half g_w12[(size_t)H1 * 3200];
__device__ __half g_w22[(size_t)HID * CATD];
__device__ __half g_cat2[(size_t)L * CATD];
__device__ __half g_q2[(size_t)HEADS * L * HD];
__device__ __half g_k2[(size_t)HEADS * L * HD];
__device__ __half g_v2[(size_t)HEADS * HD * L];

// ================= helpers =================
__device__ __forceinline__ uint32_t smem_u32(const void* p) {
    uint32_t a;
    asm("{ .reg .u64 t; cvta.to.shared.u64 t, %1; cvt.u32.u64 %0, t; }" : "=r"(a) : "l"(p));
    return a;
}
__device__ __forceinline__ void mbar_init(uint32_t a, uint32_t cnt) {
    asm volatile("mbarrier.init.shared.b64 [%0], %1;" :: "r"(a), "r"(cnt) : "memory");
}
__device__ __forceinline__ void mbar_expect(uint32_t a, uint32_t bytes) {
    asm volatile("mbarrier.arrive.expect_tx.shared.b64 _, [%0], %1;" :: "r"(a), "r"(bytes) : "memory");
}
__device__ __forceinline__ void mbar_arrive(uint32_t a) {
    asm volatile("mbarrier.arrive.shared.b64 _, [%0];" :: "r"(a) : "memory");
}
__device__ __forceinline__ void mbar_wait(uint32_t a, uint32_t parity) {
    asm volatile(
        "{\n\t.reg .pred P;\n"
        "WL_%=:\n\t"
        "mbarrier.try_wait.parity.acquire.cta.shared::cta.b64 P, [%0], %1, 0x989680;\n\t"
        "@P bra WD_%=;\n\t"
        "bra WL_%=;\n"
        "WD_%=:\n\t}"
        :: "r"(a), "r"(parity) : "memory");
}
__device__ __forceinline__ void bulk_g2s(uint32_t dst, const void* src, uint32_t bytes, uint32_t mbar) {
    asm volatile(
        "cp.async.bulk.shared::cta.global.mbarrier::complete_tx::bytes [%0], [%1], %2, [%3];"
        :: "r"(dst), "l"(src), "r"(bytes), "r"(mbar) : "memory");
}
__device__ __forceinline__ void ldsm4(uint32_t& r0, uint32_t& r1, uint32_t& r2, uint32_t& r3,
                                      uint32_t addr) {
    asm volatile("ldmatrix.sync.aligned.m8n8.x4.shared.b16 {%0,%1,%2,%3}, [%4];"
                 : "=r"(r0), "=r"(r1), "=r"(r2), "=r"(r3) : "r"(addr));
}
__device__ __forceinline__ void mma16816(float* d, const uint32_t* a, const uint32_t* b) {
    asm volatile(
        "mma.sync.aligned.m16n8k16.row.col.f32.f16.f16.f32 "
        "{%0,%1,%2,%3}, {%4,%5,%6,%7}, {%8,%9}, {%0,%1,%2,%3};"
        : "+f"(d[0]), "+f"(d[1]), "+f"(d[2]), "+f"(d[3])
        : "r"(a[0]), "r"(a[1]), "r"(a[2]), "r"(a[3]), "r"(b[0]), "r"(b[1]));
}
__device__ __forceinline__ uint32_t packh2(float a, float b) {
    __half2 h = __floats2half2_rn(a, b);
    return *(uint32_t*)&h;
}
__device__ __forceinline__ float gelu1(float x) {
    float u = 0.7978845608028654f * (x + 0.044715f * x * x * x);
    float e = __expf(2.f * u);
    return x * e / (e + 1.f);
}
__device__ __forceinline__ uint32_t swz128(uint32_t base, int r, int q) {
    return base + (uint32_t)r * 128u + ((uint32_t)(q ^ (r & 7)) << 4);
}
__device__ __forceinline__ uint32_t swz256(uint32_t base, int r, int q8) {
    int sr = r * 2 + (q8 >> 3);
    int q = q8 & 7;
    return base + (uint32_t)sr * 128u + ((uint32_t)(q ^ (sr & 7)) << 4);
}
__device__ __forceinline__ size_t tiled_off(int M, int r, int c) {
    return ((size_t)(c >> 6) * M + r) * 64 + (size_t)((((c & 63) >> 3) ^ (r & 7)) << 3) + (c & 7);
}

// ================= bulk-fed fp16 NT GEMM (4-stage, rotating producer, unrolled stages) ======
template <int MODE>
__global__ __launch_bounds__(512, 1) void gemm512(
    const __half* __restrict__ At, const __half* __restrict__ Bt,
    float* __restrict__ C, const float* __restrict__ bias,
    __half* __restrict__ catp, int nc, int kbase, int nbase,
    int M, int N, int ldc, long long zsC)
{
    constexpr uint32_t ABYTES = 128u * 128u;
    constexpr uint32_t BBYTES = 256u * 128u;
    constexpr uint32_t STAGE = ABYTES + BBYTES;   // 48KB

    extern __shared__ char smraw[];
    uint32_t s0 = smem_u32(smraw);
    uint32_t mbF = s0 + 4u * STAGE;
    uint32_t mbE = mbF + 32u;

    const int t = threadIdx.x, w = t >> 5, lane = t & 31;
    const int wm = w & 3, wn = w >> 2;
    const int m0 = blockIdx.x * 128, n0 = (nbase + blockIdx.y) * 256;
    const int z = blockIdx.z;
    const int c0 = kbase + z * nc;
    C += (size_t)z * zsC;

    if (t == 0) {
        #pragma unroll
        for (int i = 0; i < 4; i++) {
            mbar_init(mbF + (uint32_t)i * 8u, 1);
            mbar_init(mbE + (uint32_t)i * 8u, 16);
        }
    }
    __syncthreads();

    auto issue = [&](int c, int stg) {
        uint32_t mb = mbF + (uint32_t)stg * 8u;
        uint32_t ab = s0 + (uint32_t)stg * STAGE;
        mbar_expect(mb, ABYTES + BBYTES);
        bulk_g2s(ab, At + ((size_t)(c0 + c) * M + m0) * 64, ABYTES, mb);
        bulk_g2s(ab + ABYTES, Bt + ((size_t)(c0 + c) * N + n0) * 64, BBYTES, mb);
    };

    if (t == 0) { issue(0, 0); issue(1, 1); issue(2, 2); issue(3, 3); }

    uint32_t offA[4][2], offB[4][4];
    #pragma unroll
    for (int s = 0; s < 4; s++) {
        #pragma unroll
        for (int mt = 0; mt < 2; mt++) {
            int r = wm * 32 + mt * 16 + (lane & 15);
            int q = s * 2 + (lane >> 4);
            offA[s][mt] = swz128(0, r, q);
        }
        #pragma unroll
        for (int np = 0; np < 4; np++) {
            int r = wn * 64 + np * 16 + ((lane >> 4) << 3) + (lane & 7);
            int q = s * 2 + ((lane >> 3) & 1);
            offB[s][np] = ABYTES + swz128(0, r, q);
        }
    }

    float acc[2][8][4] = {};

    for (int cb = 0; cb < nc; cb += 4) {
        uint32_t par = (uint32_t)((cb >> 2) & 1);
        #pragma unroll
        for (int i = 0; i < 4; i++) {
            int c = cb + i;
            if (c >= nc) break;
            mbar_wait(mbF + (uint32_t)i * 8u, par);

            uint32_t sb = s0 + (uint32_t)i * STAGE;

            #pragma unroll
            for (int s = 0; s < 4; s++) {
                uint32_t Af[2][4];
                #pragma unroll
                for (int mt = 0; mt < 2; mt++)
                    ldsm4(Af[mt][0], Af[mt][1], Af[mt][2], Af[mt][3], sb + offA[s][mt]);
                uint32_t Bf[8][2];
                #pragma unroll
                for (int np = 0; np < 4; np++)
                    ldsm4(Bf[2 * np][0], Bf[2 * np][1], Bf[2 * np + 1][0], Bf[2 * np + 1][1],
                          sb + offB[s][np]);
                #pragma unroll
                for (int mt = 0; mt < 2; mt++)
                    #pragma unroll
                    for (int nt = 0; nt < 8; nt++)
                        mma16816(acc[mt][nt], Af[mt], Bf[nt]);
            }

            if (lane == 0) {
                mbar_arrive(mbE + (uint32_t)i * 8u);
                if (c + 4 < nc && w == (c & 15)) {
                    mbar_wait(mbE + (uint32_t)i * 8u, par);
                    issue(c + 4, i);
                }
            }
        }
    }

    #pragma unroll
    for (int mt = 0; mt < 2; mt++) {
        int row = m0 + wm * 32 + mt * 16 + (lane >> 2);
        #pragma unroll
        for (int nt = 0; nt < 8; nt++) {
            int col = n0 + wn * 64 + nt * 8 + (lane & 3) * 2;
            if (MODE == 1) {
                float b0 = bias[col], b1v = bias[col + 1];
                float v00 = acc[mt][nt][0] + b0, v01 = acc[mt][nt][1] + b1v;
                float v10 = acc[mt][nt][2] + b0, v11 = acc[mt][nt][3] + b1v;
                if (n0 >= H3) {
                    int cc = col - 6144;
                    *(__half2*)(catp + tiled_off(L, row, cc)) =
                        __floats2half2_rn(gelu1(v00), gelu1(v01));
                    *(__half2*)(catp + tiled_off(L, row + 8, cc)) =
                        __floats2half2_rn(gelu1(v10), gelu1(v11));
                } else {
                    *(__half2*)(g_hh + (size_t)row * H3 + col) = __floats2half2_rn(v00, v01);
                    *(__half2*)(g_hh + (size_t)(row + 8) * H3 + col) = __floats2half2_rn(v10, v11);
                }
            } else {
                *(float2*)(C + (size_t)row * ldc + col) =
                    make_float2(acc[mt][nt][0], acc[mt][nt][1]);
                *(float2*)(C + (size_t)(row + 8) * ldc + col) =
                    make_float2(acc[mt][nt][2], acc[mt][nt][3]);
            }
        }
    }
}

// ================= flash attention (warp-async prefetch) =================
__global__ __launch_bounds__(256, 1) void flash_k(
    const __half* __restrict__ Qg, const __half* __restrict__ Kg,
    const __half* __restrict__ Vg, __half* __restrict__ catp)
{
    extern __shared__ char smraw[];
    uint32_t s0 = smem_u32(smraw);
    const uint32_t sQ = s0;
    const uint32_t sK[2] = {s0 + 32768u, s0 + 98304u};
    const uint32_t sV[2] = {s0 + 65536u, s0 + 131072u};
    const uint32_t mbar = s0 + 163840u;

    const int t = threadIdx.x, w = t >> 5, lane = t & 31;
    const int qt = blockIdx.x, head = blockIdx.y;

    const __half* Qp = Qg + ((size_t)head * L + qt * 128) * 128;
    const __half* Kp = Kg + (size_t)head * L * 128;
    const __half* Vp = Vg + (size_t)head * 16 * 16384;

    if (t == 0) {
        mbar_init(mbar, 1); mbar_init(mbar + 8, 1);
        mbar_init(mbar + 16, 8); mbar_init(mbar + 24, 8);
    }
    __syncthreads();
    if (t == 0) {
        mbar_expect(mbar, 98304u);
        bulk_g2s(sQ, Qp, 32768u, mbar);
        bulk_g2s(sK[0], Kp, 32768u, mbar);
        bulk_g2s(sV[0], Vp, 32768u, mbar);
        mbar_expect(mbar + 8, 65536u);
        bulk_g2s(sK[1], Kp + (size_t)128 * 128, 32768u, mbar + 8);
        bulk_g2s(sV[1], Vp + 16384, 32768u, mbar + 8);
    }

    const float CSC = 0.08838834764831845f * 1.4426950408889634f;
    float m_[2] = {-1e30f, -1e30f}, l_[2] = {0.f, 0.f};
    float oacc[16][4] = {};

    for (int kt = 0; kt < 16; kt++) {
        int buf = kt & 1;
        uint32_t par = (uint32_t)((kt >> 1) & 1);
        mbar_wait(mbar + (uint32_t)buf * 8u, par);

        float sacc[16][4] = {};
        #pragma unroll
        for (int ks = 0; ks < 8; ks++) {
            uint32_t Af[4];
            {
                int r = w * 16 + (lane & 15);
                int q8 = ks * 2 + (lane >> 4);
                ldsm4(Af[0], Af[1], Af[2], Af[3], swz256(sQ, r, q8));
            }
            uint32_t Bf[16][2];
            #pragma unroll
            for (int np = 0; np < 8; np++) {
                int r = np * 16 + ((lane >> 4) << 3) + (lane & 7);
                int q8 = ks * 2 + ((lane >> 3) & 1);
                ldsm4(Bf[2 * np][0], Bf[2 * np][1], Bf[2 * np + 1][0], Bf[2 * np + 1][1],
                      swz256(sK[buf], r, q8));
            }
            #pragma unroll
            for (int nt = 0; nt < 16; nt++) mma16816(sacc[nt], Af, Bf[nt]);
        }

        #pragma unroll
        for (int h = 0; h < 2; h++) {
            float tm = -1e30f;
            #pragma unroll
            for (int nt = 0; nt < 16; nt++)
                tm = fmaxf(tm, fmaxf(sacc[nt][2 * h], sacc[nt][2 * h + 1]));
            tm *= CSC;
            tm = fmaxf(tm, __shfl_xor_sync(0xffffffffu, tm, 1));
            tm = fmaxf(tm, __shfl_xor_sync(0xffffffffu, tm, 2));
            float mn = fmaxf(m_[h], tm);
            float alpha = exp2f(m_[h] - mn);
            float rs = 0.f;
            #pragma unroll
            for (int nt = 0; nt < 16; nt++) {
                float p0 = exp2f(sacc[nt][2 * h] * CSC - mn);
                float p1 = exp2f(sacc[nt][2 * h + 1] * CSC - mn);
                sacc[nt][2 * h] = p0; sacc[nt][2 * h + 1] = p1;
                rs += p0 + p1;
            }
            rs += __shfl_xor_sync(0xffffffffu, rs, 1);
            rs += __shfl_xor_sync(0xffffffffu, rs, 2);
            l_[h] = l_[h] * alpha + rs;
            m_[h] = mn;
            #pragma unroll
            for (int nt = 0; nt < 16; nt++) { oacc[nt][2 * h] *= alpha; oacc[nt][2 * h + 1] *= alpha; }
        }

        #pragma unroll
        for (int kk = 0; kk < 8; kk++) {
            uint32_t pf[4];
            pf[0] = packh2(sacc[2 * kk][0], sacc[2 * kk][1]);
            pf[1] = packh2(sacc[2 * kk][2], sacc[2 * kk][3]);
            pf[2] = packh2(sacc[2 * kk + 1][0], sacc[2 * kk + 1][1]);
            pf[3] = packh2(sacc[2 * kk + 1][2], sacc[2 * kk + 1][3]);
            uint32_t Bv[16][2];
            #pragma unroll
            for (int np = 0; np < 8; np++) {
                int r = np * 16 + ((lane >> 4) << 3) + (lane & 7);
                int q8 = kk * 2 + ((lane >> 3) & 1);
                ldsm4(Bv[2 * np][0], Bv[2 * np][1], Bv[2 * np + 1][0], Bv[2 * np + 1][1],
                      swz256(sV[buf], r, q8));
            }
            #pragma unroll
            for (int nt = 0; nt < 16; nt++) mma16816(oacc[nt], pf, Bv[nt]);
        }

        if (lane == 0) {
            mbar_arrive(mbar + 16u + (uint32_t)buf * 8u);
            if (kt + 2 < 16 && w == (kt & 7)) {
                mbar_wait(mbar + 16u + (uint32_t)buf * 8u, par);
                mbar_expect(mbar + (uint32_t)buf * 8u, 65536u);
                bulk_g2s(sK[buf], Kp + (size_t)(kt + 2) * 128 * 128, 32768u,
                         mbar + (uint32_t)buf * 8u);
                bulk_g2s(sV[buf], Vp + (size_t)(kt + 2) * 16384, 32768u,
                         mbar + (uint32_t)buf * 8u);
            }
        }
    }

    float inv0 = 1.f / l_[0], inv1 = 1.f / l_[1];
    int row0 = qt * 128 + w * 16 + (lane >> 2);
    #pragma unroll
    for (int nt = 0; nt < 16; nt++) {
        int col = head * 128 + nt * 8 + (lane & 3) * 2;
        *(__half2*)(catp + tiled_off(L, row0, col)) =
            __floats2half2_rn(oacc[nt][0] * inv0, oacc[nt][1] * inv0);
        *(__half2*)(catp + tiled_off(L, row0 + 8, col)) =
            __floats2half2_rn(oacc[nt][2] * inv1, oacc[nt][3] * inv1);
    }
}

// ================= conversions =================
__global__ void conv_tile(const float* __restrict__ src, __half* __restrict__ dst,
                          int N, int K, long long n8) {
    long long i = (long long)blockIdx.x * 256 + threadIdx.x;
    if (i >= n8) return;
    int kq = K >> 3;
    int r = (int)(i / kq), q8i = (int)(i - (long long)r * kq);
    int c0 = q8i * 8;
    const float4* s = (const float4*)(src + (size_t)r * K + c0);
    float4 a = s[0], b = s[1];
    __half2 h0 = __floats2half2_rn(a.x, a.y);
    __half2 h1 = __floats2half2_rn(a.z, a.w);
    __half2 h2 = __floats2half2_rn(b.x, b.y);
    __half2 h3 = __floats2half2_rn(b.z, b.w);
    uint4 o;
    o.x = *(uint32_t*)&h0; o.y = *(uint32_t*)&h1;
    o.z = *(uint32_t*)&h2; o.w = *(uint32_t*)&h3;
    *(uint4*)(dst + tiled_off(N, r, c0)) = o;
}

__global__ void upext_k(const float* __restrict__ upq, const float* __restrict__ upk,
                        const float* __restrict__ upv) {
    int i = blockIdx.x * 256 + threadIdx.x;
    int o = i >> 7, j = i & 127;
    int mat = o / HID, colm = o - mat * HID;
    int jj = j - mat * 32;
    float v = 0.f;
    if (j < 96 && jj >= 0 && jj < 32) {
        const float* up = (mat == 0) ? upq : (mat == 1) ? upk : upv;
        v = up[(size_t)colm * 32 + jj];
    }
    g_w12[tiled_off(H1, o, 3072 + j)] = __float2half(v);
}

__global__ void yext_k() {
    int i = blockIdx.x * 256 + threadIdx.x;
    int l = i >> 5, j = i & 31;
    float s0 = 0.f, s1 = 0.f, s2 = 0.f;
    #pragma unroll
    for (int z = 0; z < 4; z++) {
        size_t base = (size_t)z * 3 * L * 32 + (size_t)l * 32 + j;
        s0 += g_y1p[base];
        s1 += g_y1p[base + (size_t)L * 32];
        s2 += g_y1p[base + 2 * (size_t)L * 32];
    }
    g_xmod2[tiled_off(L, l, 3072 + j)]  = __float2half(s0);
    g_xmod2[tiled_off(L, l, 3104 + j)]  = __float2half(s1);
    g_xmod2[tiled_off(L, l, 3136 + j)]  = __float2half(s2);
    g_xmod2[tiled_off(L, l, 3168 + j)]  = __float2half(0.f);
}

// ================= small kernels =================
__global__ __launch_bounds__(256) void mod_gemv(const float* __restrict__ vec,
                                                const float* __restrict__ W,
                                                const float* __restrict__ b) {
    __shared__ float sv[HID];
    int t = threadIdx.x;
    for (int j = t; j < HID; j += 256) {
        float v = vec[j];
        sv[j] = v / (1.f + expf(-v));
    }
    __syncthreads();
    int o = blockIdx.x * 8 + (t >> 5);
    int lane = t & 31;
    const float* w = W + (size_t)o * HID;
    float acc = 0.f;
    for (int k = lane; k < HID; k += 32) acc += sv[k] * w[k];
    #pragma unroll
    for (int s = 16; s; s >>= 1) acc += __shfl_xor_sync(0xffffffffu, acc, s);
    if (lane == 0) g_m[o] = acc + b[o];
}

__global__ __launch_bounds__(256) void ln_mod_k(const float* __restrict__ x) {
    int l = blockIdx.x, t = threadIdx.x;
    const float* xr = x + (size_t)l * HID;
    float s = 0.f, s2 = 0.f;
    for (int j = t; j < HID; j += 256) { float v = xr[j]; s += v; s2 += v * v; }
    __shared__ float sh[16];
    #pragma unroll
    for (int o = 16; o; o >>= 1) {
        s  += __shfl_xor_sync(0xffffffffu, s, o);
        s2 += __shfl_xor_sync(0xffffffffu, s2, o);
    }
    if ((t & 31) == 0) { sh[t >> 5] = s; sh[8 + (t >> 5)] = s2; }
    __syncthreads();
    float ts = 0.f, ts2 = 0.f;
    #pragma unroll
    for (int i = 0; i < 8; i++) { ts += sh[i]; ts2 += sh[8 + i]; }
    float mu = ts * (1.f / HID);
    float var = ts2 * (1.f / HID) - mu * mu;
    float r = rsqrtf(var + 1e-6f);
    for (int u = t; u < HID / 8; u += 256) {
        int j0 = u * 8;
        __half2 hp[4];
        #pragma unroll
        for (int e = 0; e < 4; e++) {
            int j = j0 + 2 * e;
            float v0 = (xr[j] - mu) * r;
            float v1 = (xr[j + 1] - mu) * r;
            hp[e] = __floats2half2_rn((1.f + g_m[HID + j]) * v0 + g_m[j],
                                      (1.f + g_m[HID + j + 1]) * v1 + g_m[j + 1]);
        }
        uint4 o;
        o.x = *(uint32_t*)&hp[0]; o.y = *(uint32_t*)&hp[1];
        o.z = *(uint32_t*)&hp[2]; o.w = *(uint32_t*)&hp[3];
        *(uint4*)(g_xmod2 + tiled_off(L, l, j0)) = o;
    }
}

__global__ __launch_bounds__(256) void lora_down_s(
    const __half* __restrict__ X, const float* __restrict__ D0,
    const float* __restrict__ D1, const float* __restrict__ D2,
    float* __restrict__ Yp, int nc, int kbase, int K,
    long long zs, long long ms, int ldy)
{
    __shared__ float xs[64][65];
    __shared__ float ds[64][32];
    int t = threadIdx.x;
    int m0 = blockIdx.x * 64;
    int mat = blockIdx.y, z = blockIdx.z;
    const float* D = (mat == 0) ? D0 : ((mat == 1) ? D1 : D2);
    float* Y = Yp + (size_t)z * zs + (size_t)mat * ms;
    int tx = t & 31, ty = t >> 5;
    int drow = t >> 3, df4 = t & 7;
    float acc[8] = {};
    int k0b = (kbase + z * nc) * 64;

    for (int c = 0; c < nc; c++) {
        int k0 = k0b + c * 64;
        #pragma unroll
        for (int j = 0; j < 4; j++) {
            int slot = t + j * 256;
            int row = slot >> 4, c4 = (slot & 15) * 4;
            uint2 u = *(const uint2*)(X + tiled_off(L, m0 + row, k0 + c4));
            __half2 ab = *(__half2*)&u.x, cd = *(__half2*)&u.y;
            float2 f0 = __half22float2(ab), f1 = __half22float2(cd);
            xs[c4][row] = f0.x; xs[c4 + 1][row] = f0.y;
            xs[c4 + 2][row] = f1.x; xs[c4 + 3][row] = f1.y;
        }
        #pragma unroll
        for (int j = 0; j < 2; j++) {
            int kk = (df4 + 8 * j) * 4;
            float4 vd = *(const float4*)(D + (size_t)drow * K + k0 + kk);
            ds[kk][drow] = vd.x; ds[kk + 1][drow] = vd.y;
            ds[kk + 2][drow] = vd.z; ds[kk + 3][drow] = vd.w;
        }
        __syncthreads();
        #pragma unroll
        for (int kk = 0; kk < 64; kk++) {
            float dv = ds[kk][tx];
            #pragma unroll
            for (int i = 0; i < 8; i++) acc[i] += xs[kk][ty * 8 + i] * dv;
        }
        __syncthreads();
    }
    #pragma unroll
    for (int i = 0; i < 8; i++)
        Y[(size_t)(m0 + ty * 8 + i) * ldy + tx] = acc[i];
}

__global__ __launch_bounds__(128) void qkv_finalize(
    const float* __restrict__ q_scale, const float* __restrict__ k_scale,
    const float* __restrict__ pe)
{
    __shared__ float sq[128], sk[128], red[8];

    const int head = blockIdx.x, d = threadIdx.x;
    const int l0 = blockIdx.y * 16;
    const int col = head * HD + d;

    const float qsc = q_scale[d], ksc = k_scale[d];
    const float qsc2 = q_scale[d ^ 1], ksc2 = k_scale[d ^ 1];

    for (int li = 0; li < 16; li++) {
        int l = l0 + li;
        size_t hb = (size_t)l * H3;
        float qv = __half2float(g_hh[hb + col]);
        float kv = __half2float(g_hh[hb + HID + col]);
        float vv = __half2float(g_hh[hb + 2 * HID + col]);

        __syncthreads();
        sq[d] = qv; sk[d] = kv;
        float aq = qv * qv, ak = kv * kv;
        #pragma unroll
        for (int o = 16; o; o >>= 1) {
            aq += __shfl_xor_sync(0xffffffffu, aq, o);
            ak += __shfl_xor_sync(0xffffffffu, ak, o);
        }
        if ((d & 31) == 0) { red[d >> 5] = aq; red[4 + (d >> 5)] = ak; }
        __syncthreads();

        float rq = rsqrtf((red[0] + red[1] + red[2] + red[3]) * (1.f / HD) + 1e-6f);
        float rk = rsqrtf((red[4] + red[5] + red[6] + red[7]) * (1.f / HD) + 1e-6f);

        int e = d & ~1, o_ = d | 1;
        float sce = (d & 1) ? qsc2 : qsc;
        float sco = (d & 1) ? qsc : qsc2;
        float kce = (d & 1) ? ksc2 : ksc;
        float kco = (d & 1) ? ksc : ksc2;
        float q0 = sq[e]  * rq * sce;
        float q1 = sq[o_] * rq * sco;
        float k0 = sk[e]  * rk * kce;
        float k1 = sk[o_] * rk * kco;

        const float* p = pe + ((size_t)l * 64 + (d >> 1)) * 4;
        float qo = (d & 1) ? (p[2] * q0 + p[3] * q1) : (p[0] * q0 + p[1] * q1);
        float ko = (d & 1) ? (p[2] * k0 + p[3] * k1) : (p[0] * k0 + p[1] * k1);

        {
            int q8 = d >> 3, sub = d >> 6;
            int sr = l * 2 + sub;
            size_t off = ((size_t)head * L + l) * 128 + (size_t)sub * 64 +
                         (size_t)(((q8 & 7) ^ (sr & 7)) << 3) + (d & 7);
            g_q2[off] = __float2half(qo);
            g_k2[off] = __float2half(ko);
        }
        {
            int kt = l >> 7, lc = l & 127;
            int q8 = lc >> 3;
            int sr = d * 2 + (q8 >> 3);
            size_t off = ((size_t)(head * 16 + kt)) * 16384 + (size_t)sr * 64 +
                         (size_t)(((q8 & 7) ^ (sr & 7)) << 3) + (lc & 7);
            g_v2[off] = __float2half(vv);
        }
    }
}

__global__ __launch_bounds__(256) void final_k(const float* __restrict__ x,
                                               const float* __restrict__ pu,
                                               const float* __restrict__ b2,
                                               float* __restrict__ out)
{
    int l = blockIdx.y;
    int c = blockIdx.x * 256 + threadIdx.x;
    __shared__ float sp[64];
    if (threadIdx.x < 64) {
        float s = 0.f;
        #pragma unroll
        for (int z = 0; z < 8; z++)
            s += g_plp[(size_t)z * L * 64 + (size_t)l * 64 + threadIdx.x];
        sp[threadIdx.x] = s;
    }
    __syncthreads();

    const float4* ur = (const float4*)(pu + (size_t)c * 64);
    float a = 0.f;
    #pragma unroll
    for (int r = 0; r < 16; r++) {
        float4 u = ur[r];
        a += u.x * sp[4 * r] + u.y * sp[4 * r + 1] + u.z * sp[4 * r + 2] + u.w * sp[4 * r + 3];
    }
    size_t idx = (size_t)l * HID + c;
    const size_t LH = (size_t)L * HID;
    float o = g_o[idx] + g_o[idx + LH] + g_o[idx + 2 * LH] +
              g_o[idx + 3 * LH] + g_o[idx + 4 * LH] + g_o[idx + 5 * LH] + b2[c] + a;
    out[idx] = x[idx] + g_m[2 * HID + c] * o;
}

// ================= launch =================
extern "C" void kernel_launch(void* const* d_in, const int* in_sizes, int n_in,
                              void* d_out, int out_size)
{
    const float* x   = (const float*)d_in[0];
    const float* vec = (const float*)d_in[1];
    const float* pe  = (const float*)d_in[2];
    const float* mw  = (const float*)d_in[3];
    const float* mb  = (const float*)d_in[4];
    const float* w1  = (const float*)d_in[5];
    const float* b1  = (const float*)d_in[6];
    const float* w2  = (const float*)d_in[7];
    const float* b2  = (const float*)d_in[8];
    const float* qs  = (const float*)d_in[9];
    const float* ks  = (const float*)d_in[10];
    const float* lqd = (const float*)d_in[11];
    const float* lqu = (const float*)d_in[12];
    const float* lkd = (const float*)d_in[13];
    const float* lku = (const float*)d_in[14];
    const float* lvd = (const float*)d_in[15];
    const float* lvu = (const float*)d_in[16];
    const float* pd  = (const float*)d_in[17];
    const float* pu  = (const float*)d_in[18];
    float* out = (float*)d_out;

    float *y1p, *plp, *ob;
    __half *xmod2, *w12, *w22, *cat2, *q2, *k2, *v2;
    cudaGetSymbolAddress((void**)&y1p,   g_y1p);
    cudaGetSymbolAddress((void**)&plp,   g_plp);
    cudaGetSymbolAddress((void**)&ob,    g_o);
    cudaGetSymbolAddress((void**)&xmod2, g_xmod2);
    cudaGetSymbolAddress((void**)&w12,   g_w12);
    cudaGetSymbolAddress((void**)&w22,   g_w22);
    cudaGetSymbolAddress((void**)&cat2,  g_cat2);
    cudaGetSymbolAddress((void**)&q2,    g_q2);
    cudaGetSymbolAddress((void**)&k2,    g_k2);
    cudaGetSymbolAddress((void**)&v2,    g_v2);

    const int SMG = 4 * 48 * 1024 + 64;
    const int SMF = 5 * 32 * 1024 + 64;

    static cudaStream_t s1 = 0, s2 = 0;
    static cudaEvent_t evRoot = 0, evLn = 0, evW1 = 0, evUp = 0, evW2 = 0;
    static cudaEvent_t evY = 0, evMLP = 0, evFlash = 0, evG2m = 0, evLp = 0;
    static bool init_done = false;
    if (!init_done) {
        cudaFuncSetAttribute(gemm512<1>, cudaFuncAttributeMaxDynamicSharedMemorySize, SMG);
        cudaFuncSetAttribute(gemm512<0>, cudaFuncAttributeMaxDynamicSharedMemorySize, SMG);
        cudaFuncSetAttribute(flash_k,    cudaFuncAttributeMaxDynamicSharedMemorySize, SMF);
        cudaStreamCreateWithFlags(&s1, cudaStreamNonBlocking);
        cudaStreamCreateWithFlags(&s2, cudaStreamNonBlocking);
        cudaEventCreateWithFlags(&evRoot, cudaEventDisableTiming);
        cudaEventCreateWithFlags(&evLn,   cudaEventDisableTiming);
        cudaEventCreateWithFlags(&evW1,   cudaEventDisableTiming);
        cudaEventCreateWithFlags(&evUp,   cudaEventDisableTiming);
        cudaEventCreateWithFlags(&evW2,   cudaEventDisableTiming);
        cudaEventCreateWithFlags(&evY,    cudaEventDisableTiming);
        cudaEventCreateWithFlags(&evMLP,  cudaEventDisableTiming);
        cudaEventCreateWithFlags(&evFlash,cudaEventDisableTiming);
        cudaEventCreateWithFlags(&evG2m,  cudaEventDisableTiming);
        cudaEventCreateWithFlags(&evLp,   cudaEventDisableTiming);
        init_done = true;
    }

    cudaEventRecord(evRoot, 0);
    cudaStreamWaitEvent(s1, evRoot, 0);
    cudaStreamWaitEvent(s2, evRoot, 0);

    // s0: modulation + layernorm
    mod_gemv<<<(3 * HID) / 8, 256>>>(vec, mw, mb);
    ln_mod_k<<<L, 256>>>(x);
    cudaEventRecord(evLn, 0);

    // s1: conv w1 then gemm1-MLP (profiling slot 3)
    conv_tile<<<(int)(((size_t)H1 * HID / 8 + 255) / 256), 256, 0, s1>>>(
        w1, w12, H1, HID, (size_t)H1 * HID / 8);
    cudaEventRecord(evW1, s1);
    cudaStreamWaitEvent(s1, evLn, 0);
    gemm512<1><<<dim3(L / 128, 48, 1), 512, SMG, s1>>>(
        xmod2, w12, nullptr, b1, cat2, 48, 0, 36, L, H1, 0, 0LL);
    cudaEventRecord(evMLP, s1);

    // s2: up-ext, then qkv lora downs, then y-ext
    upext_k<<<(H3 * 128) / 256, 256, 0, s2>>>(lqu, lku, lvu);
    cudaEventRecord(evUp, s2);
    cudaStreamWaitEvent(s2, evLn, 0);
    lora_down_s<<<dim3(L / 64, 3, 4), 256, 0, s2>>>(
        xmod2, lqd, lkd, lvd, y1p, 12, 0, HID,
        3LL * L * 32, (long long)L * 32, 32);
    yext_k<<<(L * 32) / 256, 256, 0, s2>>>();
    cudaEventRecord(evY, s2);

    // s1: conv w2
    conv_tile<<<(int)(((size_t)HID * CATD / 8 + 255) / 256), 256, 0, s1>>>(
        w2, w22, HID, CATD, (size_t)HID * CATD / 8);
    cudaEventRecord(evW2, s1);

    // s0: gemm1-QKV
    cudaStreamWaitEvent(0, evW1, 0);
    cudaStreamWaitEvent(0, evUp, 0);
    cudaStreamWaitEvent(0, evY, 0);
    gemm512<1><<<dim3(L / 128, 36, 1), 512, SMG>>>(
        xmod2, w12, nullptr, b1, cat2, 50, 0, 0, L, H1, 0, 0LL);

    // s0: finalize + flash
    qkv_finalize<<<dim3(HEADS, L / 16), 128>>>(qs, ks, pe);
    flash_k<<<dim3(L / 128, HEADS), 256, SMF>>>(q2, k2, v2, cat2);
    cudaEventRecord(evFlash, 0);

    // s1: gemm2 over MLP K-chunks, split-K=3 -> g_o[0..2]
    gemm512<0><<<dim3(L / 128, HID / 256, 3), 512, SMG, s1>>>(
        cat2, w22, ob, nullptr, nullptr, 64, 48, 0, L, HID, HID, (long long)L * HID);
    cudaEventRecord(evG2m, s1);

    // s2: proj lora MLP (after gemm1-MLP), then proj lora attn (after flash)
    cudaStreamWaitEvent(s2, evMLP, 0);
    lora_down_s<<<dim3(L / 64, 2, 6), 256, 0, s2>>>(
        cat2, pd, pd + (size_t)32 * CATD, nullptr, plp, 32, 48, CATD,
        (long long)L * 64, 32LL, 64);
    cudaStreamWaitEvent(s2, evFlash, 0);
    lora_down_s<<<dim3(L / 64, 2, 2), 256, 0, s2>>>(
        cat2, pd, pd + (size_t)32 * CATD, nullptr, plp + 6 * (size_t)L * 64, 24, 0, CATD,
        (long long)L * 64, 32LL, 64);
    cudaEventRecord(evLp, s2);

    // s0: gemm2 attn chunks split-K=3 -> g_o[3..5] (concurrent with s2 lora-attn)
    cudaStreamWaitEvent(0, evW2, 0);
    gemm512<0><<<dim3(L / 128, HID / 256, 3), 512, SMG>>>(
        cat2, w22, ob + 3 * (size_t)L * HID, nullptr, nullptr, 16, 0, 0, L, HID, HID,
        (long long)L * HID);

    // join
    cudaStreamWaitEvent(0, evG2m, 0);
    cudaStreamWaitEvent(0, evLp, 0);
    final_k<<<dim3(HID / 256, L), 256>>>(x, pu, b2, out);
}